// round 7
// baseline (speedup 1.0000x reference)
#include <cuda_runtime.h>
#include <math.h>

#define NB   4
#define CH   256
#define OMC  108

// ---- packed f32x2 ops ----
#define PACKF2(out, lo, hi) \
    asm("mov.b64 %0, {%1, %2};" : "=l"(out) : "f"(lo), "f"(hi))
#define UNPACKF2(lo, hi, in) \
    asm("mov.b64 {%0, %1}, %2;" : "=f"(lo), "=f"(hi) : "l"(in))
#define FMAF2(d, a, b, c) \
    asm("fma.rn.f32x2 %0, %1, %2, %3;" : "=l"(d) : "l"(a), "l"(b), "l"(c))

// ---- branch tables (7 branches) ----
// b0: lvl0 mid x0 s1->80 | b1: lvl0 high x1 s1->40 up80 | b2: lvl1 mid x1 s1->40
// b3: lvl1 low x0 s2->40 | b4: lvl1 high x2 s1->20 up40 | b5: lvl2 mid x2 s1->20
// b6: lvl2 low x1 s2->20
__device__ __constant__ int BR_SRC[7]    = {0,1,1,0,2,2,1};
__device__ __constant__ int BR_HS[7]     = {80,40,40,80,20,20,40};
__device__ __constant__ int BR_STRIDE[7] = {1,1,1,2,1,1,2};
__device__ __constant__ int BR_HO[7]     = {80,40,40,40,20,20,20};
__device__ __constant__ int BR_SOFT[7]   = {0,1,0,1,1,0,1};
__device__ __constant__ int BR_UPH[7]    = {0,80,0,0,40,0,0};
__device__ __constant__ int BR_GNSEL[7]  = {0,1,0,2,1,0,2};
__device__ __constant__ int DWPFX[7]     = {0,6400,8000,9600,16000,16400,16800};
__device__ __constant__ int OMPFX[7]     = {0,6400,8000,9600,11200,11600,12000};
__device__ __constant__ int SAMP_PFX8[7] = {0,800,1000,1200,1400,1450,1500};

// shared-source dw: per source, which weight sets (0=m,1=h,2=l) and dst prefixes
__device__ __constant__ int SRC_NSETS[3]  = {2,3,2};
__device__ __constant__ int SRC_WSEL[3][3]= {{0,2,0},{1,0,2},{1,0,0}};
__device__ __constant__ int SRC_DST[3][3] = {{0,9600,0},{6400,8000,16800},{16000,16400,0}};

// ---------------- scratch ----------------
__device__ float g_x0[NB*80*80*CH];
__device__ float g_x1[NB*40*40*CH];
__device__ float g_x2[NB*20*20*CH];
__device__ float g_dwb[18400*NB*CH];
__device__ float g_om [12400*NB*OMC];
__device__ float g_feat[12400*NB*CH];
__device__ float g_wT2[3*192*112];
__device__ float g_a[7*NB];
__device__ float g_y[3*NB*CH];
__device__ float g_z[3*NB*1024];
__device__ float g_cmean[7*NB*CH];
__device__ float g_gmu[7*NB*16];
__device__ float g_ginv[7*NB*16];

__device__ __forceinline__ const float* pick_x(int s){
    return s==0 ? g_x0 : (s==1 ? g_x1 : g_x2);
}
__device__ __forceinline__ float* pick_xm(int s){
    return s==0 ? g_x0 : (s==1 ? g_x1 : g_x2);
}

// ---------------- NCHW -> NHWC tiled transpose ----------------
__global__ void k_tr2(const float* __restrict__ in, int sel, int HW){
    __shared__ float tile[32][33];
    float* out = pick_xm(sel);
    int n  = blockIdx.z;
    int hw0 = blockIdx.x*32;
    int c0  = blockIdx.y*32;
    int tx = threadIdx.x, ty = threadIdx.y;
    #pragma unroll
    for (int q = 0; q < 4; ++q){
        int c = c0 + ty + q*8;
        int hw = hw0 + tx;
        float v = (hw < HW) ? in[((size_t)n*CH + c)*HW + hw] : 0.f;
        tile[ty + q*8][tx] = v;
    }
    __syncthreads();
    #pragma unroll
    for (int q = 0; q < 4; ++q){
        int hw = hw0 + ty + q*8;
        int c  = c0 + tx;
        if (hw < HW) out[((size_t)n*HW + hw)*CH + c] = tile[tx][ty + q*8];
    }
}

// weight transform: [dy][ic*3+dx][slot(4g x 28)]
__global__ void k_wt2(const float* __restrict__ ow){
    int i = blockIdx.x*blockDim.x + threadIdx.x;
    if (i >= 3*192*112) return;
    int slot = i % 112;
    int r    = (i / 112) % 192;
    int dy   = i / (112*192);
    int ic = r/3, dx = r%3;
    int g = slot/28, jj = slot%28;
    float v = 0.f;
    if (jj < 27) v = ow[(g*27+jj)*576 + ic*9 + dy*3 + dx];
    g_wT2[i] = v;
}

// ---------------- shared-source depthwise conv: 9 taps loaded once, 2-3 sets ----
__global__ void k_dwS(const float* __restrict__ wm, const float* __restrict__ sm_, const float* __restrict__ bm_,
                      const float* __restrict__ wh, const float* __restrict__ sh_, const float* __restrict__ bh_,
                      const float* __restrict__ wl, const float* __restrict__ sl_, const float* __restrict__ bl_){
    __shared__ unsigned long long wsm[3][64][9][2];
    __shared__ float4 ssm[3][64], bsm[3][64];
    int src = blockIdx.y, n = blockIdx.z;
    int H = (src==0) ? 80 : (src==1 ? 40 : 20);
    int W = H, HW = H*W;
    int nsets = SRC_NSETS[src];
    int t = threadIdx.x;

    for (int s = 0; s < nsets; ++s){
        int sel = SRC_WSEL[src][s];
        const float* wgt = sel==0 ? wm : (sel==1 ? wh : wl);
        const float* sc  = sel==0 ? sm_ : (sel==1 ? sh_ : sl_);
        const float* bi  = sel==0 ? bm_ : (sel==1 ? bh_ : bl_);
        for (int i = t; i < 64*9; i += 256){
            int q = i/9, tp = i%9;
            float a0 = wgt[(q*4+0)*9 + tp], a1 = wgt[(q*4+1)*9 + tp];
            float a2 = wgt[(q*4+2)*9 + tp], a3 = wgt[(q*4+3)*9 + tp];
            PACKF2(wsm[s][q][tp][0], a0, a1);
            PACKF2(wsm[s][q][tp][1], a2, a3);
        }
        for (int i = t; i < 64; i += 256){
            ssm[s][i] = *(const float4*)(sc + i*4);
            bsm[s][i] = *(const float4*)(bi + i*4);
        }
    }
    __syncthreads();

    const float* x = pick_x(src);
    int q  = t & 63;
    int c0 = q*4;
    int lane = t >> 6;
    for (int hw = blockIdx.x*4 + lane; hw < HW; hw += gridDim.x*4){
        int w = hw % W, h = hw / W;
        ulonglong2 tap[9];
        #pragma unroll
        for (int dy = 0; dy < 3; ++dy){
            int yy = h + dy - 1;
            #pragma unroll
            for (int dx = 0; dx < 3; ++dx){
                int xx = w + dx - 1;
                int tp = dy*3 + dx;
                if (yy >= 0 && yy < H && xx >= 0 && xx < W)
                    tap[tp] = *(const ulonglong2*)(x + ((size_t)(n*H+yy)*W + xx)*CH + c0);
                else { tap[tp].x = 0ull; tap[tp].y = 0ull; }
            }
        }
        #pragma unroll 3
        for (int s = 0; s < 3; ++s){
            if (s >= nsets) break;
            unsigned long long a01 = 0ull, a23 = 0ull;
            #pragma unroll
            for (int tp = 0; tp < 9; ++tp){
                FMAF2(a01, tap[tp].x, wsm[s][q][tp][0], a01);
                FMAF2(a23, tap[tp].y, wsm[s][q][tp][1], a23);
            }
            float ax, ay, az, aw;
            UNPACKF2(ax, ay, a01);
            UNPACKF2(az, aw, a23);
            float4 s4 = ssm[s][q], b4 = bsm[s][q];
            float4 o;
            float t0 = ax*s4.x + b4.x; o.x = t0/(1.f+expf(-t0));
            float t1 = ay*s4.y + b4.y; o.y = t1/(1.f+expf(-t1));
            float t2 = az*s4.z + b4.z; o.z = t2/(1.f+expf(-t2));
            float t3 = aw*s4.w + b4.w; o.w = t3/(1.f+expf(-t3));
            float* dst = g_dwb + (size_t)SRC_DST[src][s]*NB*CH;
            *(float4*)(dst + ((size_t)n*HW + hw)*CH + c0) = o;
        }
    }
}

// ---------------- grouped conv 256->108, per-group blocks, FFMA2 ----
template<int STRIDE, int PXO, int TPX, int PXQ, int THREADS>
__global__ void __launch_bounds__(THREADS)
k_om3(int H, int W, int Ho, int Wo, const float* __restrict__ ob, int bA, int bB){
    constexpr int PW  = (PXO-1)*STRIDE + 3;
    constexpr int PWP = (PW + 3) & ~3;
    constexpr int WIN = 3 + (TPX-1)*STRIDE;
    static_assert((TPX*STRIDE) % 4 == 0, "window alignment");
    static_assert(WIN <= 8, "window fits two float4");
    extern __shared__ float sh[];
    float* patch = sh;
    float* wsl   = sh + 64*PWP;

    int br   = blockIdx.z == 0 ? bA : bB;
    const float* src = g_dwb + (size_t)DWPFX[br]*NB*CH;
    float* dst       = g_om  + (size_t)OMPFX[br]*NB*OMC;

    int nt   = (Wo + PXO - 1)/PXO;
    int g    = blockIdx.y;
    int b    = blockIdx.x;
    int tile = b % nt;
    int ho   = (b/nt) % Ho;
    int n    = b/(nt*Ho);
    int wo0  = tile*PXO;
    int hsrc = ho*STRIDE;
    int wsrc0= wo0*STRIDE;
    int cb   = g*64;

    int t   = threadIdx.x;
    int pxq = t % PXQ;
    int li  = t / PXQ;
    bool act = li < 7;
    int xb  = pxq*TPX*STRIDE;

    unsigned long long a01[TPX], a23[TPX];
    #pragma unroll
    for (int p = 0; p < TPX; ++p){ a01[p] = 0ull; a23[p] = 0ull; }

    const float* wsrc_base = g_wT2 + g*28;
    for (int dy = 0; dy < 3; ++dy){
        __syncthreads();
        int gy = hsrc + dy - 1;
        for (int i = t; i < PW*64; i += THREADS){
            int c = i & 63, xx = i >> 6;
            int gx = wsrc0 + xx - 1;
            float v = 0.f;
            if (gy >= 0 && gy < H && gx >= 0 && gx < W)
                v = src[((size_t)(n*H+gy)*W + gx)*CH + cb + c];
            patch[c*PWP + xx] = v;
        }
        {
            const float* ws = wsrc_base + dy*192*112;
            for (int i = t; i < 192*7; i += THREADS){
                int row = i/7, col = (i%7)*4;
                *(float4*)(wsl + row*28 + col) = *(const float4*)(ws + row*112 + col);
            }
        }
        __syncthreads();
        if (act){
            #pragma unroll 4
            for (int ic = 0; ic < 64; ++ic){
                const float* pr = patch + ic*PWP + xb;
                float f[8];
                *(float4*)(f)   = *(const float4*)(pr);
                *(float4*)(f+4) = *(const float4*)(pr+4);
                unsigned long long sv[WIN];
                #pragma unroll
                for (int k2 = 0; k2 < WIN; ++k2) PACKF2(sv[k2], f[k2], f[k2]);
                const float* wb = wsl + (ic*3)*28 + li*4;
                #pragma unroll
                for (int dx = 0; dx < 3; ++dx){
                    ulonglong2 wv = *(const ulonglong2*)(wb + dx*28);
                    #pragma unroll
                    for (int p = 0; p < TPX; ++p){
                        FMAF2(a01[p], sv[dx + p*STRIDE], wv.x, a01[p]);
                        FMAF2(a23[p], sv[dx + p*STRIDE], wv.y, a23[p]);
                    }
                }
            }
        }
    }
    if (act){
        float bj[4];
        #pragma unroll
        for (int j = 0; j < 4; ++j){
            int jj = li*4 + j;
            bj[j] = (jj < 27) ? ob[g*27 + jj] : 0.f;
        }
        #pragma unroll
        for (int p = 0; p < TPX; ++p){
            int wo = wo0 + pxq*TPX + p;
            if (wo < Wo){
                size_t base = ((size_t)(n*Ho+ho)*Wo + wo)*OMC + g*27 + li*4;
                float av[4];
                UNPACKF2(av[0], av[1], a01[p]);
                UNPACKF2(av[2], av[3], a23[p]);
                #pragma unroll
                for (int j = 0; j < 4; ++j)
                    if (li*4 + j < 27) dst[base + j] = av[j] + bj[j];
            }
        }
    }
}

// ---------------- batched DCNv3 sampler: 8 px/block, 2 px/thread ----------------
__global__ void k_sampB(){
    __shared__ float som[8][OMC];
    __shared__ float smk[8][36];
    __shared__ float sw[8][4][9][4];
    __shared__ int   soff[8][4][9][4];
    int bx = blockIdx.x;
    int b = 0;
    #pragma unroll
    for (int i = 1; i < 7; ++i) if (bx >= SAMP_PFX8[i]) b = i;
    int n = blockIdx.y;
    int p0 = (bx - SAMP_PFX8[b])*8;
    int Ho = BR_HO[b], Wo = Ho, HW = Ho*Wo;
    int H  = BR_HS[b], W = H;
    int stride = BR_STRIDE[b];
    int use_softmax = BR_SOFT[b];
    const float* x = pick_x(BR_SRC[b]);
    const float* omp = g_om + ((size_t)OMPFX[b]*NB + (size_t)n*HW)*OMC;
    int t = threadIdx.x;

    for (int i = t; i < 8*OMC; i += 256)
        som[i/OMC][i%OMC] = omp[(size_t)(p0 + i/OMC)*OMC + i%OMC];
    __syncthreads();

    if (use_softmax){
        if (t < 32){
            int pp = t >> 2, gg = t & 3;
            float mx = -1e30f;
            #pragma unroll
            for (int k = 0; k < 9; ++k) mx = fmaxf(mx, som[pp][72 + gg*9 + k]);
            float e[9], s = 0.f;
            #pragma unroll
            for (int k = 0; k < 9; ++k){ e[k] = expf(som[pp][72 + gg*9 + k] - mx); s += e[k]; }
            float inv = 1.f/s;
            #pragma unroll
            for (int k = 0; k < 9; ++k) smk[pp][gg*9 + k] = e[k]*inv;
        }
    } else {
        for (int i = t; i < 8*36; i += 256)
            smk[i/36][i%36] = 1.f/(1.f + expf(-som[i/36][72 + i%36]));
    }
    __syncthreads();

    for (int i = t; i < 288; i += 256){
        int pix = i / 36, r = i % 36, gg = r / 9, k = r % 9;
        int hw = p0 + pix;
        int wo = hw % Wo, ho = hw / Wo;
        float py = (float)(ho*stride) + (float)(k/3 - 1) + som[pix][gg*18 + k*2];
        float px = (float)(wo*stride) + (float)(k%3 - 1) + som[pix][gg*18 + k*2 + 1];
        float m  = smk[pix][gg*9 + k];
        float fy = floorf(py), fx = floorf(px);
        float wy = py - fy, wx = px - fx;
        int iy = (int)fy, ix = (int)fx;
        #pragma unroll
        for (int d0 = 0; d0 < 2; ++d0){
            int yy = iy + d0;
            float wgy = d0 ? wy : (1.f - wy);
            #pragma unroll
            for (int d1 = 0; d1 < 2; ++d1){
                int xx = ix + d1;
                bool valid = (yy >= 0) & (yy < H) & (xx >= 0) & (xx < W);
                int yc = min(max(yy, 0), H-1);
                int xc = min(max(xx, 0), W-1);
                sw[pix][gg][k][d0*2+d1]   = valid ? wgy*(d1 ? wx : (1.f - wx))*m : 0.f;
                soff[pix][gg][k][d0*2+d1] = ((n*H + yc)*W + xc)*CH;
            }
        }
    }
    __syncthreads();

    int lane = t >> 6, q = t & 63, c0 = q*4, g = q >> 4;
    const float* xc = x + c0;
    #pragma unroll
    for (int pi = 0; pi < 2; ++pi){
        int pix = lane + pi*4;
        unsigned long long acc01 = 0ull, acc23 = 0ull;
        #pragma unroll
        for (int k = 0; k < 9; ++k){
            float4 wv = *(const float4*)&sw[pix][g][k][0];
            int4  ov = *(const int4*)&soff[pix][g][k][0];
            unsigned long long w0, w1, w2, w3;
            PACKF2(w0, wv.x, wv.x); PACKF2(w1, wv.y, wv.y);
            PACKF2(w2, wv.z, wv.z); PACKF2(w3, wv.w, wv.w);
            ulonglong2 v0 = *(const ulonglong2*)(xc + ov.x);
            ulonglong2 v1 = *(const ulonglong2*)(xc + ov.y);
            ulonglong2 v2 = *(const ulonglong2*)(xc + ov.z);
            ulonglong2 v3 = *(const ulonglong2*)(xc + ov.w);
            FMAF2(acc01, v0.x, w0, acc01); FMAF2(acc23, v0.y, w0, acc23);
            FMAF2(acc01, v1.x, w1, acc01); FMAF2(acc23, v1.y, w1, acc23);
            FMAF2(acc01, v2.x, w2, acc01); FMAF2(acc23, v2.y, w2, acc23);
            FMAF2(acc01, v3.x, w3, acc01); FMAF2(acc23, v3.y, w3, acc23);
        }
        float4 acc;
        UNPACKF2(acc.x, acc.y, acc01);
        UNPACKF2(acc.z, acc.w, acc23);
        *(float4*)(g_feat + ((size_t)OMPFX[b]*NB + (size_t)n*HW + p0 + pix)*CH + c0) = acc;
    }
}

// ---------------- batched stats: GN mean/var + weighted channel means --------
__global__ void k_statsB(){
    __shared__ float wy[80], wx[80];
    __shared__ float r1[256], r2[256];
    __shared__ float4 rw[256];
    int b = blockIdx.x >> 4, g = blockIdx.x & 15, n = blockIdx.y;
    int Hs = BR_HO[b], Ws = Hs, HW = Hs*Ws;
    int uph = BR_UPH[b];
    float normw = uph ? 1.f/((float)uph*(float)uph) : 1.f/(float)HW;
    int t = threadIdx.x;
    if (t == 0){
        if (uph){
            for (int i = 0; i < Hs; ++i){ wy[i] = 0.f; wx[i] = 0.f; }
            float ry = (float)(Hs-1)/(float)(uph-1);
            for (int j = 0; j < uph; ++j){
                float c = j*ry; int i0 = (int)floorf(c); float f = c - (float)i0;
                wy[i0] += 1.f - f;
                if (i0 + 1 < Hs) wy[i0+1] += f;
            }
            for (int i = 0; i < Hs; ++i) wx[i] = wy[i];
        } else {
            for (int i = 0; i < Hs; ++i){ wy[i] = 1.f; wx[i] = 1.f; }
        }
    }
    __syncthreads();

    const float* fb = g_feat + ((size_t)OMPFX[b]*NB + (size_t)n*HW)*CH;
    int q  = t & 3;
    int c0 = g*16 + q*4;
    float4 s4 = make_float4(0,0,0,0), w4 = make_float4(0,0,0,0);
    float ss = 0.f;
    int hw0 = t >> 2;
    int h = hw0 / Ws, w = hw0 % Ws;
    for (int hw = hw0; hw < HW; hw += 64){
        float4 v = *(const float4*)(fb + (size_t)hw*CH + c0);
        s4.x += v.x; s4.y += v.y; s4.z += v.z; s4.w += v.w;
        ss += v.x*v.x + v.y*v.y + v.z*v.z + v.w*v.w;
        float ww = wy[h]*wx[w];
        w4.x += v.x*ww; w4.y += v.y*ww; w4.z += v.z*ww; w4.w += v.w*ww;
        w += 64; while (w >= Ws){ w -= Ws; ++h; }
    }
    r1[t] = s4.x + s4.y + s4.z + s4.w;
    r2[t] = ss;
    rw[t] = w4;
    __syncthreads();
    for (int o = 128; o >= 4; o >>= 1){
        if (t < o){
            r1[t] += r1[t+o]; r2[t] += r2[t+o];
            rw[t].x += rw[t+o].x; rw[t].y += rw[t+o].y;
            rw[t].z += rw[t+o].z; rw[t].w += rw[t+o].w;
        }
        __syncthreads();
    }
    if (t == 0){
        float s  = r1[0] + r1[1] + r1[2] + r1[3];
        float sq = r2[0] + r2[1] + r2[2] + r2[3];
        float cnt = (float)HW*16.f;
        float mu  = s/cnt;
        float var = sq/cnt - mu*mu;
        g_gmu [(b*NB+n)*16 + g] = mu;
        g_ginv[(b*NB+n)*16 + g] = rsqrtf(var + 1e-5f);
    }
    if (t < 4){
        float4 wv = rw[t];
        int c = (b*NB+n)*CH + g*16 + t*4;
        g_cmean[c]   = wv.x*normw; g_cmean[c+1] = wv.y*normw;
        g_cmean[c+2] = wv.z*normw; g_cmean[c+3] = wv.w*normw;
    }
}

// ---------------- attn scalars + pooled means, all levels ----------------
__device__ __constant__ int LVL_NBR[3] = {2,3,2};
__device__ __constant__ int LVL_BRS[3][3] = {{0,1,-1},{2,3,4},{5,6,-1}};

__global__ void k_attnB(const float* __restrict__ saw, const float* __restrict__ sab,
                        const float* __restrict__ gm, const float* __restrict__ bm,
                        const float* __restrict__ gh, const float* __restrict__ bh,
                        const float* __restrict__ gl, const float* __restrict__ bl){
    __shared__ float red[256];
    __shared__ float sa;
    int lvl = blockIdx.x, n = blockIdx.y, t = threadIdx.x;
    int g = t >> 4;
    int nbr = LVL_NBR[lvl];
    float invl = 1.f/(float)nbr;
    float y = 0.f;
    for (int i = 0; i < nbr; ++i){
        int b = LVL_BRS[lvl][i];
        int gs = BR_GNSEL[b];
        const float* gam = gs==0 ? gm : (gs==1 ? gh : gl);
        const float* bet = gs==0 ? bm : (gs==1 ? bh : bl);
        float m = (g_cmean[(b*NB+n)*CH + t] - g_gmu[(b*NB+n)*16 + g])
                  * g_ginv[(b*NB+n)*16 + g] * gam[t] + bet[t];
        red[t] = m*saw[t];
        __syncthreads();
        for (int o = 128; o > 0; o >>= 1){
            if (t < o) red[t] += red[t+o];
            __syncthreads();
        }
        if (t == 0){
            float a = red[0] + sab[0];
            a = fmaxf(a, 0.f);
            a = fminf(fmaxf((a + 3.f)/6.f, 0.f), 1.f);
            sa = a; g_a[b*NB + n] = a;
        }
        __syncthreads();
        y += sa*m*invl;
        __syncthreads();
    }
    g_y[(lvl*NB + n)*CH + t] = y;
}

// ---------------- fc (all levels) ----------------
__global__ void k_fcB(const float* __restrict__ w1, const float* __restrict__ b1,
                      const float* __restrict__ w2, const float* __restrict__ b2){
    __shared__ float h[4][64];
    int lvl = blockIdx.x;
    int t = threadIdx.x;
    int n = t >> 6, j = t & 63;
    float s = b1[j];
    const float* wr = w1 + j*CH;
    const float* yv = g_y + (lvl*NB + n)*CH;
    for (int c = 0; c < CH; ++c) s += yv[c]*wr[c];
    h[n][j] = fmaxf(s, 0.f);
    __syncthreads();
    for (int og = t; og < NB*1024; og += 256){
        int nn = og >> 10, o = og & 1023;
        float s2 = b2[o];
        const float* w2r = w2 + o*64;
        #pragma unroll 16
        for (int j2 = 0; j2 < 64; ++j2) s2 += h[nn][j2]*w2r[j2];
        float z = fminf(fmaxf(s2 + 3.f, 0.f), 6.f)*(1.f/6.f);
        int qd = o >> 8;
        float v;
        if      (qd == 0) v = (z - 0.5f)*2.f + 1.f;
        else if (qd == 2) v = (z - 0.5f)*2.f;
        else              v = z - 0.5f;
        g_z[(lvl*NB + nn)*1024 + o] = v;
    }
}

// ---------------- fused: GN+attn+upsample sum -> dyrelu -> NCHW out ----------
__device__ __forceinline__ void gn_acc(float4& o, float4 raw, int b, int n, int g,
                                       float4 g4, float4 b4){
    float mu = g_gmu[(b*NB+n)*16 + g], inv = g_ginv[(b*NB+n)*16 + g], a = g_a[b*NB + n];
    o.x += a*((raw.x - mu)*inv*g4.x + b4.x);
    o.y += a*((raw.y - mu)*inv*g4.y + b4.y);
    o.z += a*((raw.z - mu)*inv*g4.z + b4.z);
    o.w += a*((raw.w - mu)*inv*g4.w + b4.w);
}
__device__ __forceinline__ float4 feat_rd(int b, int n, int HW, int hw, int c0){
    return *(const float4*)(g_feat + ((size_t)OMPFX[b]*NB + (size_t)n*HW + hw)*CH + c0);
}
__device__ __forceinline__ float4 feat_up(int b, int n, int Hs, int Ho, int h, int w, int c0){
    float r = (float)(Hs-1)/(float)(Ho-1);
    float cy = h*r, cx = w*r;
    int y0 = (int)floorf(cy), x0 = (int)floorf(cx);
    int y1 = min(y0+1, Hs-1), x1 = min(x0+1, Hs-1);
    float wyf = cy - (float)y0, wxf = cx - (float)x0;
    const float* fb = g_feat + ((size_t)OMPFX[b]*NB + (size_t)n*Hs*Hs)*CH + c0;
    float4 v00 = *(const float4*)(fb + (size_t)(y0*Hs + x0)*CH);
    float4 v01 = *(const float4*)(fb + (size_t)(y0*Hs + x1)*CH);
    float4 v10 = *(const float4*)(fb + (size_t)(y1*Hs + x0)*CH);
    float4 v11 = *(const float4*)(fb + (size_t)(y1*Hs + x1)*CH);
    float a0 = (1.f-wyf)*(1.f-wxf), a1 = (1.f-wyf)*wxf, a2 = wyf*(1.f-wxf), a3 = wyf*wxf;
    float4 o;
    o.x = v00.x*a0 + v01.x*a1 + v10.x*a2 + v11.x*a3;
    o.y = v00.y*a0 + v01.y*a1 + v10.y*a2 + v11.y*a3;
    o.z = v00.z*a0 + v01.z*a1 + v10.z*a2 + v11.z*a3;
    o.w = v00.w*a0 + v01.w*a1 + v10.w*a2 + v11.w*a3;
    return o;
}

template<int LVL>
__global__ void k_outL(float* __restrict__ out,
                       const float* __restrict__ gm, const float* __restrict__ bm,
                       const float* __restrict__ gh, const float* __restrict__ bh,
                       const float* __restrict__ gl, const float* __restrict__ bl){
    constexpr int HoL = (LVL==0) ? 80 : (LVL==1 ? 40 : 20);
    constexpr int HWL = HoL*HoL;
    constexpr float INVL = (LVL==1) ? (1.f/3.f) : 0.5f;
    __shared__ float tile[32][257];
    int n   = blockIdx.y;
    int hw0 = blockIdx.x*32;
    int tx = threadIdx.x, ty = threadIdx.y;   // (32,8)
    int tid = ty*32 + tx;

    // phase 1: compute 32 hw x 256 c sum tile (coalesced over channel quads)
    #pragma unroll
    for (int k = 0; k < 8; ++k){
        int e = k*256 + tid;
        int hwl = e >> 6;           // 0..31
        int q   = e & 63;
        int hw  = hw0 + hwl;
        if (hw < HWL){
            int c0 = q*4, g = q >> 2;
            int w = hw % HoL, h = hw / HoL;
            float4 o = make_float4(0,0,0,0);
            float4 g4, b4;
            if (LVL == 0){
                g4 = *(const float4*)(gm + c0); b4 = *(const float4*)(bm + c0);
                gn_acc(o, feat_rd(0, n, 6400, hw, c0), 0, n, g, g4, b4);
                g4 = *(const float4*)(gh + c0); b4 = *(const float4*)(bh + c0);
                gn_acc(o, feat_up(1, n, 40, 80, h, w, c0), 1, n, g, g4, b4);
            } else if (LVL == 1){
                g4 = *(const float4*)(gm + c0); b4 = *(const float4*)(bm + c0);
                gn_acc(o, feat_rd(2, n, 1600, hw, c0), 2, n, g, g4, b4);
                g4 = *(const float4*)(gl + c0); b4 = *(const float4*)(bl + c0);
                gn_acc(o, feat_rd(3, n, 1600, hw, c0), 3, n, g, g4, b4);
                g4 = *(const float4*)(gh + c0); b4 = *(const float4*)(bh + c0);
                gn_acc(o, feat_up(4, n, 20, 40, h, w, c0), 4, n, g, g4, b4);
            } else {
                g4 = *(const float4*)(gm + c0); b4 = *(const float4*)(bm + c0);
                gn_acc(o, feat_rd(5, n, 400, hw, c0), 5, n, g, g4, b4);
                g4 = *(const float4*)(gl + c0); b4 = *(const float4*)(bl + c0);
                gn_acc(o, feat_rd(6, n, 400, hw, c0), 6, n, g, g4, b4);
            }
            tile[hwl][c0]   = o.x;
            tile[hwl][c0+1] = o.y;
            tile[hwl][c0+2] = o.z;
            tile[hwl][c0+3] = o.w;
        }
    }
    __syncthreads();

    // phase 2: dyrelu + transposed NCHW write
    int hw = hw0 + tx;
    if (hw < HWL){
        const float* zb = g_z + (LVL*NB + n)*1024;
        #pragma unroll
        for (int k = 0; k < 32; ++k){
            int c = ty + k*8;
            float f = tile[tx][c]*INVL;
            float a1 = zb[c], b1 = zb[256 + c];
            float a2 = zb[512 + c], b2 = zb[768 + c];
            out[((size_t)n*CH + c)*HWL + hw] = fmaxf(f*a1 + b1, f*a2 + b2);
        }
    }
}

// ---------------- host ----------------
extern "C" void kernel_launch(void* const* d_in, const int* in_sizes, int n_in,
                              void* d_out, int out_size){
    const float* x0     = (const float*)d_in[0];
    const float* x1     = (const float*)d_in[1];
    const float* x2     = (const float*)d_in[2];
    const float* dw_w_h = (const float*)d_in[3];
    const float* dw_s_h = (const float*)d_in[4];
    const float* dw_b_h = (const float*)d_in[5];
    const float* dw_w_m = (const float*)d_in[6];
    const float* dw_s_m = (const float*)d_in[7];
    const float* dw_b_m = (const float*)d_in[8];
    const float* dw_w_l = (const float*)d_in[9];
    const float* dw_s_l = (const float*)d_in[10];
    const float* dw_b_l = (const float*)d_in[11];
    const float* off_w  = (const float*)d_in[12];
    const float* off_b  = (const float*)d_in[13];
    const float* gn_g_h = (const float*)d_in[14];
    const float* gn_b_h = (const float*)d_in[15];
    const float* gn_g_m = (const float*)d_in[16];
    const float* gn_b_m = (const float*)d_in[17];
    const float* gn_g_l = (const float*)d_in[18];
    const float* gn_b_l = (const float*)d_in[19];
    const float* sa_w   = (const float*)d_in[20];
    const float* sa_b   = (const float*)d_in[21];
    const float* fc1_w  = (const float*)d_in[22];
    const float* fc1_b  = (const float*)d_in[23];
    const float* fc2_w  = (const float*)d_in[24];
    const float* fc2_b  = (const float*)d_in[25];
    float* out = (float*)d_out;

    // stage 1: transposes, then shared-source dw (#3 <- ncu profiled)
    k_tr2<<<dim3(200, 8, NB), dim3(32,8)>>>(x0, 0, 6400);
    k_tr2<<<dim3(50,  8, NB), dim3(32,8)>>>(x1, 1, 1600);
    k_tr2<<<dim3(13,  8, NB), dim3(32,8)>>>(x2, 2,  400);
    k_dwS<<<dim3(200, 3, NB), 256>>>(dw_w_m, dw_s_m, dw_b_m,
                                     dw_w_h, dw_s_h, dw_b_h,
                                     dw_w_l, dw_s_l, dw_b_l);
    k_wt2<<<(3*192*112 + 255)/256, 256>>>(off_w);

    // stage 2: offset/mask convs (5 launches, shape-classed)
    {
        const int SM80 = (64*52 + 192*28)*4;
        k_om3<1,48,4,12,96><<<dim3(2*80*NB, 4, 1), 96, SM80>>>(80, 80, 80, 80, off_b, 0, 0);
        const int SM40 = (64*44 + 192*28)*4;
        k_om3<1,40,4,10,80><<<dim3(1*40*NB, 4, 2), 80, SM40>>>(40, 40, 40, 40, off_b, 1, 2);
        k_om3<2,20,2,10,80><<<dim3(2*40*NB, 4, 1), 80, SM40>>>(80, 80, 40, 40, off_b, 3, 3);
        const int SM20 = (64*24 + 192*28)*4;
        k_om3<1,20,4,5,64><<<dim3(1*20*NB, 4, 2), 64, SM20>>>(20, 20, 20, 20, off_b, 4, 5);
        k_om3<2,20,2,10,80><<<dim3(1*20*NB, 4, 1), 80, SM40>>>(40, 40, 20, 20, off_b, 6, 6);
    }

    // stage 3: sampling, stats, attn, fc
    k_sampB<<<dim3(1550, NB), 256>>>();
    k_statsB<<<dim3(7*16, NB), 256>>>();
    k_attnB<<<dim3(3, NB), 256>>>(sa_w, sa_b, gn_g_m, gn_b_m, gn_g_h, gn_b_h, gn_g_l, gn_b_l);
    k_fcB<<<3, 256>>>(fc1_w, fc1_b, fc2_w, fc2_b);

    // stage 4: fused sum + dyrelu + output
    k_outL<0><<<dim3(200, NB), dim3(32,8)>>>(out,
        gn_g_m, gn_b_m, gn_g_h, gn_b_h, gn_g_l, gn_b_l);
    k_outL<1><<<dim3(50, NB), dim3(32,8)>>>(out + (size_t)NB*CH*6400,
        gn_g_m, gn_b_m, gn_g_h, gn_b_h, gn_g_l, gn_b_l);
    k_outL<2><<<dim3(13, NB), dim3(32,8)>>>(out + (size_t)NB*CH*8000,
        gn_g_m, gn_b_m, gn_g_h, gn_b_h, gn_g_l, gn_b_l);
}

// round 8
// speedup vs baseline: 1.1295x; 1.1295x over previous
#include <cuda_runtime.h>
#include <math.h>

#define NB   4
#define CH   256
#define OMC  108

// ---- packed f32x2 ops ----
#define PACKF2(out, lo, hi) \
    asm("mov.b64 %0, {%1, %2};" : "=l"(out) : "f"(lo), "f"(hi))
#define UNPACKF2(lo, hi, in) \
    asm("mov.b64 {%0, %1}, %2;" : "=f"(lo), "=f"(hi) : "l"(in))
#define FMAF2(d, a, b, c) \
    asm("fma.rn.f32x2 %0, %1, %2, %3;" : "=l"(d) : "l"(a), "l"(b), "l"(c))

// ---- branch tables (7 branches) ----
__device__ __constant__ int BR_SRC[7]    = {0,1,1,0,2,2,1};
__device__ __constant__ int BR_HS[7]     = {80,40,40,80,20,20,40};
__device__ __constant__ int BR_STRIDE[7] = {1,1,1,2,1,1,2};
__device__ __constant__ int BR_HO[7]     = {80,40,40,40,20,20,20};
__device__ __constant__ int BR_SOFT[7]   = {0,1,0,1,1,0,1};
__device__ __constant__ int BR_UPH[7]    = {0,80,0,0,40,0,0};
__device__ __constant__ int BR_GNSEL[7]  = {0,1,0,2,1,0,2};
__device__ __constant__ int DWPFX[7]     = {0,6400,8000,9600,16000,16400,16800};
__device__ __constant__ int OMPFX[7]     = {0,6400,8000,9600,11200,11600,12000};
__device__ __constant__ int SAMP_PFX8[7] = {0,800,1000,1200,1400,1450,1500};

__device__ __constant__ int SRC_NSETS[3]  = {2,3,2};
__device__ __constant__ int SRC_WSEL[3][3]= {{0,2,0},{1,0,2},{1,0,0}};
__device__ __constant__ int SRC_DST[3][3] = {{0,9600,0},{6400,8000,16800},{16000,16400,0}};

// ---------------- scratch ----------------
__device__ float g_x0[NB*80*80*CH];
__device__ float g_x1[NB*40*40*CH];
__device__ float g_x2[NB*20*20*CH];
__device__ float g_dwb[18400*NB*CH];
__device__ float g_om [12400*NB*OMC];
__device__ float g_feat[12400*NB*CH];
__device__ float g_wT2[3*192*112];
__device__ float g_a[7*NB];
__device__ float g_y[3*NB*CH];
__device__ float g_z[3*NB*1024];
__device__ float g_cmean[7*NB*CH];
__device__ float g_gmu[7*NB*16];
__device__ float g_ginv[7*NB*16];

__device__ __forceinline__ const float* pick_x(int s){
    return s==0 ? g_x0 : (s==1 ? g_x1 : g_x2);
}
__device__ __forceinline__ float* pick_xm(int s){
    return s==0 ? g_x0 : (s==1 ? g_x1 : g_x2);
}

// ---------------- NCHW -> NHWC tiled transpose ----------------
__global__ void k_tr2(const float* __restrict__ in, int sel, int HW){
    __shared__ float tile[32][33];
    float* out = pick_xm(sel);
    int n  = blockIdx.z;
    int hw0 = blockIdx.x*32;
    int c0  = blockIdx.y*32;
    int tx = threadIdx.x, ty = threadIdx.y;
    #pragma unroll
    for (int q = 0; q < 4; ++q){
        int c = c0 + ty + q*8;
        int hw = hw0 + tx;
        float v = (hw < HW) ? in[((size_t)n*CH + c)*HW + hw] : 0.f;
        tile[ty + q*8][tx] = v;
    }
    __syncthreads();
    #pragma unroll
    for (int q = 0; q < 4; ++q){
        int hw = hw0 + ty + q*8;
        int c  = c0 + tx;
        if (hw < HW) out[((size_t)n*HW + hw)*CH + c] = tile[tx][ty + q*8];
    }
}

// weight transform: [dy][ic*3+dx][slot(4g x 28)]
__global__ void k_wt2(const float* __restrict__ ow){
    int i = blockIdx.x*blockDim.x + threadIdx.x;
    if (i >= 3*192*112) return;
    int slot = i % 112;
    int r    = (i / 112) % 192;
    int dy   = i / (112*192);
    int ic = r/3, dx = r%3;
    int g = slot/28, jj = slot%28;
    float v = 0.f;
    if (jj < 27) v = ow[(g*27+jj)*576 + ic*9 + dy*3 + dx];
    g_wT2[i] = v;
}

// ---------------- shared-source depthwise conv ----------------
__global__ void k_dwS(const float* __restrict__ wm, const float* __restrict__ sm_, const float* __restrict__ bm_,
                      const float* __restrict__ wh, const float* __restrict__ sh_, const float* __restrict__ bh_,
                      const float* __restrict__ wl, const float* __restrict__ sl_, const float* __restrict__ bl_){
    __shared__ unsigned long long wsm[3][64][9][2];
    __shared__ float4 ssm[3][64], bsm[3][64];
    int src = blockIdx.y, n = blockIdx.z;
    int H = (src==0) ? 80 : (src==1 ? 40 : 20);
    int W = H, HW = H*W;
    int nsets = SRC_NSETS[src];
    int t = threadIdx.x;

    for (int s = 0; s < nsets; ++s){
        int sel = SRC_WSEL[src][s];
        const float* wgt = sel==0 ? wm : (sel==1 ? wh : wl);
        const float* sc  = sel==0 ? sm_ : (sel==1 ? sh_ : sl_);
        const float* bi  = sel==0 ? bm_ : (sel==1 ? bh_ : bl_);
        for (int i = t; i < 64*9; i += 256){
            int q = i/9, tp = i%9;
            float a0 = wgt[(q*4+0)*9 + tp], a1 = wgt[(q*4+1)*9 + tp];
            float a2 = wgt[(q*4+2)*9 + tp], a3 = wgt[(q*4+3)*9 + tp];
            PACKF2(wsm[s][q][tp][0], a0, a1);
            PACKF2(wsm[s][q][tp][1], a2, a3);
        }
        for (int i = t; i < 64; i += 256){
            ssm[s][i] = *(const float4*)(sc + i*4);
            bsm[s][i] = *(const float4*)(bi + i*4);
        }
    }
    __syncthreads();

    const float* x = pick_x(src);
    int q  = t & 63;
    int c0 = q*4;
    int lane = t >> 6;
    for (int hw = blockIdx.x*4 + lane; hw < HW; hw += gridDim.x*4){
        int w = hw % W, h = hw / W;
        ulonglong2 tap[9];
        #pragma unroll
        for (int dy = 0; dy < 3; ++dy){
            int yy = h + dy - 1;
            #pragma unroll
            for (int dx = 0; dx < 3; ++dx){
                int xx = w + dx - 1;
                int tp = dy*3 + dx;
                if (yy >= 0 && yy < H && xx >= 0 && xx < W)
                    tap[tp] = *(const ulonglong2*)(x + ((size_t)(n*H+yy)*W + xx)*CH + c0);
                else { tap[tp].x = 0ull; tap[tp].y = 0ull; }
            }
        }
        #pragma unroll 3
        for (int s = 0; s < 3; ++s){
            if (s >= nsets) break;
            unsigned long long a01 = 0ull, a23 = 0ull;
            #pragma unroll
            for (int tp = 0; tp < 9; ++tp){
                FMAF2(a01, tap[tp].x, wsm[s][q][tp][0], a01);
                FMAF2(a23, tap[tp].y, wsm[s][q][tp][1], a23);
            }
            float ax, ay, az, aw;
            UNPACKF2(ax, ay, a01);
            UNPACKF2(az, aw, a23);
            float4 s4 = ssm[s][q], b4 = bsm[s][q];
            float4 o;
            float t0 = ax*s4.x + b4.x; o.x = t0/(1.f+expf(-t0));
            float t1 = ay*s4.y + b4.y; o.y = t1/(1.f+expf(-t1));
            float t2 = az*s4.z + b4.z; o.z = t2/(1.f+expf(-t2));
            float t3 = aw*s4.w + b4.w; o.w = t3/(1.f+expf(-t3));
            float* dst = g_dwb + (size_t)SRC_DST[src][s]*NB*CH;
            *(float4*)(dst + ((size_t)n*HW + hw)*CH + c0) = o;
        }
    }
}

// ---------------- grouped conv 256->108, per-group blocks, FFMA2 ----
template<int STRIDE, int PXO, int TPX, int PXQ, int THREADS>
__global__ void __launch_bounds__(THREADS)
k_om3(int H, int W, int Ho, int Wo, const float* __restrict__ ob, int bA, int bB){
    constexpr int PW  = (PXO-1)*STRIDE + 3;
    constexpr int PWP = (PW + 3) & ~3;
    constexpr int WIN = 3 + (TPX-1)*STRIDE;
    static_assert((TPX*STRIDE) % 4 == 0, "window alignment");
    static_assert(WIN <= 8, "window fits two float4");
    extern __shared__ float sh[];
    float* patch = sh;
    float* wsl   = sh + 64*PWP;

    int br   = blockIdx.z == 0 ? bA : bB;
    const float* src = g_dwb + (size_t)DWPFX[br]*NB*CH;
    float* dst       = g_om  + (size_t)OMPFX[br]*NB*OMC;

    int nt   = (Wo + PXO - 1)/PXO;
    int g    = blockIdx.y;
    int b    = blockIdx.x;
    int tile = b % nt;
    int ho   = (b/nt) % Ho;
    int n    = b/(nt*Ho);
    int wo0  = tile*PXO;
    int hsrc = ho*STRIDE;
    int wsrc0= wo0*STRIDE;
    int cb   = g*64;

    int t   = threadIdx.x;
    int pxq = t % PXQ;
    int li  = t / PXQ;
    bool act = li < 7;
    int xb  = pxq*TPX*STRIDE;

    unsigned long long a01[TPX], a23[TPX];
    #pragma unroll
    for (int p = 0; p < TPX; ++p){ a01[p] = 0ull; a23[p] = 0ull; }

    const float* wsrc_base = g_wT2 + g*28;
    for (int dy = 0; dy < 3; ++dy){
        __syncthreads();
        int gy = hsrc + dy - 1;
        for (int i = t; i < PW*64; i += THREADS){
            int c = i & 63, xx = i >> 6;
            int gx = wsrc0 + xx - 1;
            float v = 0.f;
            if (gy >= 0 && gy < H && gx >= 0 && gx < W)
                v = src[((size_t)(n*H+gy)*W + gx)*CH + cb + c];
            patch[c*PWP + xx] = v;
        }
        {
            const float* ws = wsrc_base + dy*192*112;
            for (int i = t; i < 192*7; i += THREADS){
                int row = i/7, col = (i%7)*4;
                *(float4*)(wsl + row*28 + col) = *(const float4*)(ws + row*112 + col);
            }
        }
        __syncthreads();
        if (act){
            #pragma unroll 4
            for (int ic = 0; ic < 64; ++ic){
                const float* pr = patch + ic*PWP + xb;
                float f[8];
                *(float4*)(f)   = *(const float4*)(pr);
                *(float4*)(f+4) = *(const float4*)(pr+4);
                unsigned long long sv[WIN];
                #pragma unroll
                for (int k2 = 0; k2 < WIN; ++k2) PACKF2(sv[k2], f[k2], f[k2]);
                const float* wb = wsl + (ic*3)*28 + li*4;
                #pragma unroll
                for (int dx = 0; dx < 3; ++dx){
                    ulonglong2 wv = *(const ulonglong2*)(wb + dx*28);
                    #pragma unroll
                    for (int p = 0; p < TPX; ++p){
                        FMAF2(a01[p], sv[dx + p*STRIDE], wv.x, a01[p]);
                        FMAF2(a23[p], sv[dx + p*STRIDE], wv.y, a23[p]);
                    }
                }
            }
        }
    }
    if (act){
        float bj[4];
        #pragma unroll
        for (int j = 0; j < 4; ++j){
            int jj = li*4 + j;
            bj[j] = (jj < 27) ? ob[g*27 + jj] : 0.f;
        }
        #pragma unroll
        for (int p = 0; p < TPX; ++p){
            int wo = wo0 + pxq*TPX + p;
            if (wo < Wo){
                size_t base = ((size_t)(n*Ho+ho)*Wo + wo)*OMC + g*27 + li*4;
                float av[4];
                UNPACKF2(av[0], av[1], a01[p]);
                UNPACKF2(av[2], av[3], a23[p]);
                #pragma unroll
                for (int j = 0; j < 4; ++j)
                    if (li*4 + j < 27) dst[base + j] = av[j] + bj[j];
            }
        }
    }
}

// ---------------- batched DCNv3 sampler: 8 px/block, 2 px/thread ----------------
__global__ void k_sampB(){
    __shared__ float som[8][OMC];
    __shared__ float smk[8][36];
    __shared__ float sw[8][4][9][4];
    __shared__ int   soff[8][4][9][4];
    int bx = blockIdx.x;
    int b = 0;
    #pragma unroll
    for (int i = 1; i < 7; ++i) if (bx >= SAMP_PFX8[i]) b = i;
    int n = blockIdx.y;
    int p0 = (bx - SAMP_PFX8[b])*8;
    int Ho = BR_HO[b], Wo = Ho, HW = Ho*Wo;
    int H  = BR_HS[b], W = H;
    int stride = BR_STRIDE[b];
    int use_softmax = BR_SOFT[b];
    const float* x = pick_x(BR_SRC[b]);
    const float* omp = g_om + ((size_t)OMPFX[b]*NB + (size_t)n*HW)*OMC;
    int t = threadIdx.x;

    for (int i = t; i < 8*OMC; i += 256)
        som[i/OMC][i%OMC] = omp[(size_t)(p0 + i/OMC)*OMC + i%OMC];
    __syncthreads();

    if (use_softmax){
        if (t < 32){
            int pp = t >> 2, gg = t & 3;
            float mx = -1e30f;
            #pragma unroll
            for (int k = 0; k < 9; ++k) mx = fmaxf(mx, som[pp][72 + gg*9 + k]);
            float e[9], s = 0.f;
            #pragma unroll
            for (int k = 0; k < 9; ++k){ e[k] = expf(som[pp][72 + gg*9 + k] - mx); s += e[k]; }
            float inv = 1.f/s;
            #pragma unroll
            for (int k = 0; k < 9; ++k) smk[pp][gg*9 + k] = e[k]*inv;
        }
    } else {
        for (int i = t; i < 8*36; i += 256)
            smk[i/36][i%36] = 1.f/(1.f + expf(-som[i/36][72 + i%36]));
    }
    __syncthreads();

    for (int i = t; i < 288; i += 256){
        int pix = i / 36, r = i % 36, gg = r / 9, k = r % 9;
        int hw = p0 + pix;
        int wo = hw % Wo, ho = hw / Wo;
        float py = (float)(ho*stride) + (float)(k/3 - 1) + som[pix][gg*18 + k*2];
        float px = (float)(wo*stride) + (float)(k%3 - 1) + som[pix][gg*18 + k*2 + 1];
        float m  = smk[pix][gg*9 + k];
        float fy = floorf(py), fx = floorf(px);
        float wy = py - fy, wx = px - fx;
        int iy = (int)fy, ix = (int)fx;
        #pragma unroll
        for (int d0 = 0; d0 < 2; ++d0){
            int yy = iy + d0;
            float wgy = d0 ? wy : (1.f - wy);
            #pragma unroll
            for (int d1 = 0; d1 < 2; ++d1){
                int xx = ix + d1;
                bool valid = (yy >= 0) & (yy < H) & (xx >= 0) & (xx < W);
                int yc = min(max(yy, 0), H-1);
                int xc = min(max(xx, 0), W-1);
                sw[pix][gg][k][d0*2+d1]   = valid ? wgy*(d1 ? wx : (1.f - wx))*m : 0.f;
                soff[pix][gg][k][d0*2+d1] = ((n*H + yc)*W + xc)*CH;
            }
        }
    }
    __syncthreads();

    int lane = t >> 6, q = t & 63, c0 = q*4, g = q >> 4;
    const float* xc = x + c0;
    #pragma unroll
    for (int pi = 0; pi < 2; ++pi){
        int pix = lane + pi*4;
        unsigned long long acc01 = 0ull, acc23 = 0ull;
        #pragma unroll
        for (int k = 0; k < 9; ++k){
            float4 wv = *(const float4*)&sw[pix][g][k][0];
            int4  ov = *(const int4*)&soff[pix][g][k][0];
            unsigned long long w0, w1, w2, w3;
            PACKF2(w0, wv.x, wv.x); PACKF2(w1, wv.y, wv.y);
            PACKF2(w2, wv.z, wv.z); PACKF2(w3, wv.w, wv.w);
            ulonglong2 v0 = *(const ulonglong2*)(xc + ov.x);
            ulonglong2 v1 = *(const ulonglong2*)(xc + ov.y);
            ulonglong2 v2 = *(const ulonglong2*)(xc + ov.z);
            ulonglong2 v3 = *(const ulonglong2*)(xc + ov.w);
            FMAF2(acc01, v0.x, w0, acc01); FMAF2(acc23, v0.y, w0, acc23);
            FMAF2(acc01, v1.x, w1, acc01); FMAF2(acc23, v1.y, w1, acc23);
            FMAF2(acc01, v2.x, w2, acc01); FMAF2(acc23, v2.y, w2, acc23);
            FMAF2(acc01, v3.x, w3, acc01); FMAF2(acc23, v3.y, w3, acc23);
        }
        float4 acc;
        UNPACKF2(acc.x, acc.y, acc01);
        UNPACKF2(acc.z, acc.w, acc23);
        *(float4*)(g_feat + ((size_t)OMPFX[b]*NB + (size_t)n*HW + p0 + pix)*CH + c0) = acc;
    }
}

// ---------------- batched stats ----------------
__global__ void k_statsB(){
    __shared__ float wy[80], wx[80];
    __shared__ float r1[256], r2[256];
    __shared__ float4 rw[256];
    int b = blockIdx.x >> 4, g = blockIdx.x & 15, n = blockIdx.y;
    int Hs = BR_HO[b], Ws = Hs, HW = Hs*Ws;
    int uph = BR_UPH[b];
    float normw = uph ? 1.f/((float)uph*(float)uph) : 1.f/(float)HW;
    int t = threadIdx.x;
    if (t == 0){
        if (uph){
            for (int i = 0; i < Hs; ++i){ wy[i] = 0.f; wx[i] = 0.f; }
            float ry = (float)(Hs-1)/(float)(uph-1);
            for (int j = 0; j < uph; ++j){
                float c = j*ry; int i0 = (int)floorf(c); float f = c - (float)i0;
                wy[i0] += 1.f - f;
                if (i0 + 1 < Hs) wy[i0+1] += f;
            }
            for (int i = 0; i < Hs; ++i) wx[i] = wy[i];
        } else {
            for (int i = 0; i < Hs; ++i){ wy[i] = 1.f; wx[i] = 1.f; }
        }
    }
    __syncthreads();

    const float* fb = g_feat + ((size_t)OMPFX[b]*NB + (size_t)n*HW)*CH;
    int q  = t & 3;
    int c0 = g*16 + q*4;
    float4 s4 = make_float4(0,0,0,0), w4 = make_float4(0,0,0,0);
    float ss = 0.f;
    int hw0 = t >> 2;
    int h = hw0 / Ws, w = hw0 % Ws;
    for (int hw = hw0; hw < HW; hw += 64){
        float4 v = *(const float4*)(fb + (size_t)hw*CH + c0);
        s4.x += v.x; s4.y += v.y; s4.z += v.z; s4.w += v.w;
        ss += v.x*v.x + v.y*v.y + v.z*v.z + v.w*v.w;
        float ww = wy[h]*wx[w];
        w4.x += v.x*ww; w4.y += v.y*ww; w4.z += v.z*ww; w4.w += v.w*ww;
        w += 64; while (w >= Ws){ w -= Ws; ++h; }
    }
    r1[t] = s4.x + s4.y + s4.z + s4.w;
    r2[t] = ss;
    rw[t] = w4;
    __syncthreads();
    for (int o = 128; o >= 4; o >>= 1){
        if (t < o){
            r1[t] += r1[t+o]; r2[t] += r2[t+o];
            rw[t].x += rw[t+o].x; rw[t].y += rw[t+o].y;
            rw[t].z += rw[t+o].z; rw[t].w += rw[t+o].w;
        }
        __syncthreads();
    }
    if (t == 0){
        float s  = r1[0] + r1[1] + r1[2] + r1[3];
        float sq = r2[0] + r2[1] + r2[2] + r2[3];
        float cnt = (float)HW*16.f;
        float mu  = s/cnt;
        float var = sq/cnt - mu*mu;
        g_gmu [(b*NB+n)*16 + g] = mu;
        g_ginv[(b*NB+n)*16 + g] = rsqrtf(var + 1e-5f);
    }
    if (t < 4){
        float4 wv = rw[t];
        int c = (b*NB+n)*CH + g*16 + t*4;
        g_cmean[c]   = wv.x*normw; g_cmean[c+1] = wv.y*normw;
        g_cmean[c+2] = wv.z*normw; g_cmean[c+3] = wv.w*normw;
    }
}

// ---------------- attn scalars + pooled means ----------------
__device__ __constant__ int LVL_NBR[3] = {2,3,2};
__device__ __constant__ int LVL_BRS[3][3] = {{0,1,-1},{2,3,4},{5,6,-1}};

__global__ void k_attnB(const float* __restrict__ saw, const float* __restrict__ sab,
                        const float* __restrict__ gm, const float* __restrict__ bm,
                        const float* __restrict__ gh, const float* __restrict__ bh,
                        const float* __restrict__ gl, const float* __restrict__ bl){
    __shared__ float red[256];
    __shared__ float sa;
    int lvl = blockIdx.x, n = blockIdx.y, t = threadIdx.x;
    int g = t >> 4;
    int nbr = LVL_NBR[lvl];
    float invl = 1.f/(float)nbr;
    float y = 0.f;
    for (int i = 0; i < nbr; ++i){
        int b = LVL_BRS[lvl][i];
        int gs = BR_GNSEL[b];
        const float* gam = gs==0 ? gm : (gs==1 ? gh : gl);
        const float* bet = gs==0 ? bm : (gs==1 ? bh : bl);
        float m = (g_cmean[(b*NB+n)*CH + t] - g_gmu[(b*NB+n)*16 + g])
                  * g_ginv[(b*NB+n)*16 + g] * gam[t] + bet[t];
        red[t] = m*saw[t];
        __syncthreads();
        for (int o = 128; o > 0; o >>= 1){
            if (t < o) red[t] += red[t+o];
            __syncthreads();
        }
        if (t == 0){
            float a = red[0] + sab[0];
            a = fmaxf(a, 0.f);
            a = fminf(fmaxf((a + 3.f)/6.f, 0.f), 1.f);
            sa = a; g_a[b*NB + n] = a;
        }
        __syncthreads();
        y += sa*m*invl;
        __syncthreads();
    }
    g_y[(lvl*NB + n)*CH + t] = y;
}

// ---------------- fc (all levels) ----------------
__global__ void k_fcB(const float* __restrict__ w1, const float* __restrict__ b1,
                      const float* __restrict__ w2, const float* __restrict__ b2){
    __shared__ float h[4][64];
    int lvl = blockIdx.x;
    int t = threadIdx.x;
    int n = t >> 6, j = t & 63;
    float s = b1[j];
    const float* wr = w1 + j*CH;
    const float* yv = g_y + (lvl*NB + n)*CH;
    for (int c = 0; c < CH; ++c) s += yv[c]*wr[c];
    h[n][j] = fmaxf(s, 0.f);
    __syncthreads();
    for (int og = t; og < NB*1024; og += 256){
        int nn = og >> 10, o = og & 1023;
        float s2 = b2[o];
        const float* w2r = w2 + o*64;
        #pragma unroll 16
        for (int j2 = 0; j2 < 64; ++j2) s2 += h[nn][j2]*w2r[j2];
        float z = fminf(fmaxf(s2 + 3.f, 0.f), 6.f)*(1.f/6.f);
        int qd = o >> 8;
        float v;
        if      (qd == 0) v = (z - 0.5f)*2.f + 1.f;
        else if (qd == 2) v = (z - 0.5f)*2.f;
        else              v = z - 0.5f;
        g_z[(lvl*NB + nn)*1024 + o] = v;
    }
}

// ---------------- fused: GN+attn+upsample sum -> dyrelu -> NCHW out ----------
__device__ __forceinline__ void gn_acc(float4& o, float4 raw, int b, int n, int g,
                                       float4 g4, float4 b4){
    float mu = g_gmu[(b*NB+n)*16 + g], inv = g_ginv[(b*NB+n)*16 + g], a = g_a[b*NB + n];
    o.x += a*((raw.x - mu)*inv*g4.x + b4.x);
    o.y += a*((raw.y - mu)*inv*g4.y + b4.y);
    o.z += a*((raw.z - mu)*inv*g4.z + b4.z);
    o.w += a*((raw.w - mu)*inv*g4.w + b4.w);
}
__device__ __forceinline__ float4 feat_rd(int b, int n, int HW, int hw, int c0){
    return *(const float4*)(g_feat + ((size_t)OMPFX[b]*NB + (size_t)n*HW + hw)*CH + c0);
}
__device__ __forceinline__ float4 feat_up(int b, int n, int Hs, int Ho, int h, int w, int c0){
    float r = (float)(Hs-1)/(float)(Ho-1);
    float cy = h*r, cx = w*r;
    int y0 = (int)floorf(cy), x0 = (int)floorf(cx);
    int y1 = min(y0+1, Hs-1), x1 = min(x0+1, Hs-1);
    float wyf = cy - (float)y0, wxf = cx - (float)x0;
    const float* fb = g_feat + ((size_t)OMPFX[b]*NB + (size_t)n*Hs*Hs)*CH + c0;
    float4 v00 = *(const float4*)(fb + (size_t)(y0*Hs + x0)*CH);
    float4 v01 = *(const float4*)(fb + (size_t)(y0*Hs + x1)*CH);
    float4 v10 = *(const float4*)(fb + (size_t)(y1*Hs + x0)*CH);
    float4 v11 = *(const float4*)(fb + (size_t)(y1*Hs + x1)*CH);
    float a0 = (1.f-wyf)*(1.f-wxf), a1 = (1.f-wyf)*wxf, a2 = wyf*(1.f-wxf), a3 = wyf*wxf;
    float4 o;
    o.x = v00.x*a0 + v01.x*a1 + v10.x*a2 + v11.x*a3;
    o.y = v00.y*a0 + v01.y*a1 + v10.y*a2 + v11.y*a3;
    o.z = v00.z*a0 + v01.z*a1 + v10.z*a2 + v11.z*a3;
    o.w = v00.w*a0 + v01.w*a1 + v10.w*a2 + v11.w*a3;
    return o;
}

template<int LVL>
__global__ void k_outL(float* __restrict__ out,
                       const float* __restrict__ gm, const float* __restrict__ bm,
                       const float* __restrict__ gh, const float* __restrict__ bh,
                       const float* __restrict__ gl, const float* __restrict__ bl){
    constexpr int HoL = (LVL==0) ? 80 : (LVL==1 ? 40 : 20);
    constexpr int HWL = HoL*HoL;
    constexpr float INVL = (LVL==1) ? (1.f/3.f) : 0.5f;
    __shared__ float tile[32][257];
    int n   = blockIdx.y;
    int hw0 = blockIdx.x*32;
    int tx = threadIdx.x, ty = threadIdx.y;
    int tid = ty*32 + tx;

    #pragma unroll
    for (int k = 0; k < 8; ++k){
        int e = k*256 + tid;
        int hwl = e >> 6;
        int q   = e & 63;
        int hw  = hw0 + hwl;
        if (hw < HWL){
            int c0 = q*4, g = q >> 2;
            int w = hw % HoL, h = hw / HoL;
            float4 o = make_float4(0,0,0,0);
            float4 g4, b4;
            if (LVL == 0){
                g4 = *(const float4*)(gm + c0); b4 = *(const float4*)(bm + c0);
                gn_acc(o, feat_rd(0, n, 6400, hw, c0), 0, n, g, g4, b4);
                g4 = *(const float4*)(gh + c0); b4 = *(const float4*)(bh + c0);
                gn_acc(o, feat_up(1, n, 40, 80, h, w, c0), 1, n, g, g4, b4);
            } else if (LVL == 1){
                g4 = *(const float4*)(gm + c0); b4 = *(const float4*)(bm + c0);
                gn_acc(o, feat_rd(2, n, 1600, hw, c0), 2, n, g, g4, b4);
                g4 = *(const float4*)(gl + c0); b4 = *(const float4*)(bl + c0);
                gn_acc(o, feat_rd(3, n, 1600, hw, c0), 3, n, g, g4, b4);
                g4 = *(const float4*)(gh + c0); b4 = *(const float4*)(bh + c0);
                gn_acc(o, feat_up(4, n, 20, 40, h, w, c0), 4, n, g, g4, b4);
            } else {
                g4 = *(const float4*)(gm + c0); b4 = *(const float4*)(bm + c0);
                gn_acc(o, feat_rd(5, n, 400, hw, c0), 5, n, g, g4, b4);
                g4 = *(const float4*)(gl + c0); b4 = *(const float4*)(bl + c0);
                gn_acc(o, feat_rd(6, n, 400, hw, c0), 6, n, g, g4, b4);
            }
            tile[hwl][c0]   = o.x;
            tile[hwl][c0+1] = o.y;
            tile[hwl][c0+2] = o.z;
            tile[hwl][c0+3] = o.w;
        }
    }
    __syncthreads();

    int hw = hw0 + tx;
    if (hw < HWL){
        const float* zb = g_z + (LVL*NB + n)*1024;
        #pragma unroll
        for (int k = 0; k < 32; ++k){
            int c = ty + k*8;
            float f = tile[tx][c]*INVL;
            float a1 = zb[c], b1 = zb[256 + c];
            float a2 = zb[512 + c], b2 = zb[768 + c];
            out[((size_t)n*CH + c)*HWL + hw] = fmaxf(f*a1 + b1, f*a2 + b2);
        }
    }
}

// ---------------- host: multi-stream fork/join (graph-capturable) ----------------
extern "C" void kernel_launch(void* const* d_in, const int* in_sizes, int n_in,
                              void* d_out, int out_size){
    const float* x0     = (const float*)d_in[0];
    const float* x1     = (const float*)d_in[1];
    const float* x2     = (const float*)d_in[2];
    const float* dw_w_h = (const float*)d_in[3];
    const float* dw_s_h = (const float*)d_in[4];
    const float* dw_b_h = (const float*)d_in[5];
    const float* dw_w_m = (const float*)d_in[6];
    const float* dw_s_m = (const float*)d_in[7];
    const float* dw_b_m = (const float*)d_in[8];
    const float* dw_w_l = (const float*)d_in[9];
    const float* dw_s_l = (const float*)d_in[10];
    const float* dw_b_l = (const float*)d_in[11];
    const float* off_w  = (const float*)d_in[12];
    const float* off_b  = (const float*)d_in[13];
    const float* gn_g_h = (const float*)d_in[14];
    const float* gn_b_h = (const float*)d_in[15];
    const float* gn_g_m = (const float*)d_in[16];
    const float* gn_b_m = (const float*)d_in[17];
    const float* gn_g_l = (const float*)d_in[18];
    const float* gn_b_l = (const float*)d_in[19];
    const float* sa_w   = (const float*)d_in[20];
    const float* sa_b   = (const float*)d_in[21];
    const float* fc1_w  = (const float*)d_in[22];
    const float* fc1_b  = (const float*)d_in[23];
    const float* fc2_w  = (const float*)d_in[24];
    const float* fc2_b  = (const float*)d_in[25];
    float* out = (float*)d_out;

    // lazy stream/event creation (first call is the uncaptured correctness run)
    static cudaStream_t s1, s2, s3;
    static cudaEvent_t eFork, eT1, eT2, eDw, eWt, eO1, eO2, eO3, eFc, eL1, eL2;
    static bool inited = false;
    if (!inited){
        cudaStreamCreateWithFlags(&s1, cudaStreamNonBlocking);
        cudaStreamCreateWithFlags(&s2, cudaStreamNonBlocking);
        cudaStreamCreateWithFlags(&s3, cudaStreamNonBlocking);
        cudaEventCreateWithFlags(&eFork, cudaEventDisableTiming);
        cudaEventCreateWithFlags(&eT1,  cudaEventDisableTiming);
        cudaEventCreateWithFlags(&eT2,  cudaEventDisableTiming);
        cudaEventCreateWithFlags(&eDw,  cudaEventDisableTiming);
        cudaEventCreateWithFlags(&eWt,  cudaEventDisableTiming);
        cudaEventCreateWithFlags(&eO1,  cudaEventDisableTiming);
        cudaEventCreateWithFlags(&eO2,  cudaEventDisableTiming);
        cudaEventCreateWithFlags(&eO3,  cudaEventDisableTiming);
        cudaEventCreateWithFlags(&eFc,  cudaEventDisableTiming);
        cudaEventCreateWithFlags(&eL1,  cudaEventDisableTiming);
        cudaEventCreateWithFlags(&eL2,  cudaEventDisableTiming);
        inited = true;
    }
    cudaStream_t s0 = 0;   // capture-origin (legacy) stream

    // fork
    cudaEventRecord(eFork, s0);
    cudaStreamWaitEvent(s1, eFork, 0);
    cudaStreamWaitEvent(s2, eFork, 0);
    cudaStreamWaitEvent(s3, eFork, 0);

    // stage 1: transposes concurrent; dwS stays at global launch index 3
    k_tr2<<<dim3(200, 8, NB), dim3(32,8), 0, s0>>>(x0, 0, 6400);
    k_tr2<<<dim3(50,  8, NB), dim3(32,8), 0, s1>>>(x1, 1, 1600);
    k_tr2<<<dim3(13,  8, NB), dim3(32,8), 0, s2>>>(x2, 2,  400);
    cudaEventRecord(eT1, s1);
    cudaEventRecord(eT2, s2);
    cudaStreamWaitEvent(s0, eT1, 0);
    cudaStreamWaitEvent(s0, eT2, 0);
    k_dwS<<<dim3(200, 3, NB), 256, 0, s0>>>(dw_w_m, dw_s_m, dw_b_m,
                                            dw_w_h, dw_s_h, dw_b_h,
                                            dw_w_l, dw_s_l, dw_b_l);
    cudaEventRecord(eDw, s0);
    k_wt2<<<(3*192*112 + 255)/256, 256, 0, s3>>>(off_w);
    cudaEventRecord(eWt, s3);

    // stage 2: om launches concurrent on 4 streams (all need dwS + wt2)
    cudaStreamWaitEvent(s0, eWt, 0);
    cudaStreamWaitEvent(s1, eDw, 0); cudaStreamWaitEvent(s1, eWt, 0);
    cudaStreamWaitEvent(s2, eDw, 0); cudaStreamWaitEvent(s2, eWt, 0);
    cudaStreamWaitEvent(s3, eDw, 0);
    {
        const int SM80 = (64*52 + 192*28)*4;
        k_om3<1,48,4,12,96><<<dim3(2*80*NB, 4, 1), 96, SM80, s0>>>(80, 80, 80, 80, off_b, 0, 0);
        const int SM40 = (64*44 + 192*28)*4;
        k_om3<1,40,4,10,80><<<dim3(1*40*NB, 4, 2), 80, SM40, s1>>>(40, 40, 40, 40, off_b, 1, 2);
        k_om3<2,20,2,10,80><<<dim3(2*40*NB, 4, 1), 80, SM40, s2>>>(80, 80, 40, 40, off_b, 3, 3);
        const int SM20 = (64*24 + 192*28)*4;
        k_om3<1,20,4,5,64><<<dim3(1*20*NB, 4, 2), 64, SM20, s3>>>(20, 20, 20, 20, off_b, 4, 5);
        k_om3<2,20,2,10,80><<<dim3(1*20*NB, 4, 1), 80, SM40, s3>>>(40, 40, 20, 20, off_b, 6, 6);
    }
    cudaEventRecord(eO1, s1);
    cudaEventRecord(eO2, s2);
    cudaEventRecord(eO3, s3);
    cudaStreamWaitEvent(s0, eO1, 0);
    cudaStreamWaitEvent(s0, eO2, 0);
    cudaStreamWaitEvent(s0, eO3, 0);

    // stage 3: sampling, stats, attn, fc (dependent chain)
    k_sampB <<<dim3(1550, NB), 256, 0, s0>>>();
    k_statsB<<<dim3(7*16, NB), 256, 0, s0>>>();
    k_attnB <<<dim3(3, NB),    256, 0, s0>>>(sa_w, sa_b, gn_g_m, gn_b_m, gn_g_h, gn_b_h, gn_g_l, gn_b_l);
    k_fcB   <<<3,              256, 0, s0>>>(fc1_w, fc1_b, fc2_w, fc2_b);
    cudaEventRecord(eFc, s0);
    cudaStreamWaitEvent(s1, eFc, 0);
    cudaStreamWaitEvent(s2, eFc, 0);

    // stage 4: fused outputs concurrent
    k_outL<0><<<dim3(200, NB), dim3(32,8), 0, s0>>>(out,
        gn_g_m, gn_b_m, gn_g_h, gn_b_h, gn_g_l, gn_b_l);
    k_outL<1><<<dim3(50, NB),  dim3(32,8), 0, s1>>>(out + (size_t)NB*CH*6400,
        gn_g_m, gn_b_m, gn_g_h, gn_b_h, gn_g_l, gn_b_l);
    k_outL<2><<<dim3(13, NB),  dim3(32,8), 0, s2>>>(out + (size_t)NB*CH*8000,
        gn_g_m, gn_b_m, gn_g_h, gn_b_h, gn_g_l, gn_b_l);
    cudaEventRecord(eL1, s1);
    cudaEventRecord(eL2, s2);
    cudaStreamWaitEvent(s0, eL1, 0);
    cudaStreamWaitEvent(s0, eL2, 0);
}

// round 9
// speedup vs baseline: 1.1906x; 1.0541x over previous
#include <cuda_runtime.h>
#include <math.h>

#define NB   4
#define CH   256
#define OMC  108

// ---- packed f32x2 ops ----
#define PACKF2(out, lo, hi) \
    asm("mov.b64 %0, {%1, %2};" : "=l"(out) : "f"(lo), "f"(hi))
#define UNPACKF2(lo, hi, in) \
    asm("mov.b64 {%0, %1}, %2;" : "=f"(lo), "=f"(hi) : "l"(in))
#define FMAF2(d, a, b, c) \
    asm("fma.rn.f32x2 %0, %1, %2, %3;" : "=l"(d) : "l"(a), "l"(b), "l"(c))

// ---- branch tables (7 branches) ----
__device__ __constant__ int BR_SRC[7]    = {0,1,1,0,2,2,1};
__device__ __constant__ int BR_HS[7]     = {80,40,40,80,20,20,40};
__device__ __constant__ int BR_STRIDE[7] = {1,1,1,2,1,1,2};
__device__ __constant__ int BR_HO[7]     = {80,40,40,40,20,20,20};
__device__ __constant__ int BR_SOFT[7]   = {0,1,0,1,1,0,1};
__device__ __constant__ int BR_UPH[7]    = {0,80,0,0,40,0,0};
__device__ __constant__ int BR_GNSEL[7]  = {0,1,0,2,1,0,2};
__device__ __constant__ int DWPFX[7]     = {0,6400,8000,9600,16000,16400,16800};
__device__ __constant__ int OMPFX[7]     = {0,6400,8000,9600,11200,11600,12000};
__device__ __constant__ int SAMP_PFX8[7] = {0,800,1000,1200,1400,1450,1500};

__device__ __constant__ int SRC_NSETS[3]  = {2,3,2};
__device__ __constant__ int SRC_WSEL[3][3]= {{0,2,0},{1,0,2},{1,0,0}};
__device__ __constant__ int SRC_DST[3][3] = {{0,9600,0},{6400,8000,16800},{16000,16400,0}};

// ---------------- scratch ----------------
__device__ float g_x0[NB*80*80*CH];
__device__ float g_x1[NB*40*40*CH];
__device__ float g_x2[NB*20*20*CH];
__device__ float g_dwb[18400*NB*CH];
__device__ float g_om [12400*NB*OMC];
__device__ float g_feat[12400*NB*CH];
__device__ float g_wT2[3*192*112];
__device__ float g_a[7*NB];
__device__ float g_y[3*NB*CH];
__device__ float g_z[3*NB*1024];
__device__ float g_cmean[7*NB*CH];
__device__ float g_gmu[7*NB*16];
__device__ float g_ginv[7*NB*16];

__device__ __forceinline__ const float* pick_x(int s){
    return s==0 ? g_x0 : (s==1 ? g_x1 : g_x2);
}
__device__ __forceinline__ float* pick_xm(int s){
    return s==0 ? g_x0 : (s==1 ? g_x1 : g_x2);
}

// ---------------- NCHW -> NHWC tiled transpose ----------------
__global__ void k_tr2(const float* __restrict__ in, int sel, int HW){
    __shared__ float tile[32][33];
    float* out = pick_xm(sel);
    int n  = blockIdx.z;
    int hw0 = blockIdx.x*32;
    int c0  = blockIdx.y*32;
    int tx = threadIdx.x, ty = threadIdx.y;
    #pragma unroll
    for (int q = 0; q < 4; ++q){
        int c = c0 + ty + q*8;
        int hw = hw0 + tx;
        float v = (hw < HW) ? in[((size_t)n*CH + c)*HW + hw] : 0.f;
        tile[ty + q*8][tx] = v;
    }
    __syncthreads();
    #pragma unroll
    for (int q = 0; q < 4; ++q){
        int hw = hw0 + ty + q*8;
        int c  = c0 + tx;
        if (hw < HW) out[((size_t)n*HW + hw)*CH + c] = tile[tx][ty + q*8];
    }
}

// weight transform: [dy][ic*3+dx][slot(4g x 28)]
__global__ void k_wt2(const float* __restrict__ ow){
    int i = blockIdx.x*blockDim.x + threadIdx.x;
    if (i >= 3*192*112) return;
    int slot = i % 112;
    int r    = (i / 112) % 192;
    int dy   = i / (112*192);
    int ic = r/3, dx = r%3;
    int g = slot/28, jj = slot%28;
    float v = 0.f;
    if (jj < 27) v = ow[(g*27+jj)*576 + ic*9 + dy*3 + dx];
    g_wT2[i] = v;
}

// ---------------- shared-source depthwise conv (single source per launch) ----
__global__ void k_dwS(int src,
                      const float* __restrict__ wm, const float* __restrict__ sm_, const float* __restrict__ bm_,
                      const float* __restrict__ wh, const float* __restrict__ sh_, const float* __restrict__ bh_,
                      const float* __restrict__ wl, const float* __restrict__ sl_, const float* __restrict__ bl_){
    __shared__ unsigned long long wsm[3][64][9][2];
    __shared__ float4 ssm[3][64], bsm[3][64];
    int n = blockIdx.z;
    int H = (src==0) ? 80 : (src==1 ? 40 : 20);
    int W = H, HW = H*W;
    int nsets = SRC_NSETS[src];
    int t = threadIdx.x;

    for (int s = 0; s < nsets; ++s){
        int sel = SRC_WSEL[src][s];
        const float* wgt = sel==0 ? wm : (sel==1 ? wh : wl);
        const float* sc  = sel==0 ? sm_ : (sel==1 ? sh_ : sl_);
        const float* bi  = sel==0 ? bm_ : (sel==1 ? bh_ : bl_);
        for (int i = t; i < 64*9; i += 256){
            int q = i/9, tp = i%9;
            float a0 = wgt[(q*4+0)*9 + tp], a1 = wgt[(q*4+1)*9 + tp];
            float a2 = wgt[(q*4+2)*9 + tp], a3 = wgt[(q*4+3)*9 + tp];
            PACKF2(wsm[s][q][tp][0], a0, a1);
            PACKF2(wsm[s][q][tp][1], a2, a3);
        }
        for (int i = t; i < 64; i += 256){
            ssm[s][i] = *(const float4*)(sc + i*4);
            bsm[s][i] = *(const float4*)(bi + i*4);
        }
    }
    __syncthreads();

    const float* x = pick_x(src);
    int q  = t & 63;
    int c0 = q*4;
    int lane = t >> 6;
    for (int hw = blockIdx.x*4 + lane; hw < HW; hw += gridDim.x*4){
        int w = hw % W, h = hw / W;
        ulonglong2 tap[9];
        #pragma unroll
        for (int dy = 0; dy < 3; ++dy){
            int yy = h + dy - 1;
            #pragma unroll
            for (int dx = 0; dx < 3; ++dx){
                int xx = w + dx - 1;
                int tp = dy*3 + dx;
                if (yy >= 0 && yy < H && xx >= 0 && xx < W)
                    tap[tp] = *(const ulonglong2*)(x + ((size_t)(n*H+yy)*W + xx)*CH + c0);
                else { tap[tp].x = 0ull; tap[tp].y = 0ull; }
            }
        }
        #pragma unroll 3
        for (int s = 0; s < 3; ++s){
            if (s >= nsets) break;
            unsigned long long a01 = 0ull, a23 = 0ull;
            #pragma unroll
            for (int tp = 0; tp < 9; ++tp){
                FMAF2(a01, tap[tp].x, wsm[s][q][tp][0], a01);
                FMAF2(a23, tap[tp].y, wsm[s][q][tp][1], a23);
            }
            float ax, ay, az, aw;
            UNPACKF2(ax, ay, a01);
            UNPACKF2(az, aw, a23);
            float4 s4 = ssm[s][q], b4 = bsm[s][q];
            float4 o;
            float t0 = ax*s4.x + b4.x; o.x = t0/(1.f+expf(-t0));
            float t1 = ay*s4.y + b4.y; o.y = t1/(1.f+expf(-t1));
            float t2 = az*s4.z + b4.z; o.z = t2/(1.f+expf(-t2));
            float t3 = aw*s4.w + b4.w; o.w = t3/(1.f+expf(-t3));
            float* dst = g_dwb + (size_t)SRC_DST[src][s]*NB*CH;
            *(float4*)(dst + ((size_t)n*HW + hw)*CH + c0) = o;
        }
    }
}

// ---------------- grouped conv 256->108, per-group blocks, FFMA2 ----
template<int STRIDE, int PXO, int TPX, int PXQ, int THREADS>
__global__ void __launch_bounds__(THREADS)
k_om3(int H, int W, int Ho, int Wo, const float* __restrict__ ob, int bA, int bB){
    constexpr int PW  = (PXO-1)*STRIDE + 3;
    constexpr int PWP = (PW + 3) & ~3;
    constexpr int WIN = 3 + (TPX-1)*STRIDE;
    static_assert((TPX*STRIDE) % 4 == 0, "window alignment");
    static_assert(WIN <= 8, "window fits two float4");
    extern __shared__ float sh[];
    float* patch = sh;
    float* wsl   = sh + 64*PWP;

    int br   = blockIdx.z == 0 ? bA : bB;
    const float* src = g_dwb + (size_t)DWPFX[br]*NB*CH;
    float* dst       = g_om  + (size_t)OMPFX[br]*NB*OMC;

    int nt   = (Wo + PXO - 1)/PXO;
    int g    = blockIdx.y;
    int b    = blockIdx.x;
    int tile = b % nt;
    int ho   = (b/nt) % Ho;
    int n    = b/(nt*Ho);
    int wo0  = tile*PXO;
    int hsrc = ho*STRIDE;
    int wsrc0= wo0*STRIDE;
    int cb   = g*64;

    int t   = threadIdx.x;
    int pxq = t % PXQ;
    int li  = t / PXQ;
    bool act = li < 7;
    int xb  = pxq*TPX*STRIDE;

    unsigned long long a01[TPX], a23[TPX];
    #pragma unroll
    for (int p = 0; p < TPX; ++p){ a01[p] = 0ull; a23[p] = 0ull; }

    const float* wsrc_base = g_wT2 + g*28;
    for (int dy = 0; dy < 3; ++dy){
        __syncthreads();
        int gy = hsrc + dy - 1;
        for (int i = t; i < PW*64; i += THREADS){
            int c = i & 63, xx = i >> 6;
            int gx = wsrc0 + xx - 1;
            float v = 0.f;
            if (gy >= 0 && gy < H && gx >= 0 && gx < W)
                v = src[((size_t)(n*H+gy)*W + gx)*CH + cb + c];
            patch[c*PWP + xx] = v;
        }
        {
            const float* ws = wsrc_base + dy*192*112;
            for (int i = t; i < 192*7; i += THREADS){
                int row = i/7, col = (i%7)*4;
                *(float4*)(wsl + row*28 + col) = *(const float4*)(ws + row*112 + col);
            }
        }
        __syncthreads();
        if (act){
            #pragma unroll 4
            for (int ic = 0; ic < 64; ++ic){
                const float* pr = patch + ic*PWP + xb;
                float f[8];
                *(float4*)(f)   = *(const float4*)(pr);
                *(float4*)(f+4) = *(const float4*)(pr+4);
                unsigned long long sv[WIN];
                #pragma unroll
                for (int k2 = 0; k2 < WIN; ++k2) PACKF2(sv[k2], f[k2], f[k2]);
                const float* wb = wsl + (ic*3)*28 + li*4;
                #pragma unroll
                for (int dx = 0; dx < 3; ++dx){
                    ulonglong2 wv = *(const ulonglong2*)(wb + dx*28);
                    #pragma unroll
                    for (int p = 0; p < TPX; ++p){
                        FMAF2(a01[p], sv[dx + p*STRIDE], wv.x, a01[p]);
                        FMAF2(a23[p], sv[dx + p*STRIDE], wv.y, a23[p]);
                    }
                }
            }
        }
    }
    if (act){
        float bj[4];
        #pragma unroll
        for (int j = 0; j < 4; ++j){
            int jj = li*4 + j;
            bj[j] = (jj < 27) ? ob[g*27 + jj] : 0.f;
        }
        #pragma unroll
        for (int p = 0; p < TPX; ++p){
            int wo = wo0 + pxq*TPX + p;
            if (wo < Wo){
                size_t base = ((size_t)(n*Ho+ho)*Wo + wo)*OMC + g*27 + li*4;
                float av[4];
                UNPACKF2(av[0], av[1], a01[p]);
                UNPACKF2(av[2], av[3], a23[p]);
                #pragma unroll
                for (int j = 0; j < 4; ++j)
                    if (li*4 + j < 27) dst[base + j] = av[j] + bj[j];
            }
        }
    }
}

// ---------------- batched DCNv3 sampler (block-offset subset launch) ----------
__global__ void k_sampB(int bx0){
    __shared__ float som[8][OMC];
    __shared__ float smk[8][36];
    __shared__ float sw[8][4][9][4];
    __shared__ int   soff[8][4][9][4];
    int bx = blockIdx.x + bx0;
    int b = 0;
    #pragma unroll
    for (int i = 1; i < 7; ++i) if (bx >= SAMP_PFX8[i]) b = i;
    int n = blockIdx.y;
    int p0 = (bx - SAMP_PFX8[b])*8;
    int Ho = BR_HO[b], Wo = Ho, HW = Ho*Wo;
    int H  = BR_HS[b], W = H;
    int stride = BR_STRIDE[b];
    int use_softmax = BR_SOFT[b];
    const float* x = pick_x(BR_SRC[b]);
    const float* omp = g_om + ((size_t)OMPFX[b]*NB + (size_t)n*HW)*OMC;
    int t = threadIdx.x;

    for (int i = t; i < 8*OMC; i += 256)
        som[i/OMC][i%OMC] = omp[(size_t)(p0 + i/OMC)*OMC + i%OMC];
    __syncthreads();

    if (use_softmax){
        if (t < 32){
            int pp = t >> 2, gg = t & 3;
            float mx = -1e30f;
            #pragma unroll
            for (int k = 0; k < 9; ++k) mx = fmaxf(mx, som[pp][72 + gg*9 + k]);
            float e[9], s = 0.f;
            #pragma unroll
            for (int k = 0; k < 9; ++k){ e[k] = expf(som[pp][72 + gg*9 + k] - mx); s += e[k]; }
            float inv = 1.f/s;
            #pragma unroll
            for (int k = 0; k < 9; ++k) smk[pp][gg*9 + k] = e[k]*inv;
        }
    } else {
        for (int i = t; i < 8*36; i += 256)
            smk[i/36][i%36] = 1.f/(1.f + expf(-som[i/36][72 + i%36]));
    }
    __syncthreads();

    for (int i = t; i < 288; i += 256){
        int pix = i / 36, r = i % 36, gg = r / 9, k = r % 9;
        int hw = p0 + pix;
        int wo = hw % Wo, ho = hw / Wo;
        float py = (float)(ho*stride) + (float)(k/3 - 1) + som[pix][gg*18 + k*2];
        float px = (float)(wo*stride) + (float)(k%3 - 1) + som[pix][gg*18 + k*2 + 1];
        float m  = smk[pix][gg*9 + k];
        float fy = floorf(py), fx = floorf(px);
        float wy = py - fy, wx = px - fx;
        int iy = (int)fy, ix = (int)fx;
        #pragma unroll
        for (int d0 = 0; d0 < 2; ++d0){
            int yy = iy + d0;
            float wgy = d0 ? wy : (1.f - wy);
            #pragma unroll
            for (int d1 = 0; d1 < 2; ++d1){
                int xx = ix + d1;
                bool valid = (yy >= 0) & (yy < H) & (xx >= 0) & (xx < W);
                int yc = min(max(yy, 0), H-1);
                int xc = min(max(xx, 0), W-1);
                sw[pix][gg][k][d0*2+d1]   = valid ? wgy*(d1 ? wx : (1.f - wx))*m : 0.f;
                soff[pix][gg][k][d0*2+d1] = ((n*H + yc)*W + xc)*CH;
            }
        }
    }
    __syncthreads();

    int lane = t >> 6, q = t & 63, c0 = q*4, g = q >> 4;
    const float* xc = x + c0;
    #pragma unroll
    for (int pi = 0; pi < 2; ++pi){
        int pix = lane + pi*4;
        unsigned long long acc01 = 0ull, acc23 = 0ull;
        #pragma unroll
        for (int k = 0; k < 9; ++k){
            float4 wv = *(const float4*)&sw[pix][g][k][0];
            int4  ov = *(const int4*)&soff[pix][g][k][0];
            unsigned long long w0, w1, w2, w3;
            PACKF2(w0, wv.x, wv.x); PACKF2(w1, wv.y, wv.y);
            PACKF2(w2, wv.z, wv.z); PACKF2(w3, wv.w, wv.w);
            ulonglong2 v0 = *(const ulonglong2*)(xc + ov.x);
            ulonglong2 v1 = *(const ulonglong2*)(xc + ov.y);
            ulonglong2 v2 = *(const ulonglong2*)(xc + ov.z);
            ulonglong2 v3 = *(const ulonglong2*)(xc + ov.w);
            FMAF2(acc01, v0.x, w0, acc01); FMAF2(acc23, v0.y, w0, acc23);
            FMAF2(acc01, v1.x, w1, acc01); FMAF2(acc23, v1.y, w1, acc23);
            FMAF2(acc01, v2.x, w2, acc01); FMAF2(acc23, v2.y, w2, acc23);
            FMAF2(acc01, v3.x, w3, acc01); FMAF2(acc23, v3.y, w3, acc23);
        }
        float4 acc;
        UNPACKF2(acc.x, acc.y, acc01);
        UNPACKF2(acc.z, acc.w, acc23);
        *(float4*)(g_feat + ((size_t)OMPFX[b]*NB + (size_t)n*HW + p0 + pix)*CH + c0) = acc;
    }
}

// ---------------- batched stats (branch-offset subset launch) ----------------
__global__ void k_statsB(int boff){
    __shared__ float wy[80], wx[80];
    __shared__ float r1[256], r2[256];
    __shared__ float4 rw[256];
    int b = (blockIdx.x >> 4) + boff, g = blockIdx.x & 15, n = blockIdx.y;
    int Hs = BR_HO[b], Ws = Hs, HW = Hs*Ws;
    int uph = BR_UPH[b];
    float normw = uph ? 1.f/((float)uph*(float)uph) : 1.f/(float)HW;
    int t = threadIdx.x;
    if (t == 0){
        if (uph){
            for (int i = 0; i < Hs; ++i){ wy[i] = 0.f; wx[i] = 0.f; }
            float ry = (float)(Hs-1)/(float)(uph-1);
            for (int j = 0; j < uph; ++j){
                float c = j*ry; int i0 = (int)floorf(c); float f = c - (float)i0;
                wy[i0] += 1.f - f;
                if (i0 + 1 < Hs) wy[i0+1] += f;
            }
            for (int i = 0; i < Hs; ++i) wx[i] = wy[i];
        } else {
            for (int i = 0; i < Hs; ++i){ wy[i] = 1.f; wx[i] = 1.f; }
        }
    }
    __syncthreads();

    const float* fb = g_feat + ((size_t)OMPFX[b]*NB + (size_t)n*HW)*CH;
    int q  = t & 3;
    int c0 = g*16 + q*4;
    float4 s4 = make_float4(0,0,0,0), w4 = make_float4(0,0,0,0);
    float ss = 0.f;
    int hw0 = t >> 2;
    int h = hw0 / Ws, w = hw0 % Ws;
    for (int hw = hw0; hw < HW; hw += 64){
        float4 v = *(const float4*)(fb + (size_t)hw*CH + c0);
        s4.x += v.x; s4.y += v.y; s4.z += v.z; s4.w += v.w;
        ss += v.x*v.x + v.y*v.y + v.z*v.z + v.w*v.w;
        float ww = wy[h]*wx[w];
        w4.x += v.x*ww; w4.y += v.y*ww; w4.z += v.z*ww; w4.w += v.w*ww;
        w += 64; while (w >= Ws){ w -= Ws; ++h; }
    }
    r1[t] = s4.x + s4.y + s4.z + s4.w;
    r2[t] = ss;
    rw[t] = w4;
    __syncthreads();
    for (int o = 128; o >= 4; o >>= 1){
        if (t < o){
            r1[t] += r1[t+o]; r2[t] += r2[t+o];
            rw[t].x += rw[t+o].x; rw[t].y += rw[t+o].y;
            rw[t].z += rw[t+o].z; rw[t].w += rw[t+o].w;
        }
        __syncthreads();
    }
    if (t == 0){
        float s  = r1[0] + r1[1] + r1[2] + r1[3];
        float sq = r2[0] + r2[1] + r2[2] + r2[3];
        float cnt = (float)HW*16.f;
        float mu  = s/cnt;
        float var = sq/cnt - mu*mu;
        g_gmu [(b*NB+n)*16 + g] = mu;
        g_ginv[(b*NB+n)*16 + g] = rsqrtf(var + 1e-5f);
    }
    if (t < 4){
        float4 wv = rw[t];
        int c = (b*NB+n)*CH + g*16 + t*4;
        g_cmean[c]   = wv.x*normw; g_cmean[c+1] = wv.y*normw;
        g_cmean[c+2] = wv.z*normw; g_cmean[c+3] = wv.w*normw;
    }
}

// ---------------- attn scalars + pooled means ----------------
__device__ __constant__ int LVL_NBR[3] = {2,3,2};
__device__ __constant__ int LVL_BRS[3][3] = {{0,1,-1},{2,3,4},{5,6,-1}};

__global__ void k_attnB(const float* __restrict__ saw, const float* __restrict__ sab,
                        const float* __restrict__ gm, const float* __restrict__ bm,
                        const float* __restrict__ gh, const float* __restrict__ bh,
                        const float* __restrict__ gl, const float* __restrict__ bl){
    __shared__ float red[256];
    __shared__ float sa;
    int lvl = blockIdx.x, n = blockIdx.y, t = threadIdx.x;
    int g = t >> 4;
    int nbr = LVL_NBR[lvl];
    float invl = 1.f/(float)nbr;
    float y = 0.f;
    for (int i = 0; i < nbr; ++i){
        int b = LVL_BRS[lvl][i];
        int gs = BR_GNSEL[b];
        const float* gam = gs==0 ? gm : (gs==1 ? gh : gl);
        const float* bet = gs==0 ? bm : (gs==1 ? bh : bl);
        float m = (g_cmean[(b*NB+n)*CH + t] - g_gmu[(b*NB+n)*16 + g])
                  * g_ginv[(b*NB+n)*16 + g] * gam[t] + bet[t];
        red[t] = m*saw[t];
        __syncthreads();
        for (int o = 128; o > 0; o >>= 1){
            if (t < o) red[t] += red[t+o];
            __syncthreads();
        }
        if (t == 0){
            float a = red[0] + sab[0];
            a = fmaxf(a, 0.f);
            a = fminf(fmaxf((a + 3.f)/6.f, 0.f), 1.f);
            sa = a; g_a[b*NB + n] = a;
        }
        __syncthreads();
        y += sa*m*invl;
        __syncthreads();
    }
    g_y[(lvl*NB + n)*CH + t] = y;
}

// ---------------- fc (all levels) ----------------
__global__ void k_fcB(const float* __restrict__ w1, const float* __restrict__ b1,
                      const float* __restrict__ w2, const float* __restrict__ b2){
    __shared__ float h[4][64];
    int lvl = blockIdx.x;
    int t = threadIdx.x;
    int n = t >> 6, j = t & 63;
    float s = b1[j];
    const float* wr = w1 + j*CH;
    const float* yv = g_y + (lvl*NB + n)*CH;
    for (int c = 0; c < CH; ++c) s += yv[c]*wr[c];
    h[n][j] = fmaxf(s, 0.f);
    __syncthreads();
    for (int og = t; og < NB*1024; og += 256){
        int nn = og >> 10, o = og & 1023;
        float s2 = b2[o];
        const float* w2r = w2 + o*64;
        #pragma unroll 16
        for (int j2 = 0; j2 < 64; ++j2) s2 += h[nn][j2]*w2r[j2];
        float z = fminf(fmaxf(s2 + 3.f, 0.f), 6.f)*(1.f/6.f);
        int qd = o >> 8;
        float v;
        if      (qd == 0) v = (z - 0.5f)*2.f + 1.f;
        else if (qd == 2) v = (z - 0.5f)*2.f;
        else              v = z - 0.5f;
        g_z[(lvl*NB + nn)*1024 + o] = v;
    }
}

// ---------------- fused: GN+attn+upsample sum -> dyrelu -> NCHW out ----------
__device__ __forceinline__ void gn_acc(float4& o, float4 raw, int b, int n, int g,
                                       float4 g4, float4 b4){
    float mu = g_gmu[(b*NB+n)*16 + g], inv = g_ginv[(b*NB+n)*16 + g], a = g_a[b*NB + n];
    o.x += a*((raw.x - mu)*inv*g4.x + b4.x);
    o.y += a*((raw.y - mu)*inv*g4.y + b4.y);
    o.z += a*((raw.z - mu)*inv*g4.z + b4.z);
    o.w += a*((raw.w - mu)*inv*g4.w + b4.w);
}
__device__ __forceinline__ float4 feat_rd(int b, int n, int HW, int hw, int c0){
    return *(const float4*)(g_feat + ((size_t)OMPFX[b]*NB + (size_t)n*HW + hw)*CH + c0);
}
__device__ __forceinline__ float4 feat_up(int b, int n, int Hs, int Ho, int h, int w, int c0){
    float r = (float)(Hs-1)/(float)(Ho-1);
    float cy = h*r, cx = w*r;
    int y0 = (int)floorf(cy), x0 = (int)floorf(cx);
    int y1 = min(y0+1, Hs-1), x1 = min(x0+1, Hs-1);
    float wyf = cy - (float)y0, wxf = cx - (float)x0;
    const float* fb = g_feat + ((size_t)OMPFX[b]*NB + (size_t)n*Hs*Hs)*CH + c0;
    float4 v00 = *(const float4*)(fb + (size_t)(y0*Hs + x0)*CH);
    float4 v01 = *(const float4*)(fb + (size_t)(y0*Hs + x1)*CH);
    float4 v10 = *(const float4*)(fb + (size_t)(y1*Hs + x0)*CH);
    float4 v11 = *(const float4*)(fb + (size_t)(y1*Hs + x1)*CH);
    float a0 = (1.f-wyf)*(1.f-wxf), a1 = (1.f-wyf)*wxf, a2 = wyf*(1.f-wxf), a3 = wyf*wxf;
    float4 o;
    o.x = v00.x*a0 + v01.x*a1 + v10.x*a2 + v11.x*a3;
    o.y = v00.y*a0 + v01.y*a1 + v10.y*a2 + v11.y*a3;
    o.z = v00.z*a0 + v01.z*a1 + v10.z*a2 + v11.z*a3;
    o.w = v00.w*a0 + v01.w*a1 + v10.w*a2 + v11.w*a3;
    return o;
}

template<int LVL>
__global__ void k_outL(float* __restrict__ out,
                       const float* __restrict__ gm, const float* __restrict__ bm,
                       const float* __restrict__ gh, const float* __restrict__ bh,
                       const float* __restrict__ gl, const float* __restrict__ bl){
    constexpr int HoL = (LVL==0) ? 80 : (LVL==1 ? 40 : 20);
    constexpr int HWL = HoL*HoL;
    constexpr float INVL = (LVL==1) ? (1.f/3.f) : 0.5f;
    __shared__ float tile[32][257];
    int n   = blockIdx.y;
    int hw0 = blockIdx.x*32;
    int tx = threadIdx.x, ty = threadIdx.y;
    int tid = ty*32 + tx;

    #pragma unroll
    for (int k = 0; k < 8; ++k){
        int e = k*256 + tid;
        int hwl = e >> 6;
        int q   = e & 63;
        int hw  = hw0 + hwl;
        if (hw < HWL){
            int c0 = q*4, g = q >> 2;
            int w = hw % HoL, h = hw / HoL;
            float4 o = make_float4(0,0,0,0);
            float4 g4, b4;
            if (LVL == 0){
                g4 = *(const float4*)(gm + c0); b4 = *(const float4*)(bm + c0);
                gn_acc(o, feat_rd(0, n, 6400, hw, c0), 0, n, g, g4, b4);
                g4 = *(const float4*)(gh + c0); b4 = *(const float4*)(bh + c0);
                gn_acc(o, feat_up(1, n, 40, 80, h, w, c0), 1, n, g, g4, b4);
            } else if (LVL == 1){
                g4 = *(const float4*)(gm + c0); b4 = *(const float4*)(bm + c0);
                gn_acc(o, feat_rd(2, n, 1600, hw, c0), 2, n, g, g4, b4);
                g4 = *(const float4*)(gl + c0); b4 = *(const float4*)(bl + c0);
                gn_acc(o, feat_rd(3, n, 1600, hw, c0), 3, n, g, g4, b4);
                g4 = *(const float4*)(gh + c0); b4 = *(const float4*)(bh + c0);
                gn_acc(o, feat_up(4, n, 20, 40, h, w, c0), 4, n, g, g4, b4);
            } else {
                g4 = *(const float4*)(gm + c0); b4 = *(const float4*)(bm + c0);
                gn_acc(o, feat_rd(5, n, 400, hw, c0), 5, n, g, g4, b4);
                g4 = *(const float4*)(gl + c0); b4 = *(const float4*)(bl + c0);
                gn_acc(o, feat_rd(6, n, 400, hw, c0), 6, n, g, g4, b4);
            }
            tile[hwl][c0]   = o.x;
            tile[hwl][c0+1] = o.y;
            tile[hwl][c0+2] = o.z;
            tile[hwl][c0+3] = o.w;
        }
    }
    __syncthreads();

    int hw = hw0 + tx;
    if (hw < HWL){
        const float* zb = g_z + (LVL*NB + n)*1024;
        #pragma unroll
        for (int k = 0; k < 32; ++k){
            int c = ty + k*8;
            float f = tile[tx][c]*INVL;
            float a1 = zb[c], b1 = zb[256 + c];
            float a2 = zb[512 + c], b2 = zb[768 + c];
            out[((size_t)n*CH + c)*HWL + hw] = fmaxf(f*a1 + b1, f*a2 + b2);
        }
    }
}

// ---------------- host: branch-pipelined fork/join (graph-capturable) ----------
extern "C" void kernel_launch(void* const* d_in, const int* in_sizes, int n_in,
                              void* d_out, int out_size){
    const float* x0     = (const float*)d_in[0];
    const float* x1     = (const float*)d_in[1];
    const float* x2     = (const float*)d_in[2];
    const float* dw_w_h = (const float*)d_in[3];
    const float* dw_s_h = (const float*)d_in[4];
    const float* dw_b_h = (const float*)d_in[5];
    const float* dw_w_m = (const float*)d_in[6];
    const float* dw_s_m = (const float*)d_in[7];
    const float* dw_b_m = (const float*)d_in[8];
    const float* dw_w_l = (const float*)d_in[9];
    const float* dw_s_l = (const float*)d_in[10];
    const float* dw_b_l = (const float*)d_in[11];
    const float* off_w  = (const float*)d_in[12];
    const float* off_b  = (const float*)d_in[13];
    const float* gn_g_h = (const float*)d_in[14];
    const float* gn_b_h = (const float*)d_in[15];
    const float* gn_g_m = (const float*)d_in[16];
    const float* gn_b_m = (const float*)d_in[17];
    const float* gn_g_l = (const float*)d_in[18];
    const float* gn_b_l = (const float*)d_in[19];
    const float* sa_w   = (const float*)d_in[20];
    const float* sa_b   = (const float*)d_in[21];
    const float* fc1_w  = (const float*)d_in[22];
    const float* fc1_b  = (const float*)d_in[23];
    const float* fc2_w  = (const float*)d_in[24];
    const float* fc2_b  = (const float*)d_in[25];
    float* out = (float*)d_out;

    static cudaStream_t s1, s2, s3;
    static cudaEvent_t eFork, eWt, eDw0, eDw1, eO3, eO20, eStR, eFc, eL1, eL2;
    static bool inited = false;
    if (!inited){
        cudaStreamCreateWithFlags(&s1, cudaStreamNonBlocking);
        cudaStreamCreateWithFlags(&s2, cudaStreamNonBlocking);
        cudaStreamCreateWithFlags(&s3, cudaStreamNonBlocking);
        cudaEventCreateWithFlags(&eFork, cudaEventDisableTiming);
        cudaEventCreateWithFlags(&eWt,  cudaEventDisableTiming);
        cudaEventCreateWithFlags(&eDw0, cudaEventDisableTiming);
        cudaEventCreateWithFlags(&eDw1, cudaEventDisableTiming);
        cudaEventCreateWithFlags(&eO3,  cudaEventDisableTiming);
        cudaEventCreateWithFlags(&eO20, cudaEventDisableTiming);
        cudaEventCreateWithFlags(&eStR, cudaEventDisableTiming);
        cudaEventCreateWithFlags(&eFc,  cudaEventDisableTiming);
        cudaEventCreateWithFlags(&eL1,  cudaEventDisableTiming);
        cudaEventCreateWithFlags(&eL2,  cudaEventDisableTiming);
        inited = true;
    }
    cudaStream_t s0 = 0;

    // fork
    cudaEventRecord(eFork, s0);
    cudaStreamWaitEvent(s1, eFork, 0);
    cudaStreamWaitEvent(s2, eFork, 0);
    cudaStreamWaitEvent(s3, eFork, 0);

    // stage 1: per-source chains (dwS(src0) is global launch #3 for ncu)
    k_tr2<<<dim3(200, 8, NB), dim3(32,8), 0, s0>>>(x0, 0, 6400);
    k_tr2<<<dim3(50,  8, NB), dim3(32,8), 0, s1>>>(x1, 1, 1600);
    k_tr2<<<dim3(13,  8, NB), dim3(32,8), 0, s2>>>(x2, 2,  400);
    k_dwS<<<dim3(200, 1, NB), 256, 0, s0>>>(0, dw_w_m, dw_s_m, dw_b_m,
                                               dw_w_h, dw_s_h, dw_b_h,
                                               dw_w_l, dw_s_l, dw_b_l);
    cudaEventRecord(eDw0, s0);
    k_wt2<<<(3*192*112 + 255)/256, 256, 0, s3>>>(off_w);
    cudaEventRecord(eWt, s3);
    k_dwS<<<dim3(50, 1, NB), 256, 0, s1>>>(1, dw_w_m, dw_s_m, dw_b_m,
                                              dw_w_h, dw_s_h, dw_b_h,
                                              dw_w_l, dw_s_l, dw_b_l);
    cudaEventRecord(eDw1, s1);
    k_dwS<<<dim3(13, 1, NB), 256, 0, s2>>>(2, dw_w_m, dw_s_m, dw_b_m,
                                              dw_w_h, dw_s_h, dw_b_h,
                                              dw_w_l, dw_s_l, dw_b_l);

    // stage 2: om per class, each as early as its deps allow
    cudaStreamWaitEvent(s0, eWt, 0);
    cudaStreamWaitEvent(s1, eWt, 0);
    cudaStreamWaitEvent(s2, eWt, 0);
    cudaStreamWaitEvent(s3, eDw0, 0);
    const int SM80 = (64*52 + 192*28)*4;
    const int SM40 = (64*44 + 192*28)*4;
    const int SM20 = (64*24 + 192*28)*4;
    // critical path: om80 (b0) on s0
    k_om3<1,48,4,12,96><<<dim3(2*80*NB, 4, 1), 96, SM80, s0>>>(80, 80, 80, 80, off_b, 0, 0);
    // b1,b2 on s1; b3 (s2-stride from src0) + b6 on s3; b4,b5 on s2
    k_om3<1,40,4,10,80><<<dim3(1*40*NB, 4, 2), 80, SM40, s1>>>(40, 40, 40, 40, off_b, 1, 2);
    k_om3<2,20,2,10,80><<<dim3(2*40*NB, 4, 1), 80, SM40, s3>>>(80, 80, 40, 40, off_b, 3, 3);
    cudaStreamWaitEvent(s3, eDw1, 0);
    k_om3<2,20,2,10,80><<<dim3(1*20*NB, 4, 1), 80, SM40, s3>>>(40, 40, 20, 20, off_b, 6, 6);
    cudaEventRecord(eO3, s3);
    cudaStreamWaitEvent(s2, eDw1, 0);   // b4/b5 need src2 (own stream) only; b4 src2, b5 src2
    k_om3<1,20,4,5,64><<<dim3(1*20*NB, 4, 2), 64, SM20, s2>>>(20, 20, 20, 20, off_b, 4, 5);
    cudaEventRecord(eO20, s2);

    // stage 3a: sampler+stats for b0 on s0 (critical path)
    k_sampB <<<dim3(800, NB),  256, 0, s0>>>(0);
    k_statsB<<<dim3(16, NB),   256, 0, s0>>>(0);

    // stage 3b: sampler+stats for b1..b6 on s1 (overlaps om80/samp_b0)
    cudaStreamWaitEvent(s1, eO3, 0);
    cudaStreamWaitEvent(s1, eO20, 0);
    k_sampB <<<dim3(750, NB),  256, 0, s1>>>(800);
    k_statsB<<<dim3(6*16, NB), 256, 0, s1>>>(1);
    cudaEventRecord(eStR, s1);

    // stage 3c: attn + fc on s0 (needs all stats)
    cudaStreamWaitEvent(s0, eStR, 0);
    k_attnB <<<dim3(3, NB), 256, 0, s0>>>(sa_w, sa_b, gn_g_m, gn_b_m, gn_g_h, gn_b_h, gn_g_l, gn_b_l);
    k_fcB   <<<3,           256, 0, s0>>>(fc1_w, fc1_b, fc2_w, fc2_b);
    cudaEventRecord(eFc, s0);
    cudaStreamWaitEvent(s1, eFc, 0);
    cudaStreamWaitEvent(s2, eFc, 0);

    // stage 4: fused outputs concurrent
    k_outL<0><<<dim3(200, NB), dim3(32,8), 0, s0>>>(out,
        gn_g_m, gn_b_m, gn_g_h, gn_b_h, gn_g_l, gn_b_l);
    k_outL<1><<<dim3(50, NB),  dim3(32,8), 0, s1>>>(out + (size_t)NB*CH*6400,
        gn_g_m, gn_b_m, gn_g_h, gn_b_h, gn_g_l, gn_b_l);
    k_outL<2><<<dim3(13, NB),  dim3(32,8), 0, s2>>>(out + (size_t)NB*CH*8000,
        gn_g_m, gn_b_m, gn_g_h, gn_b_h, gn_g_l, gn_b_l);
    cudaEventRecord(eL1, s1);
    cudaEventRecord(eL2, s2);
    cudaStreamWaitEvent(s0, eL1, 0);
    cudaStreamWaitEvent(s0, eL2, 0);
}

// round 11
// speedup vs baseline: 1.2562x; 1.0551x over previous
#include <cuda_runtime.h>
#include <math.h>

#define NB   4
#define CH   256
#define OMC  108

// ---- packed f32x2 ops ----
#define PACKF2(out, lo, hi) \
    asm("mov.b64 %0, {%1, %2};" : "=l"(out) : "f"(lo), "f"(hi))
#define UNPACKF2(lo, hi, in) \
    asm("mov.b64 {%0, %1}, %2;" : "=f"(lo), "=f"(hi) : "l"(in))
#define FMAF2(d, a, b, c) \
    asm("fma.rn.f32x2 %0, %1, %2, %3;" : "=l"(d) : "l"(a), "l"(b), "l"(c))

// ---- branch tables (7 branches) ----
__device__ __constant__ int BR_SRC[7]    = {0,1,1,0,2,2,1};
__device__ __constant__ int BR_HS[7]     = {80,40,40,80,20,20,40};
__device__ __constant__ int BR_STRIDE[7] = {1,1,1,2,1,1,2};
__device__ __constant__ int BR_HO[7]     = {80,40,40,40,20,20,20};
__device__ __constant__ int BR_SOFT[7]   = {0,1,0,1,1,0,1};
__device__ __constant__ int BR_UPH[7]    = {0,80,0,0,40,0,0};
__device__ __constant__ int BR_GNSEL[7]  = {0,1,0,2,1,0,2};
__device__ __constant__ int DWPFX[7]     = {0,6400,8000,9600,16000,16400,16800};
__device__ __constant__ int OMPFX[7]     = {0,6400,8000,9600,11200,11600,12000};
__device__ __constant__ int SAMP_PFX8[7] = {0,800,1000,1200,1400,1450,1500};

__device__ __constant__ int SRC_NSETS[3]  = {2,3,2};
__device__ __constant__ int SRC_WSEL[3][3]= {{0,2,0},{1,0,2},{1,0,0}};
__device__ __constant__ int SRC_DST[3][3] = {{0,9600,0},{6400,8000,16800},{16000,16400,0}};

// ---------------- scratch ----------------
__device__ float g_x0[NB*80*80*CH];
__device__ float g_x1[NB*40*40*CH];
__device__ float g_x2[NB*20*20*CH];
__device__ float g_dwb[18400*NB*CH];
__device__ float g_om [12400*NB*OMC];
__device__ float g_feat[12400*NB*CH];
__device__ float g_wT2[3*192*112];
__device__ float g_a[7*NB];
__device__ float g_y[3*NB*CH];
__device__ float g_z[3*NB*1024];
__device__ float g_cmean[7*NB*CH];
__device__ float g_gmu[7*NB*16];
__device__ float g_ginv[7*NB*16];

__device__ __forceinline__ const float* pick_x(int s){
    return s==0 ? g_x0 : (s==1 ? g_x1 : g_x2);
}
__device__ __forceinline__ float* pick_xm(int s){
    return s==0 ? g_x0 : (s==1 ? g_x1 : g_x2);
}

// ---------------- NCHW -> NHWC tiled transpose ----------------
__global__ void k_tr2(const float* __restrict__ in, int sel, int HW){
    __shared__ float tile[32][33];
    float* out = pick_xm(sel);
    int n  = blockIdx.z;
    int hw0 = blockIdx.x*32;
    int c0  = blockIdx.y*32;
    int tx = threadIdx.x, ty = threadIdx.y;
    #pragma unroll
    for (int q = 0; q < 4; ++q){
        int c = c0 + ty + q*8;
        int hw = hw0 + tx;
        float v = (hw < HW) ? in[((size_t)n*CH + c)*HW + hw] : 0.f;
        tile[ty + q*8][tx] = v;
    }
    __syncthreads();
    #pragma unroll
    for (int q = 0; q < 4; ++q){
        int hw = hw0 + ty + q*8;
        int c  = c0 + tx;
        if (hw < HW) out[((size_t)n*HW + hw)*CH + c] = tile[tx][ty + q*8];
    }
}

// weight transform: [dy][ic*3+dx][slot(4g x 28)]
__global__ void k_wt2(const float* __restrict__ ow){
    int i = blockIdx.x*blockDim.x + threadIdx.x;
    if (i >= 3*192*112) return;
    int slot = i % 112;
    int r    = (i / 112) % 192;
    int dy   = i / (112*192);
    int ic = r/3, dx = r%3;
    int g = slot/28, jj = slot%28;
    float v = 0.f;
    if (jj < 27) v = ow[(g*27+jj)*576 + ic*9 + dy*3 + dx];
    g_wT2[i] = v;
}

// ---------------- shared-source depthwise conv (single source per launch) ----
__global__ void k_dwS(int src,
                      const float* __restrict__ wm, const float* __restrict__ sm_, const float* __restrict__ bm_,
                      const float* __restrict__ wh, const float* __restrict__ sh_, const float* __restrict__ bh_,
                      const float* __restrict__ wl, const float* __restrict__ sl_, const float* __restrict__ bl_){
    __shared__ unsigned long long wsm[3][64][9][2];
    __shared__ float4 ssm[3][64], bsm[3][64];
    int n = blockIdx.z;
    int H = (src==0) ? 80 : (src==1 ? 40 : 20);
    int W = H, HW = H*W;
    int nsets = SRC_NSETS[src];
    int t = threadIdx.x;

    for (int s = 0; s < nsets; ++s){
        int sel = SRC_WSEL[src][s];
        const float* wgt = sel==0 ? wm : (sel==1 ? wh : wl);
        const float* sc  = sel==0 ? sm_ : (sel==1 ? sh_ : sl_);
        const float* bi  = sel==0 ? bm_ : (sel==1 ? bh_ : bl_);
        for (int i = t; i < 64*9; i += 256){
            int q = i/9, tp = i%9;
            float a0 = wgt[(q*4+0)*9 + tp], a1 = wgt[(q*4+1)*9 + tp];
            float a2 = wgt[(q*4+2)*9 + tp], a3 = wgt[(q*4+3)*9 + tp];
            PACKF2(wsm[s][q][tp][0], a0, a1);
            PACKF2(wsm[s][q][tp][1], a2, a3);
        }
        for (int i = t; i < 64; i += 256){
            ssm[s][i] = *(const float4*)(sc + i*4);
            bsm[s][i] = *(const float4*)(bi + i*4);
        }
    }
    __syncthreads();

    const float* x = pick_x(src);
    int q  = t & 63;
    int c0 = q*4;
    int lane = t >> 6;
    for (int hw = blockIdx.x*4 + lane; hw < HW; hw += gridDim.x*4){
        int w = hw % W, h = hw / W;
        ulonglong2 tap[9];
        #pragma unroll
        for (int dy = 0; dy < 3; ++dy){
            int yy = h + dy - 1;
            #pragma unroll
            for (int dx = 0; dx < 3; ++dx){
                int xx = w + dx - 1;
                int tp = dy*3 + dx;
                if (yy >= 0 && yy < H && xx >= 0 && xx < W)
                    tap[tp] = *(const ulonglong2*)(x + ((size_t)(n*H+yy)*W + xx)*CH + c0);
                else { tap[tp].x = 0ull; tap[tp].y = 0ull; }
            }
        }
        #pragma unroll 3
        for (int s = 0; s < 3; ++s){
            if (s >= nsets) break;
            unsigned long long a01 = 0ull, a23 = 0ull;
            #pragma unroll
            for (int tp = 0; tp < 9; ++tp){
                FMAF2(a01, tap[tp].x, wsm[s][q][tp][0], a01);
                FMAF2(a23, tap[tp].y, wsm[s][q][tp][1], a23);
            }
            float ax, ay, az, aw;
            UNPACKF2(ax, ay, a01);
            UNPACKF2(az, aw, a23);
            float4 s4 = ssm[s][q], b4 = bsm[s][q];
            float4 o;
            float t0 = ax*s4.x + b4.x; o.x = t0/(1.f+expf(-t0));
            float t1 = ay*s4.y + b4.y; o.y = t1/(1.f+expf(-t1));
            float t2 = az*s4.z + b4.z; o.z = t2/(1.f+expf(-t2));
            float t3 = aw*s4.w + b4.w; o.w = t3/(1.f+expf(-t3));
            float* dst = g_dwb + (size_t)SRC_DST[src][s]*NB*CH;
            *(float4*)(dst + ((size_t)n*HW + hw)*CH + c0) = o;
        }
    }
}

// ---------------- grouped conv 256->108, per-group blocks, FFMA2 ----
template<int STRIDE, int PXO, int TPX, int PXQ, int THREADS>
__global__ void __launch_bounds__(THREADS)
k_om3(int H, int W, int Ho, int Wo, const float* __restrict__ ob, int bA, int bB){
    constexpr int PW  = (PXO-1)*STRIDE + 3;
    constexpr int PWP = (PW + 3) & ~3;
    constexpr int WIN = 3 + (TPX-1)*STRIDE;
    static_assert((TPX*STRIDE) % 4 == 0, "window alignment");
    static_assert(WIN <= 8, "window fits two float4");
    extern __shared__ float sh[];
    float* patch = sh;
    float* wsl   = sh + 64*PWP;

    int br   = blockIdx.z == 0 ? bA : bB;
    const float* src = g_dwb + (size_t)DWPFX[br]*NB*CH;
    float* dst       = g_om  + (size_t)OMPFX[br]*NB*OMC;

    int nt   = (Wo + PXO - 1)/PXO;
    int g    = blockIdx.y;
    int b    = blockIdx.x;
    int tile = b % nt;
    int ho   = (b/nt) % Ho;
    int n    = b/(nt*Ho);
    int wo0  = tile*PXO;
    int hsrc = ho*STRIDE;
    int wsrc0= wo0*STRIDE;
    int cb   = g*64;

    int t   = threadIdx.x;
    int pxq = t % PXQ;
    int li  = t / PXQ;
    bool act = li < 7;
    int xb  = pxq*TPX*STRIDE;

    unsigned long long a01[TPX], a23[TPX];
    #pragma unroll
    for (int p = 0; p < TPX; ++p){ a01[p] = 0ull; a23[p] = 0ull; }

    const float* wsrc_base = g_wT2 + g*28;
    for (int dy = 0; dy < 3; ++dy){
        __syncthreads();
        int gy = hsrc + dy - 1;
        for (int i = t; i < PW*64; i += THREADS){
            int c = i & 63, xx = i >> 6;
            int gx = wsrc0 + xx - 1;
            float v = 0.f;
            if (gy >= 0 && gy < H && gx >= 0 && gx < W)
                v = src[((size_t)(n*H+gy)*W + gx)*CH + cb + c];
            patch[c*PWP + xx] = v;
        }
        {
            const float* ws = wsrc_base + dy*192*112;
            for (int i = t; i < 192*7; i += THREADS){
                int row = i/7, col = (i%7)*4;
                *(float4*)(wsl + row*28 + col) = *(const float4*)(ws + row*112 + col);
            }
        }
        __syncthreads();
        if (act){
            #pragma unroll 4
            for (int ic = 0; ic < 64; ++ic){
                const float* pr = patch + ic*PWP + xb;
                float f[8];
                *(float4*)(f)   = *(const float4*)(pr);
                *(float4*)(f+4) = *(const float4*)(pr+4);
                unsigned long long sv[WIN];
                #pragma unroll
                for (int k2 = 0; k2 < WIN; ++k2) PACKF2(sv[k2], f[k2], f[k2]);
                const float* wb = wsl + (ic*3)*28 + li*4;
                #pragma unroll
                for (int dx = 0; dx < 3; ++dx){
                    ulonglong2 wv = *(const ulonglong2*)(wb + dx*28);
                    #pragma unroll
                    for (int p = 0; p < TPX; ++p){
                        FMAF2(a01[p], sv[dx + p*STRIDE], wv.x, a01[p]);
                        FMAF2(a23[p], sv[dx + p*STRIDE], wv.y, a23[p]);
                    }
                }
            }
        }
    }
    if (act){
        float bj[4];
        #pragma unroll
        for (int j = 0; j < 4; ++j){
            int jj = li*4 + j;
            bj[j] = (jj < 27) ? ob[g*27 + jj] : 0.f;
        }
        #pragma unroll
        for (int p = 0; p < TPX; ++p){
            int wo = wo0 + pxq*TPX + p;
            if (wo < Wo){
                size_t base = ((size_t)(n*Ho+ho)*Wo + wo)*OMC + g*27 + li*4;
                float av[4];
                UNPACKF2(av[0], av[1], a01[p]);
                UNPACKF2(av[2], av[3], a23[p]);
                #pragma unroll
                for (int j = 0; j < 4; ++j)
                    if (li*4 + j < 27) dst[base + j] = av[j] + bj[j];
            }
        }
    }
}

// ---------------- batched DCNv3 sampler (block-offset subset launch) ----------
__global__ void k_sampB(int bx0){
    __shared__ float som[8][OMC];
    __shared__ float smk[8][36];
    __shared__ float sw[8][4][9][4];
    __shared__ int   soff[8][4][9][4];
    int bx = blockIdx.x + bx0;
    int b = 0;
    #pragma unroll
    for (int i = 1; i < 7; ++i) if (bx >= SAMP_PFX8[i]) b = i;
    int n = blockIdx.y;
    int p0 = (bx - SAMP_PFX8[b])*8;
    int Ho = BR_HO[b], Wo = Ho, HW = Ho*Wo;
    int H  = BR_HS[b], W = H;
    int stride = BR_STRIDE[b];
    int use_softmax = BR_SOFT[b];
    const float* x = pick_x(BR_SRC[b]);
    const float* omp = g_om + ((size_t)OMPFX[b]*NB + (size_t)n*HW)*OMC;
    int t = threadIdx.x;

    for (int i = t; i < 8*OMC; i += 256)
        som[i/OMC][i%OMC] = omp[(size_t)(p0 + i/OMC)*OMC + i%OMC];
    __syncthreads();

    if (use_softmax){
        if (t < 32){
            int pp = t >> 2, gg = t & 3;
            float mx = -1e30f;
            #pragma unroll
            for (int k = 0; k < 9; ++k) mx = fmaxf(mx, som[pp][72 + gg*9 + k]);
            float e[9], s = 0.f;
            #pragma unroll
            for (int k = 0; k < 9; ++k){ e[k] = expf(som[pp][72 + gg*9 + k] - mx); s += e[k]; }
            float inv = 1.f/s;
            #pragma unroll
            for (int k = 0; k < 9; ++k) smk[pp][gg*9 + k] = e[k]*inv;
        }
    } else {
        for (int i = t; i < 8*36; i += 256)
            smk[i/36][i%36] = 1.f/(1.f + expf(-som[i/36][72 + i%36]));
    }
    __syncthreads();

    for (int i = t; i < 288; i += 256){
        int pix = i / 36, r = i % 36, gg = r / 9, k = r % 9;
        int hw = p0 + pix;
        int wo = hw % Wo, ho = hw / Wo;
        float py = (float)(ho*stride) + (float)(k/3 - 1) + som[pix][gg*18 + k*2];
        float px = (float)(wo*stride) + (float)(k%3 - 1) + som[pix][gg*18 + k*2 + 1];
        float m  = smk[pix][gg*9 + k];
        float fy = floorf(py), fx = floorf(px);
        float wy = py - fy, wx = px - fx;
        int iy = (int)fy, ix = (int)fx;
        #pragma unroll
        for (int d0 = 0; d0 < 2; ++d0){
            int yy = iy + d0;
            float wgy = d0 ? wy : (1.f - wy);
            #pragma unroll
            for (int d1 = 0; d1 < 2; ++d1){
                int xx = ix + d1;
                bool valid = (yy >= 0) & (yy < H) & (xx >= 0) & (xx < W);
                int yc = min(max(yy, 0), H-1);
                int xc = min(max(xx, 0), W-1);
                sw[pix][gg][k][d0*2+d1]   = valid ? wgy*(d1 ? wx : (1.f - wx))*m : 0.f;
                soff[pix][gg][k][d0*2+d1] = ((n*H + yc)*W + xc)*CH;
            }
        }
    }
    __syncthreads();

    int lane = t >> 6, q = t & 63, c0 = q*4, g = q >> 4;
    const float* xc = x + c0;
    #pragma unroll
    for (int pi = 0; pi < 2; ++pi){
        int pix = lane + pi*4;
        unsigned long long acc01 = 0ull, acc23 = 0ull;
        #pragma unroll
        for (int k = 0; k < 9; ++k){
            float4 wv = *(const float4*)&sw[pix][g][k][0];
            int4  ov = *(const int4*)&soff[pix][g][k][0];
            unsigned long long w0, w1, w2, w3;
            PACKF2(w0, wv.x, wv.x); PACKF2(w1, wv.y, wv.y);
            PACKF2(w2, wv.z, wv.z); PACKF2(w3, wv.w, wv.w);
            ulonglong2 v0 = *(const ulonglong2*)(xc + ov.x);
            ulonglong2 v1 = *(const ulonglong2*)(xc + ov.y);
            ulonglong2 v2 = *(const ulonglong2*)(xc + ov.z);
            ulonglong2 v3 = *(const ulonglong2*)(xc + ov.w);
            FMAF2(acc01, v0.x, w0, acc01); FMAF2(acc23, v0.y, w0, acc23);
            FMAF2(acc01, v1.x, w1, acc01); FMAF2(acc23, v1.y, w1, acc23);
            FMAF2(acc01, v2.x, w2, acc01); FMAF2(acc23, v2.y, w2, acc23);
            FMAF2(acc01, v3.x, w3, acc01); FMAF2(acc23, v3.y, w3, acc23);
        }
        float4 acc;
        UNPACKF2(acc.x, acc.y, acc01);
        UNPACKF2(acc.z, acc.w, acc23);
        *(float4*)(g_feat + ((size_t)OMPFX[b]*NB + (size_t)n*HW + p0 + pix)*CH + c0) = acc;
    }
}

// ---------------- batched stats (branch-offset subset launch) ----------------
__global__ void k_statsB(int boff){
    __shared__ float wy[80], wx[80];
    __shared__ float r1[256], r2[256];
    __shared__ float4 rw[256];
    int b = (blockIdx.x >> 4) + boff, g = blockIdx.x & 15, n = blockIdx.y;
    int Hs = BR_HO[b], Ws = Hs, HW = Hs*Ws;
    int uph = BR_UPH[b];
    float normw = uph ? 1.f/((float)uph*(float)uph) : 1.f/(float)HW;
    int t = threadIdx.x;
    if (t == 0){
        if (uph){
            for (int i = 0; i < Hs; ++i){ wy[i] = 0.f; wx[i] = 0.f; }
            float ry = (float)(Hs-1)/(float)(uph-1);
            for (int j = 0; j < uph; ++j){
                float c = j*ry; int i0 = (int)floorf(c); float f = c - (float)i0;
                wy[i0] += 1.f - f;
                if (i0 + 1 < Hs) wy[i0+1] += f;
            }
            for (int i = 0; i < Hs; ++i) wx[i] = wy[i];
        } else {
            for (int i = 0; i < Hs; ++i){ wy[i] = 1.f; wx[i] = 1.f; }
        }
    }
    __syncthreads();

    const float* fb = g_feat + ((size_t)OMPFX[b]*NB + (size_t)n*HW)*CH;
    int q  = t & 3;
    int c0 = g*16 + q*4;
    float4 s4 = make_float4(0,0,0,0), w4 = make_float4(0,0,0,0);
    float ss = 0.f;
    int hw0 = t >> 2;
    int h = hw0 / Ws, w = hw0 % Ws;
    for (int hw = hw0; hw < HW; hw += 64){
        float4 v = *(const float4*)(fb + (size_t)hw*CH + c0);
        s4.x += v.x; s4.y += v.y; s4.z += v.z; s4.w += v.w;
        ss += v.x*v.x + v.y*v.y + v.z*v.z + v.w*v.w;
        float ww = wy[h]*wx[w];
        w4.x += v.x*ww; w4.y += v.y*ww; w4.z += v.z*ww; w4.w += v.w*ww;
        w += 64; while (w >= Ws){ w -= Ws; ++h; }
    }
    r1[t] = s4.x + s4.y + s4.z + s4.w;
    r2[t] = ss;
    rw[t] = w4;
    __syncthreads();
    for (int o = 128; o >= 4; o >>= 1){
        if (t < o){
            r1[t] += r1[t+o]; r2[t] += r2[t+o];
            rw[t].x += rw[t+o].x; rw[t].y += rw[t+o].y;
            rw[t].z += rw[t+o].z; rw[t].w += rw[t+o].w;
        }
        __syncthreads();
    }
    if (t == 0){
        float s  = r1[0] + r1[1] + r1[2] + r1[3];
        float sq = r2[0] + r2[1] + r2[2] + r2[3];
        float cnt = (float)HW*16.f;
        float mu  = s/cnt;
        float var = sq/cnt - mu*mu;
        g_gmu [(b*NB+n)*16 + g] = mu;
        g_ginv[(b*NB+n)*16 + g] = rsqrtf(var + 1e-5f);
    }
    if (t < 4){
        float4 wv = rw[t];
        int c = (b*NB+n)*CH + g*16 + t*4;
        g_cmean[c]   = wv.x*normw; g_cmean[c+1] = wv.y*normw;
        g_cmean[c+2] = wv.z*normw; g_cmean[c+3] = wv.w*normw;
    }
}

// ---------------- attn scalars + pooled means ----------------
__device__ __constant__ int LVL_NBR[3] = {2,3,2};
__device__ __constant__ int LVL_BRS[3][3] = {{0,1,-1},{2,3,4},{5,6,-1}};

__global__ void k_attnB(const float* __restrict__ saw, const float* __restrict__ sab,
                        const float* __restrict__ gm, const float* __restrict__ bm,
                        const float* __restrict__ gh, const float* __restrict__ bh,
                        const float* __restrict__ gl, const float* __restrict__ bl){
    __shared__ float red[256];
    __shared__ float sa;
    int lvl = blockIdx.x, n = blockIdx.y, t = threadIdx.x;
    int g = t >> 4;
    int nbr = LVL_NBR[lvl];
    float invl = 1.f/(float)nbr;
    float y = 0.f;
    for (int i = 0; i < nbr; ++i){
        int b = LVL_BRS[lvl][i];
        int gs = BR_GNSEL[b];
        const float* gam = gs==0 ? gm : (gs==1 ? gh : gl);
        const float* bet = gs==0 ? bm : (gs==1 ? bh : bl);
        float m = (g_cmean[(b*NB+n)*CH + t] - g_gmu[(b*NB+n)*16 + g])
                  * g_ginv[(b*NB+n)*16 + g] * gam[t] + bet[t];
        red[t] = m*saw[t];
        __syncthreads();
        for (int o = 128; o > 0; o >>= 1){
            if (t < o) red[t] += red[t+o];
            __syncthreads();
        }
        if (t == 0){
            float a = red[0] + sab[0];
            a = fmaxf(a, 0.f);
            a = fminf(fmaxf((a + 3.f)/6.f, 0.f), 1.f);
            sa = a; g_a[b*NB + n] = a;
        }
        __syncthreads();
        y += sa*m*invl;
        __syncthreads();
    }
    g_y[(lvl*NB + n)*CH + t] = y;
}

// ---------------- fc (all levels) ----------------
__global__ void k_fcB(const float* __restrict__ w1, const float* __restrict__ b1,
                      const float* __restrict__ w2, const float* __restrict__ b2){
    __shared__ float h[4][64];
    int lvl = blockIdx.x;
    int t = threadIdx.x;
    int n = t >> 6, j = t & 63;
    float s = b1[j];
    const float* wr = w1 + j*CH;
    const float* yv = g_y + (lvl*NB + n)*CH;
    for (int c = 0; c < CH; ++c) s += yv[c]*wr[c];
    h[n][j] = fmaxf(s, 0.f);
    __syncthreads();
    for (int og = t; og < NB*1024; og += 256){
        int nn = og >> 10, o = og & 1023;
        float s2 = b2[o];
        const float* w2r = w2 + o*64;
        #pragma unroll 16
        for (int j2 = 0; j2 < 64; ++j2) s2 += h[nn][j2]*w2r[j2];
        float z = fminf(fmaxf(s2 + 3.f, 0.f), 6.f)*(1.f/6.f);
        int qd = o >> 8;
        float v;
        if      (qd == 0) v = (z - 0.5f)*2.f + 1.f;
        else if (qd == 2) v = (z - 0.5f)*2.f;
        else              v = z - 0.5f;
        g_z[(lvl*NB + nn)*1024 + o] = v;
    }
}

// ---------------- fused: GN+attn+upsample sum -> dyrelu -> NCHW out ----------
__device__ __forceinline__ void gn_acc(float4& o, float4 raw, int b, int n, int g,
                                       float4 g4, float4 b4){
    float mu = g_gmu[(b*NB+n)*16 + g], inv = g_ginv[(b*NB+n)*16 + g], a = g_a[b*NB + n];
    o.x += a*((raw.x - mu)*inv*g4.x + b4.x);
    o.y += a*((raw.y - mu)*inv*g4.y + b4.y);
    o.z += a*((raw.z - mu)*inv*g4.z + b4.z);
    o.w += a*((raw.w - mu)*inv*g4.w + b4.w);
}
__device__ __forceinline__ float4 feat_rd(int b, int n, int HW, int hw, int c0){
    return *(const float4*)(g_feat + ((size_t)OMPFX[b]*NB + (size_t)n*HW + hw)*CH + c0);
}
__device__ __forceinline__ float4 feat_up(int b, int n, int Hs, int Ho, int h, int w, int c0){
    float r = (float)(Hs-1)/(float)(Ho-1);
    float cy = h*r, cx = w*r;
    int y0 = (int)floorf(cy), x0 = (int)floorf(cx);
    int y1 = min(y0+1, Hs-1), x1 = min(x0+1, Hs-1);
    float wyf = cy - (float)y0, wxf = cx - (float)x0;
    const float* fb = g_feat + ((size_t)OMPFX[b]*NB + (size_t)n*Hs*Hs)*CH + c0;
    float4 v00 = *(const float4*)(fb + (size_t)(y0*Hs + x0)*CH);
    float4 v01 = *(const float4*)(fb + (size_t)(y0*Hs + x1)*CH);
    float4 v10 = *(const float4*)(fb + (size_t)(y1*Hs + x0)*CH);
    float4 v11 = *(const float4*)(fb + (size_t)(y1*Hs + x1)*CH);
    float a0 = (1.f-wyf)*(1.f-wxf), a1 = (1.f-wyf)*wxf, a2 = wyf*(1.f-wxf), a3 = wyf*wxf;
    float4 o;
    o.x = v00.x*a0 + v01.x*a1 + v10.x*a2 + v11.x*a3;
    o.y = v00.y*a0 + v01.y*a1 + v10.y*a2 + v11.y*a3;
    o.z = v00.z*a0 + v01.z*a1 + v10.z*a2 + v11.z*a3;
    o.w = v00.w*a0 + v01.w*a1 + v10.w*a2 + v11.w*a3;
    return o;
}

template<int LVL>
__global__ void k_outL(float* __restrict__ out,
                       const float* __restrict__ gm, const float* __restrict__ bm,
                       const float* __restrict__ gh, const float* __restrict__ bh,
                       const float* __restrict__ gl, const float* __restrict__ bl){
    constexpr int HoL = (LVL==0) ? 80 : (LVL==1 ? 40 : 20);
    constexpr int HWL = HoL*HoL;
    constexpr float INVL = (LVL==1) ? (1.f/3.f) : 0.5f;
    __shared__ float tile[32][257];
    int n   = blockIdx.y;
    int hw0 = blockIdx.x*32;
    int tx = threadIdx.x, ty = threadIdx.y;
    int tid = ty*32 + tx;

    #pragma unroll
    for (int k = 0; k < 8; ++k){
        int e = k*256 + tid;
        int hwl = e >> 6;
        int q   = e & 63;
        int hw  = hw0 + hwl;
        if (hw < HWL){
            int c0 = q*4, g = q >> 2;
            int w = hw % HoL, h = hw / HoL;
            float4 o = make_float4(0,0,0,0);
            float4 g4, b4;
            if (LVL == 0){
                g4 = *(const float4*)(gm + c0); b4 = *(const float4*)(bm + c0);
                gn_acc(o, feat_rd(0, n, 6400, hw, c0), 0, n, g, g4, b4);
                g4 = *(const float4*)(gh + c0); b4 = *(const float4*)(bh + c0);
                gn_acc(o, feat_up(1, n, 40, 80, h, w, c0), 1, n, g, g4, b4);
            } else if (LVL == 1){
                g4 = *(const float4*)(gm + c0); b4 = *(const float4*)(bm + c0);
                gn_acc(o, feat_rd(2, n, 1600, hw, c0), 2, n, g, g4, b4);
                g4 = *(const float4*)(gl + c0); b4 = *(const float4*)(bl + c0);
                gn_acc(o, feat_rd(3, n, 1600, hw, c0), 3, n, g, g4, b4);
                g4 = *(const float4*)(gh + c0); b4 = *(const float4*)(bh + c0);
                gn_acc(o, feat_up(4, n, 20, 40, h, w, c0), 4, n, g, g4, b4);
            } else {
                g4 = *(const float4*)(gm + c0); b4 = *(const float4*)(bm + c0);
                gn_acc(o, feat_rd(5, n, 400, hw, c0), 5, n, g, g4, b4);
                g4 = *(const float4*)(gl + c0); b4 = *(const float4*)(bl + c0);
                gn_acc(o, feat_rd(6, n, 400, hw, c0), 6, n, g, g4, b4);
            }
            tile[hwl][c0]   = o.x;
            tile[hwl][c0+1] = o.y;
            tile[hwl][c0+2] = o.z;
            tile[hwl][c0+3] = o.w;
        }
    }
    __syncthreads();

    int hw = hw0 + tx;
    if (hw < HWL){
        const float* zb = g_z + (LVL*NB + n)*1024;
        #pragma unroll
        for (int k = 0; k < 32; ++k){
            int c = ty + k*8;
            float f = tile[tx][c]*INVL;
            float a1 = zb[c], b1 = zb[256 + c];
            float a2 = zb[512 + c], b2 = zb[768 + c];
            out[((size_t)n*CH + c)*HWL + hw] = fmaxf(f*a1 + b1, f*a2 + b2);
        }
    }
}

// ---------------- host: branch-pipelined fork/join (graph-capturable) ----------
extern "C" void kernel_launch(void* const* d_in, const int* in_sizes, int n_in,
                              void* d_out, int out_size){
    const float* x0     = (const float*)d_in[0];
    const float* x1     = (const float*)d_in[1];
    const float* x2     = (const float*)d_in[2];
    const float* dw_w_h = (const float*)d_in[3];
    const float* dw_s_h = (const float*)d_in[4];
    const float* dw_b_h = (const float*)d_in[5];
    const float* dw_w_m = (const float*)d_in[6];
    const float* dw_s_m = (const float*)d_in[7];
    const float* dw_b_m = (const float*)d_in[8];
    const float* dw_w_l = (const float*)d_in[9];
    const float* dw_s_l = (const float*)d_in[10];
    const float* dw_b_l = (const float*)d_in[11];
    const float* off_w  = (const float*)d_in[12];
    const float* off_b  = (const float*)d_in[13];
    const float* gn_g_h = (const float*)d_in[14];
    const float* gn_b_h = (const float*)d_in[15];
    const float* gn_g_m = (const float*)d_in[16];
    const float* gn_b_m = (const float*)d_in[17];
    const float* gn_g_l = (const float*)d_in[18];
    const float* gn_b_l = (const float*)d_in[19];
    const float* sa_w   = (const float*)d_in[20];
    const float* sa_b   = (const float*)d_in[21];
    const float* fc1_w  = (const float*)d_in[22];
    const float* fc1_b  = (const float*)d_in[23];
    const float* fc2_w  = (const float*)d_in[24];
    const float* fc2_b  = (const float*)d_in[25];
    float* out = (float*)d_out;

    static cudaStream_t s1, s2, s3;
    static cudaEvent_t eFork, eWt, eDw0, eDw1, eO3, eO20, eStR, eFc, eL1, eL2;
    static bool inited = false;
    if (!inited){
        cudaStreamCreateWithFlags(&s1, cudaStreamNonBlocking);
        cudaStreamCreateWithFlags(&s2, cudaStreamNonBlocking);
        cudaStreamCreateWithFlags(&s3, cudaStreamNonBlocking);
        cudaEventCreateWithFlags(&eFork, cudaEventDisableTiming);
        cudaEventCreateWithFlags(&eWt,  cudaEventDisableTiming);
        cudaEventCreateWithFlags(&eDw0, cudaEventDisableTiming);
        cudaEventCreateWithFlags(&eDw1, cudaEventDisableTiming);
        cudaEventCreateWithFlags(&eO3,  cudaEventDisableTiming);
        cudaEventCreateWithFlags(&eO20, cudaEventDisableTiming);
        cudaEventCreateWithFlags(&eStR, cudaEventDisableTiming);
        cudaEventCreateWithFlags(&eFc,  cudaEventDisableTiming);
        cudaEventCreateWithFlags(&eL1,  cudaEventDisableTiming);
        cudaEventCreateWithFlags(&eL2,  cudaEventDisableTiming);
        inited = true;
    }
    cudaStream_t s0 = 0;

    // fork
    cudaEventRecord(eFork, s0);
    cudaStreamWaitEvent(s1, eFork, 0);
    cudaStreamWaitEvent(s2, eFork, 0);
    cudaStreamWaitEvent(s3, eFork, 0);

    // stage 1: per-source chains (dwS(src0) is global launch #3 for ncu)
    k_tr2<<<dim3(200, 8, NB), dim3(32,8), 0, s0>>>(x0, 0, 6400);
    k_tr2<<<dim3(50,  8, NB), dim3(32,8), 0, s1>>>(x1, 1, 1600);
    k_tr2<<<dim3(13,  8, NB), dim3(32,8), 0, s2>>>(x2, 2,  400);
    k_dwS<<<dim3(200, 1, NB), 256, 0, s0>>>(0, dw_w_m, dw_s_m, dw_b_m,
                                               dw_w_h, dw_s_h, dw_b_h,
                                               dw_w_l, dw_s_l, dw_b_l);
    cudaEventRecord(eDw0, s0);
    k_wt2<<<(3*192*112 + 255)/256, 256, 0, s3>>>(off_w);
    cudaEventRecord(eWt, s3);
    k_dwS<<<dim3(50, 1, NB), 256, 0, s1>>>(1, dw_w_m, dw_s_m, dw_b_m,
                                              dw_w_h, dw_s_h, dw_b_h,
                                              dw_w_l, dw_s_l, dw_b_l);
    cudaEventRecord(eDw1, s1);
    k_dwS<<<dim3(13, 1, NB), 256, 0, s2>>>(2, dw_w_m, dw_s_m, dw_b_m,
                                              dw_w_h, dw_s_h, dw_b_h,
                                              dw_w_l, dw_s_l, dw_b_l);

    // stage 2: om per class, each as early as its deps allow
    cudaStreamWaitEvent(s0, eWt, 0);
    cudaStreamWaitEvent(s1, eWt, 0);
    cudaStreamWaitEvent(s2, eWt, 0);
    cudaStreamWaitEvent(s3, eDw0, 0);
    const int SM80 = (64*84 + 192*28)*4;   // 43008 B (<48KB, no attribute needed)
    const int SM40 = (64*44 + 192*28)*4;
    const int SM40s2 = (64*84 + 192*28)*4; // full-row stride-2 tile
    const int SM20 = (64*24 + 192*28)*4;
    // critical path: om80 (b0), full 80-px row per block
    k_om3<1,80,4,20,160><<<dim3(1*80*NB, 4, 1), 160, SM80, s0>>>(80, 80, 80, 80, off_b, 0, 0);
    // b1,b2 on s1; b3 full-row stride-2 + b6 on s3; b4,b5 on s2
    k_om3<1,40,4,10,80><<<dim3(1*40*NB, 4, 2), 80, SM40, s1>>>(40, 40, 40, 40, off_b, 1, 2);
    k_om3<2,40,2,20,160><<<dim3(1*40*NB, 4, 1), 160, SM40s2, s3>>>(80, 80, 40, 40, off_b, 3, 3);
    cudaStreamWaitEvent(s3, eDw1, 0);
    k_om3<2,20,2,10,80><<<dim3(1*20*NB, 4, 1), 80, SM40, s3>>>(40, 40, 20, 20, off_b, 6, 6);
    cudaEventRecord(eO3, s3);
    cudaStreamWaitEvent(s2, eDw1, 0);
    k_om3<1,20,4,5,64><<<dim3(1*20*NB, 4, 2), 64, SM20, s2>>>(20, 20, 20, 20, off_b, 4, 5);
    cudaEventRecord(eO20, s2);

    // stage 3a: sampler+stats for b0 on s0 (critical path)
    k_sampB <<<dim3(800, NB),  256, 0, s0>>>(0);
    k_statsB<<<dim3(16, NB),   256, 0, s0>>>(0);

    // stage 3b: sampler+stats for b1..b6 on s1 (overlaps om80/samp_b0)
    cudaStreamWaitEvent(s1, eO3, 0);
    cudaStreamWaitEvent(s1, eO20, 0);
    k_sampB <<<dim3(750, NB),  256, 0, s1>>>(800);
    k_statsB<<<dim3(6*16, NB), 256, 0, s1>>>(1);
    cudaEventRecord(eStR, s1);

    // stage 3c: attn + fc on s0 (needs all stats)
    cudaStreamWaitEvent(s0, eStR, 0);
    k_attnB <<<dim3(3, NB), 256, 0, s0>>>(sa_w, sa_b, gn_g_m, gn_b_m, gn_g_h, gn_b_h, gn_g_l, gn_b_l);
    k_fcB   <<<3,           256, 0, s0>>>(fc1_w, fc1_b, fc2_w, fc2_b);
    cudaEventRecord(eFc, s0);
    cudaStreamWaitEvent(s1, eFc, 0);
    cudaStreamWaitEvent(s2, eFc, 0);

    // stage 4: fused outputs concurrent
    k_outL<0><<<dim3(200, NB), dim3(32,8), 0, s0>>>(out,
        gn_g_m, gn_b_m, gn_g_h, gn_b_h, gn_g_l, gn_b_l);
    k_outL<1><<<dim3(50, NB),  dim3(32,8), 0, s1>>>(out + (size_t)NB*CH*6400,
        gn_g_m, gn_b_m, gn_g_h, gn_b_h, gn_g_l, gn_b_l);
    k_outL<2><<<dim3(13, NB),  dim3(32,8), 0, s2>>>(out + (size_t)NB*CH*8000,
        gn_g_m, gn_b_m, gn_g_h, gn_b_h, gn_g_l, gn_b_l);
    cudaEventRecord(eL1, s1);
    cudaEventRecord(eL2, s2);
    cudaStreamWaitEvent(s0, eL1, 0);
    cudaStreamWaitEvent(s0, eL2, 0);
}

// round 13
// speedup vs baseline: 1.2655x; 1.0074x over previous
#include <cuda_runtime.h>
#include <math.h>

#define NB   4
#define CH   256
#define OMC  108

// ---- packed f32x2 ops ----
#define PACKF2(out, lo, hi) \
    asm("mov.b64 %0, {%1, %2};" : "=l"(out) : "f"(lo), "f"(hi))
#define UNPACKF2(lo, hi, in) \
    asm("mov.b64 {%0, %1}, %2;" : "=f"(lo), "=f"(hi) : "l"(in))
#define FMAF2(d, a, b, c) \
    asm("fma.rn.f32x2 %0, %1, %2, %3;" : "=l"(d) : "l"(a), "l"(b), "l"(c))

// ---- branch tables (7 branches) ----
__device__ __constant__ int BR_SRC[7]    = {0,1,1,0,2,2,1};
__device__ __constant__ int BR_HS[7]     = {80,40,40,80,20,20,40};
__device__ __constant__ int BR_STRIDE[7] = {1,1,1,2,1,1,2};
__device__ __constant__ int BR_HO[7]     = {80,40,40,40,20,20,20};
__device__ __constant__ int BR_SOFT[7]   = {0,1,0,1,1,0,1};
__device__ __constant__ int BR_UPH[7]    = {0,80,0,0,40,0,0};
__device__ __constant__ int BR_GNSEL[7]  = {0,1,0,2,1,0,2};
__device__ __constant__ int DWPFX[7]     = {0,6400,8000,9600,16000,16400,16800};
__device__ __constant__ int OMPFX[7]     = {0,6400,8000,9600,11200,11600,12000};
__device__ __constant__ int SAMP_PFX16[7] = {0,400,500,600,700,725,750};

__device__ __constant__ int SRC_NSETS[3]  = {2,3,2};
__device__ __constant__ int SRC_WSEL[3][3]= {{0,2,0},{1,0,2},{1,0,0}};
__device__ __constant__ int SRC_DST[3][3] = {{0,9600,0},{6400,8000,16800},{16000,16400,0}};

// ---------------- scratch ----------------
__device__ float g_x0[NB*80*80*CH];
__device__ float g_x1[NB*40*40*CH];
__device__ float g_x2[NB*20*20*CH];
__device__ float g_dwb[18400*NB*CH];
__device__ float g_om [12400*NB*OMC];
__device__ float g_feat[12400*NB*CH];
__device__ float g_wT2[3*192*112];
__device__ float g_a[7*NB];
__device__ float g_y[3*NB*CH];
__device__ float g_z[3*NB*1024];
__device__ float g_cmean[7*NB*CH];
__device__ float g_gmu[7*NB*16];
__device__ float g_ginv[7*NB*16];

__device__ __forceinline__ const float* pick_x(int s){
    return s==0 ? g_x0 : (s==1 ? g_x1 : g_x2);
}
__device__ __forceinline__ float* pick_xm(int s){
    return s==0 ? g_x0 : (s==1 ? g_x1 : g_x2);
}

// ---------------- NCHW -> NHWC tiled transpose ----------------
__global__ void k_tr2(const float* __restrict__ in, int sel, int HW){
    __shared__ float tile[32][33];
    float* out = pick_xm(sel);
    int n  = blockIdx.z;
    int hw0 = blockIdx.x*32;
    int c0  = blockIdx.y*32;
    int tx = threadIdx.x, ty = threadIdx.y;
    #pragma unroll
    for (int q = 0; q < 4; ++q){
        int c = c0 + ty + q*8;
        int hw = hw0 + tx;
        float v = (hw < HW) ? in[((size_t)n*CH + c)*HW + hw] : 0.f;
        tile[ty + q*8][tx] = v;
    }
    __syncthreads();
    #pragma unroll
    for (int q = 0; q < 4; ++q){
        int hw = hw0 + ty + q*8;
        int c  = c0 + tx;
        if (hw < HW) out[((size_t)n*HW + hw)*CH + c] = tile[tx][ty + q*8];
    }
}

// weight transform: [dy][ic*3+dx][slot(4g x 28)]
__global__ void k_wt2(const float* __restrict__ ow){
    int i = blockIdx.x*blockDim.x + threadIdx.x;
    if (i >= 3*192*112) return;
    int slot = i % 112;
    int r    = (i / 112) % 192;
    int dy   = i / (112*192);
    int ic = r/3, dx = r%3;
    int g = slot/28, jj = slot%28;
    float v = 0.f;
    if (jj < 27) v = ow[(g*27+jj)*576 + ic*9 + dy*3 + dx];
    g_wT2[i] = v;
}

// ---------------- shared-source depthwise conv (single source per launch) ----
__global__ void __launch_bounds__(256, 3)
k_dwS(int src,
      const float* __restrict__ wm, const float* __restrict__ sm_, const float* __restrict__ bm_,
      const float* __restrict__ wh, const float* __restrict__ sh_, const float* __restrict__ bh_,
      const float* __restrict__ wl, const float* __restrict__ sl_, const float* __restrict__ bl_){
    __shared__ unsigned long long wsm[3][64][9][2];
    __shared__ float4 ssm[3][64], bsm[3][64];
    int n = blockIdx.z;
    int H = (src==0) ? 80 : (src==1 ? 40 : 20);
    int W = H, HW = H*W;
    int nsets = SRC_NSETS[src];
    int t = threadIdx.x;

    for (int s = 0; s < nsets; ++s){
        int sel = SRC_WSEL[src][s];
        const float* wgt = sel==0 ? wm : (sel==1 ? wh : wl);
        const float* sc  = sel==0 ? sm_ : (sel==1 ? sh_ : sl_);
        const float* bi  = sel==0 ? bm_ : (sel==1 ? bh_ : bl_);
        for (int i = t; i < 64*9; i += 256){
            int q = i/9, tp = i%9;
            float a0 = wgt[(q*4+0)*9 + tp], a1 = wgt[(q*4+1)*9 + tp];
            float a2 = wgt[(q*4+2)*9 + tp], a3 = wgt[(q*4+3)*9 + tp];
            PACKF2(wsm[s][q][tp][0], a0, a1);
            PACKF2(wsm[s][q][tp][1], a2, a3);
        }
        for (int i = t; i < 64; i += 256){
            ssm[s][i] = *(const float4*)(sc + i*4);
            bsm[s][i] = *(const float4*)(bi + i*4);
        }
    }
    __syncthreads();

    const float* x = pick_x(src);
    int q  = t & 63;
    int c0 = q*4;
    int lane = t >> 6;
    for (int hw = blockIdx.x*4 + lane; hw < HW; hw += gridDim.x*4){
        int w = hw % W, h = hw / W;
        ulonglong2 tap[9];
        #pragma unroll
        for (int dy = 0; dy < 3; ++dy){
            int yy = h + dy - 1;
            #pragma unroll
            for (int dx = 0; dx < 3; ++dx){
                int xx = w + dx - 1;
                int tp = dy*3 + dx;
                if (yy >= 0 && yy < H && xx >= 0 && xx < W)
                    tap[tp] = *(const ulonglong2*)(x + ((size_t)(n*H+yy)*W + xx)*CH + c0);
                else { tap[tp].x = 0ull; tap[tp].y = 0ull; }
            }
        }
        #pragma unroll 3
        for (int s = 0; s < 3; ++s){
            if (s >= nsets) break;
            unsigned long long a01 = 0ull, a23 = 0ull;
            #pragma unroll
            for (int tp = 0; tp < 9; ++tp){
                FMAF2(a01, tap[tp].x, wsm[s][q][tp][0], a01);
                FMAF2(a23, tap[tp].y, wsm[s][q][tp][1], a23);
            }
            float ax, ay, az, aw;
            UNPACKF2(ax, ay, a01);
            UNPACKF2(az, aw, a23);
            float4 s4 = ssm[s][q], b4 = bsm[s][q];
            float4 o;
            float t0 = ax*s4.x + b4.x; o.x = t0/(1.f+expf(-t0));
            float t1 = ay*s4.y + b4.y; o.y = t1/(1.f+expf(-t1));
            float t2 = az*s4.z + b4.z; o.z = t2/(1.f+expf(-t2));
            float t3 = aw*s4.w + b4.w; o.w = t3/(1.f+expf(-t3));
            float* dst = g_dwb + (size_t)SRC_DST[src][s]*NB*CH;
            *(float4*)(dst + ((size_t)n*HW + hw)*CH + c0) = o;
        }
    }
}

// ---------------- grouped conv 256->108, per-group blocks, FFMA2 ----
template<int STRIDE, int PXO, int TPX, int PXQ, int THREADS>
__global__ void __launch_bounds__(THREADS)
k_om3(int H, int W, int Ho, int Wo, const float* __restrict__ ob, int bA, int bB){
    constexpr int PW  = (PXO-1)*STRIDE + 3;
    constexpr int PWP = (PW + 3) & ~3;
    constexpr int WIN = 3 + (TPX-1)*STRIDE;
    static_assert((TPX*STRIDE) % 4 == 0, "window alignment");
    static_assert(WIN <= 8, "window fits two float4");
    extern __shared__ float sh[];
    float* patch = sh;
    float* wsl   = sh + 64*PWP;

    int br   = blockIdx.z == 0 ? bA : bB;
    const float* src = g_dwb + (size_t)DWPFX[br]*NB*CH;
    float* dst       = g_om  + (size_t)OMPFX[br]*NB*OMC;

    int nt   = (Wo + PXO - 1)/PXO;
    int g    = blockIdx.y;
    int b    = blockIdx.x;
    int tile = b % nt;
    int ho   = (b/nt) % Ho;
    int n    = b/(nt*Ho);
    int wo0  = tile*PXO;
    int hsrc = ho*STRIDE;
    int wsrc0= wo0*STRIDE;
    int cb   = g*64;

    int t   = threadIdx.x;
    int pxq = t % PXQ;
    int li  = t / PXQ;
    bool act = li < 7;
    int xb  = pxq*TPX*STRIDE;

    unsigned long long a01[TPX], a23[TPX];
    #pragma unroll
    for (int p = 0; p < TPX; ++p){ a01[p] = 0ull; a23[p] = 0ull; }

    const float* wsrc_base = g_wT2 + g*28;
    for (int dy = 0; dy < 3; ++dy){
        __syncthreads();
        int gy = hsrc + dy - 1;
        for (int i = t; i < PW*64; i += THREADS){
            int c = i & 63, xx = i >> 6;
            int gx = wsrc0 + xx - 1;
            float v = 0.f;
            if (gy >= 0 && gy < H && gx >= 0 && gx < W)
                v = src[((size_t)(n*H+gy)*W + gx)*CH + cb + c];
            patch[c*PWP + xx] = v;
        }
        {
            const float* ws = wsrc_base + dy*192*112;
            for (int i = t; i < 192*7; i += THREADS){
                int row = i/7, col = (i%7)*4;
                *(float4*)(wsl + row*28 + col) = *(const float4*)(ws + row*112 + col);
            }
        }
        __syncthreads();
        if (act){
            #pragma unroll 4
            for (int ic = 0; ic < 64; ++ic){
                const float* pr = patch + ic*PWP + xb;
                float f[8];
                *(float4*)(f)   = *(const float4*)(pr);
                *(float4*)(f+4) = *(const float4*)(pr+4);
                unsigned long long sv[WIN];
                #pragma unroll
                for (int k2 = 0; k2 < WIN; ++k2) PACKF2(sv[k2], f[k2], f[k2]);
                const float* wb = wsl + (ic*3)*28 + li*4;
                #pragma unroll
                for (int dx = 0; dx < 3; ++dx){
                    ulonglong2 wv = *(const ulonglong2*)(wb + dx*28);
                    #pragma unroll
                    for (int p = 0; p < TPX; ++p){
                        FMAF2(a01[p], sv[dx + p*STRIDE], wv.x, a01[p]);
                        FMAF2(a23[p], sv[dx + p*STRIDE], wv.y, a23[p]);
                    }
                }
            }
        }
    }
    if (act){
        float bj[4];
        #pragma unroll
        for (int j = 0; j < 4; ++j){
            int jj = li*4 + j;
            bj[j] = (jj < 27) ? ob[g*27 + jj] : 0.f;
        }
        #pragma unroll
        for (int p = 0; p < TPX; ++p){
            int wo = wo0 + pxq*TPX + p;
            if (wo < Wo){
                size_t base = ((size_t)(n*Ho+ho)*Wo + wo)*OMC + g*27 + li*4;
                float av[4];
                UNPACKF2(av[0], av[1], a01[p]);
                UNPACKF2(av[2], av[3], a23[p]);
                #pragma unroll
                for (int j = 0; j < 4; ++j)
                    if (li*4 + j < 27) dst[base + j] = av[j] + bj[j];
            }
        }
    }
}

// ---------------- batched DCNv3 sampler: 16 px/block, 4 px/thread ----------
__global__ void k_sampB(int bx0){
    __shared__ float som[16][OMC];
    __shared__ float smk[16][36];
    __shared__ float sw[16][4][9][4];
    __shared__ int   soff[16][4][9][4];
    int bx = blockIdx.x + bx0;
    int b = 0;
    #pragma unroll
    for (int i = 1; i < 7; ++i) if (bx >= SAMP_PFX16[i]) b = i;
    int n = blockIdx.y;
    int p0 = (bx - SAMP_PFX16[b])*16;
    int Ho = BR_HO[b], Wo = Ho, HW = Ho*Wo;
    int H  = BR_HS[b], W = H;
    int stride = BR_STRIDE[b];
    int use_softmax = BR_SOFT[b];
    const float* x = pick_x(BR_SRC[b]);
    const float* omp = g_om + ((size_t)OMPFX[b]*NB + (size_t)n*HW)*OMC;
    int t = threadIdx.x;

    for (int i = t; i < 16*OMC; i += 256)
        som[i/OMC][i%OMC] = omp[(size_t)(p0 + i/OMC)*OMC + i%OMC];
    __syncthreads();

    if (use_softmax){
        if (t < 64){
            int pp = t >> 2, gg = t & 3;
            float mx = -1e30f;
            #pragma unroll
            for (int k = 0; k < 9; ++k) mx = fmaxf(mx, som[pp][72 + gg*9 + k]);
            float e[9], s = 0.f;
            #pragma unroll
            for (int k = 0; k < 9; ++k){ e[k] = expf(som[pp][72 + gg*9 + k] - mx); s += e[k]; }
            float inv = 1.f/s;
            #pragma unroll
            for (int k = 0; k < 9; ++k) smk[pp][gg*9 + k] = e[k]*inv;
        }
    } else {
        for (int i = t; i < 16*36; i += 256)
            smk[i/36][i%36] = 1.f/(1.f + expf(-som[i/36][72 + i%36]));
    }
    __syncthreads();

    for (int i = t; i < 16*36; i += 256){
        int pix = i / 36, r = i % 36, gg = r / 9, k = r % 9;
        int hw = p0 + pix;
        int wo = hw % Wo, ho = hw / Wo;
        float py = (float)(ho*stride) + (float)(k/3 - 1) + som[pix][gg*18 + k*2];
        float px = (float)(wo*stride) + (float)(k%3 - 1) + som[pix][gg*18 + k*2 + 1];
        float m  = smk[pix][gg*9 + k];
        float fy = floorf(py), fx = floorf(px);
        float wy = py - fy, wx = px - fx;
        int iy = (int)fy, ix = (int)fx;
        #pragma unroll
        for (int d0 = 0; d0 < 2; ++d0){
            int yy = iy + d0;
            float wgy = d0 ? wy : (1.f - wy);
            #pragma unroll
            for (int d1 = 0; d1 < 2; ++d1){
                int xx = ix + d1;
                bool valid = (yy >= 0) & (yy < H) & (xx >= 0) & (xx < W);
                int yc = min(max(yy, 0), H-1);
                int xc = min(max(xx, 0), W-1);
                sw[pix][gg][k][d0*2+d1]   = valid ? wgy*(d1 ? wx : (1.f - wx))*m : 0.f;
                soff[pix][gg][k][d0*2+d1] = ((n*H + yc)*W + xc)*CH;
            }
        }
    }
    __syncthreads();

    int lane = t >> 6, q = t & 63, c0 = q*4, g = q >> 4;
    const float* xc = x + c0;
    #pragma unroll
    for (int pi = 0; pi < 4; ++pi){
        int pix = lane + pi*4;
        unsigned long long acc01 = 0ull, acc23 = 0ull;
        #pragma unroll
        for (int k = 0; k < 9; ++k){
            float4 wv = *(const float4*)&sw[pix][g][k][0];
            int4  ov = *(const int4*)&soff[pix][g][k][0];
            unsigned long long w0, w1, w2, w3;
            PACKF2(w0, wv.x, wv.x); PACKF2(w1, wv.y, wv.y);
            PACKF2(w2, wv.z, wv.z); PACKF2(w3, wv.w, wv.w);
            ulonglong2 v0 = *(const ulonglong2*)(xc + ov.x);
            ulonglong2 v1 = *(const ulonglong2*)(xc + ov.y);
            ulonglong2 v2 = *(const ulonglong2*)(xc + ov.z);
            ulonglong2 v3 = *(const ulonglong2*)(xc + ov.w);
            FMAF2(acc01, v0.x, w0, acc01); FMAF2(acc23, v0.y, w0, acc23);
            FMAF2(acc01, v1.x, w1, acc01); FMAF2(acc23, v1.y, w1, acc23);
            FMAF2(acc01, v2.x, w2, acc01); FMAF2(acc23, v2.y, w2, acc23);
            FMAF2(acc01, v3.x, w3, acc01); FMAF2(acc23, v3.y, w3, acc23);
        }
        float4 acc;
        UNPACKF2(acc.x, acc.y, acc01);
        UNPACKF2(acc.z, acc.w, acc23);
        *(float4*)(g_feat + ((size_t)OMPFX[b]*NB + (size_t)n*HW + p0 + pix)*CH + c0) = acc;
    }
}

// ---------------- batched stats (branch-offset subset launch) ----------------
__global__ void k_statsB(int boff){
    __shared__ float wy[80], wx[80];
    __shared__ float r1[256], r2[256];
    __shared__ float4 rw[256];
    int b = (blockIdx.x >> 4) + boff, g = blockIdx.x & 15, n = blockIdx.y;
    int Hs = BR_HO[b], Ws = Hs, HW = Hs*Ws;
    int uph = BR_UPH[b];
    float normw = uph ? 1.f/((float)uph*(float)uph) : 1.f/(float)HW;
    int t = threadIdx.x;
    if (t == 0){
        if (uph){
            for (int i = 0; i < Hs; ++i){ wy[i] = 0.f; wx[i] = 0.f; }
            float ry = (float)(Hs-1)/(float)(uph-1);
            for (int j = 0; j < uph; ++j){
                float c = j*ry; int i0 = (int)floorf(c); float f = c - (float)i0;
                wy[i0] += 1.f - f;
                if (i0 + 1 < Hs) wy[i0+1] += f;
            }
            for (int i = 0; i < Hs; ++i) wx[i] = wy[i];
        } else {
            for (int i = 0; i < Hs; ++i){ wy[i] = 1.f; wx[i] = 1.f; }
        }
    }
    __syncthreads();

    const float* fb = g_feat + ((size_t)OMPFX[b]*NB + (size_t)n*HW)*CH;
    int q  = t & 3;
    int c0 = g*16 + q*4;
    float4 s4 = make_float4(0,0,0,0), w4 = make_float4(0,0,0,0);
    float ss = 0.f;
    int hw0 = t >> 2;
    int h = hw0 / Ws, w = hw0 % Ws;
    for (int hw = hw0; hw < HW; hw += 64){
        float4 v = *(const float4*)(fb + (size_t)hw*CH + c0);
        s4.x += v.x; s4.y += v.y; s4.z += v.z; s4.w += v.w;
        ss += v.x*v.x + v.y*v.y + v.z*v.z + v.w*v.w;
        float ww = wy[h]*wx[w];
        w4.x += v.x*ww; w4.y += v.y*ww; w4.z += v.z*ww; w4.w += v.w*ww;
        w += 64; while (w >= Ws){ w -= Ws; ++h; }
    }
    r1[t] = s4.x + s4.y + s4.z + s4.w;
    r2[t] = ss;
    rw[t] = w4;
    __syncthreads();
    for (int o = 128; o >= 4; o >>= 1){
        if (t < o){
            r1[t] += r1[t+o]; r2[t] += r2[t+o];
            rw[t].x += rw[t+o].x; rw[t].y += rw[t+o].y;
            rw[t].z += rw[t+o].z; rw[t].w += rw[t+o].w;
        }
        __syncthreads();
    }
    if (t == 0){
        float s  = r1[0] + r1[1] + r1[2] + r1[3];
        float sq = r2[0] + r2[1] + r2[2] + r2[3];
        float cnt = (float)HW*16.f;
        float mu  = s/cnt;
        float var = sq/cnt - mu*mu;
        g_gmu [(b*NB+n)*16 + g] = mu;
        g_ginv[(b*NB+n)*16 + g] = rsqrtf(var + 1e-5f);
    }
    if (t < 4){
        float4 wv = rw[t];
        int c = (b*NB+n)*CH + g*16 + t*4;
        g_cmean[c]   = wv.x*normw; g_cmean[c+1] = wv.y*normw;
        g_cmean[c+2] = wv.z*normw; g_cmean[c+3] = wv.w*normw;
    }
}

// ---------------- attn scalars + pooled means ----------------
__device__ __constant__ int LVL_NBR[3] = {2,3,2};
__device__ __constant__ int LVL_BRS[3][3] = {{0,1,-1},{2,3,4},{5,6,-1}};

__global__ void k_attnB(const float* __restrict__ saw, const float* __restrict__ sab,
                        const float* __restrict__ gm, const float* __restrict__ bm,
                        const float* __restrict__ gh, const float* __restrict__ bh,
                        const float* __restrict__ gl, const float* __restrict__ bl){
    __shared__ float red[256];
    __shared__ float sa;
    int lvl = blockIdx.x, n = blockIdx.y, t = threadIdx.x;
    int g = t >> 4;
    int nbr = LVL_NBR[lvl];
    float invl = 1.f/(float)nbr;
    float y = 0.f;
    for (int i = 0; i < nbr; ++i){
        int b = LVL_BRS[lvl][i];
        int gs = BR_GNSEL[b];
        const float* gam = gs==0 ? gm : (gs==1 ? gh : gl);
        const float* bet = gs==0 ? bm : (gs==1 ? bh : bl);
        float m = (g_cmean[(b*NB+n)*CH + t] - g_gmu[(b*NB+n)*16 + g])
                  * g_ginv[(b*NB+n)*16 + g] * gam[t] + bet[t];
        red[t] = m*saw[t];
        __syncthreads();
        for (int o = 128; o > 0; o >>= 1){
            if (t < o) red[t] += red[t+o];
            __syncthreads();
        }
        if (t == 0){
            float a = red[0] + sab[0];
            a = fmaxf(a, 0.f);
            a = fminf(fmaxf((a + 3.f)/6.f, 0.f), 1.f);
            sa = a; g_a[b*NB + n] = a;
        }
        __syncthreads();
        y += sa*m*invl;
        __syncthreads();
    }
    g_y[(lvl*NB + n)*CH + t] = y;
}

// ---------------- fc (all levels) ----------------
__global__ void k_fcB(const float* __restrict__ w1, const float* __restrict__ b1,
                      const float* __restrict__ w2, const float* __restrict__ b2){
    __shared__ float h[4][64];
    int lvl = blockIdx.x;
    int t = threadIdx.x;
    int n = t >> 6, j = t & 63;
    float s = b1[j];
    const float* wr = w1 + j*CH;
    const float* yv = g_y + (lvl*NB + n)*CH;
    for (int c = 0; c < CH; ++c) s += yv[c]*wr[c];
    h[n][j] = fmaxf(s, 0.f);
    __syncthreads();
    for (int og = t; og < NB*1024; og += 256){
        int nn = og >> 10, o = og & 1023;
        float s2 = b2[o];
        const float* w2r = w2 + o*64;
        #pragma unroll 16
        for (int j2 = 0; j2 < 64; ++j2) s2 += h[nn][j2]*w2r[j2];
        float z = fminf(fmaxf(s2 + 3.f, 0.f), 6.f)*(1.f/6.f);
        int qd = o >> 8;
        float v;
        if      (qd == 0) v = (z - 0.5f)*2.f + 1.f;
        else if (qd == 2) v = (z - 0.5f)*2.f;
        else              v = z - 0.5f;
        g_z[(lvl*NB + nn)*1024 + o] = v;
    }
}

// ---------------- fused: GN+attn+upsample sum -> dyrelu -> NCHW out ----------
__device__ __forceinline__ void gn_acc(float4& o, float4 raw, int b, int n, int g,
                                       float4 g4, float4 b4){
    float mu = g_gmu[(b*NB+n)*16 + g], inv = g_ginv[(b*NB+n)*16 + g], a = g_a[b*NB + n];
    o.x += a*((raw.x - mu)*inv*g4.x + b4.x);
    o.y += a*((raw.y - mu)*inv*g4.y + b4.y);
    o.z += a*((raw.z - mu)*inv*g4.z + b4.z);
    o.w += a*((raw.w - mu)*inv*g4.w + b4.w);
}
__device__ __forceinline__ float4 feat_rd(int b, int n, int HW, int hw, int c0){
    return *(const float4*)(g_feat + ((size_t)OMPFX[b]*NB + (size_t)n*HW + hw)*CH + c0);
}
__device__ __forceinline__ float4 feat_up(int b, int n, int Hs, int Ho, int h, int w, int c0){
    float r = (float)(Hs-1)/(float)(Ho-1);
    float cy = h*r, cx = w*r;
    int y0 = (int)floorf(cy), x0 = (int)floorf(cx);
    int y1 = min(y0+1, Hs-1), x1 = min(x0+1, Hs-1);
    float wyf = cy - (float)y0, wxf = cx - (float)x0;
    const float* fb = g_feat + ((size_t)OMPFX[b]*NB + (size_t)n*Hs*Hs)*CH + c0;
    float4 v00 = *(const float4*)(fb + (size_t)(y0*Hs + x0)*CH);
    float4 v01 = *(const float4*)(fb + (size_t)(y0*Hs + x1)*CH);
    float4 v10 = *(const float4*)(fb + (size_t)(y1*Hs + x0)*CH);
    float4 v11 = *(const float4*)(fb + (size_t)(y1*Hs + x1)*CH);
    float a0 = (1.f-wyf)*(1.f-wxf), a1 = (1.f-wyf)*wxf, a2 = wyf*(1.f-wxf), a3 = wyf*wxf;
    float4 o;
    o.x = v00.x*a0 + v01.x*a1 + v10.x*a2 + v11.x*a3;
    o.y = v00.y*a0 + v01.y*a1 + v10.y*a2 + v11.y*a3;
    o.z = v00.z*a0 + v01.z*a1 + v10.z*a2 + v11.z*a3;
    o.w = v00.w*a0 + v01.w*a1 + v10.w*a2 + v11.w*a3;
    return o;
}

template<int LVL>
__global__ void k_outL(float* __restrict__ out,
                       const float* __restrict__ gm, const float* __restrict__ bm,
                       const float* __restrict__ gh, const float* __restrict__ bh,
                       const float* __restrict__ gl, const float* __restrict__ bl){
    constexpr int HoL = (LVL==0) ? 80 : (LVL==1 ? 40 : 20);
    constexpr int HWL = HoL*HoL;
    constexpr float INVL = (LVL==1) ? (1.f/3.f) : 0.5f;
    __shared__ float tile[32][257];
    int n   = blockIdx.y;
    int hw0 = blockIdx.x*32;
    int tx = threadIdx.x, ty = threadIdx.y;
    int tid = ty*32 + tx;

    #pragma unroll
    for (int k = 0; k < 8; ++k){
        int e = k*256 + tid;
        int hwl = e >> 6;
        int q   = e & 63;
        int hw  = hw0 + hwl;
        if (hw < HWL){
            int c0 = q*4, g = q >> 2;
            int w = hw % HoL, h = hw / HoL;
            float4 o = make_float4(0,0,0,0);
            float4 g4, b4;
            if (LVL == 0){
                g4 = *(const float4*)(gm + c0); b4 = *(const float4*)(bm + c0);
                gn_acc(o, feat_rd(0, n, 6400, hw, c0), 0, n, g, g4, b4);
                g4 = *(const float4*)(gh + c0); b4 = *(const float4*)(bh + c0);
                gn_acc(o, feat_up(1, n, 40, 80, h, w, c0), 1, n, g, g4, b4);
            } else if (LVL == 1){
                g4 = *(const float4*)(gm + c0); b4 = *(const float4*)(bm + c0);
                gn_acc(o, feat_rd(2, n, 1600, hw, c0), 2, n, g, g4, b4);
                g4 = *(const float4*)(gl + c0); b4 = *(const float4*)(bl + c0);
                gn_acc(o, feat_rd(3, n, 1600, hw, c0), 3, n, g, g4, b4);
                g4 = *(const float4*)(gh + c0); b4 = *(const float4*)(bh + c0);
                gn_acc(o, feat_up(4, n, 20, 40, h, w, c0), 4, n, g, g4, b4);
            } else {
                g4 = *(const float4*)(gm + c0); b4 = *(const float4*)(bm + c0);
                gn_acc(o, feat_rd(5, n, 400, hw, c0), 5, n, g, g4, b4);
                g4 = *(const float4*)(gl + c0); b4 = *(const float4*)(bl + c0);
                gn_acc(o, feat_rd(6, n, 400, hw, c0), 6, n, g, g4, b4);
            }
            tile[hwl][c0]   = o.x;
            tile[hwl][c0+1] = o.y;
            tile[hwl][c0+2] = o.z;
            tile[hwl][c0+3] = o.w;
        }
    }
    __syncthreads();

    int hw = hw0 + tx;
    if (hw < HWL){
        const float* zb = g_z + (LVL*NB + n)*1024;
        #pragma unroll
        for (int k = 0; k < 32; ++k){
            int c = ty + k*8;
            float f = tile[tx][c]*INVL;
            float a1 = zb[c], b1 = zb[256 + c];
            float a2 = zb[512 + c], b2 = zb[768 + c];
            out[((size_t)n*CH + c)*HWL + hw] = fmaxf(f*a1 + b1, f*a2 + b2);
        }
    }
}

// ---------------- host: branch-pipelined fork/join (graph-capturable) ----------
extern "C" void kernel_launch(void* const* d_in, const int* in_sizes, int n_in,
                              void* d_out, int out_size){
    const float* x0     = (const float*)d_in[0];
    const float* x1     = (const float*)d_in[1];
    const float* x2     = (const float*)d_in[2];
    const float* dw_w_h = (const float*)d_in[3];
    const float* dw_s_h = (const float*)d_in[4];
    const float* dw_b_h = (const float*)d_in[5];
    const float* dw_w_m = (const float*)d_in[6];
    const float* dw_s_m = (const float*)d_in[7];
    const float* dw_b_m = (const float*)d_in[8];
    const float* dw_w_l = (const float*)d_in[9];
    const float* dw_s_l = (const float*)d_in[10];
    const float* dw_b_l = (const float*)d_in[11];
    const float* off_w  = (const float*)d_in[12];
    const float* off_b  = (const float*)d_in[13];
    const float* gn_g_h = (const float*)d_in[14];
    const float* gn_b_h = (const float*)d_in[15];
    const float* gn_g_m = (const float*)d_in[16];
    const float* gn_b_m = (const float*)d_in[17];
    const float* gn_g_l = (const float*)d_in[18];
    const float* gn_b_l = (const float*)d_in[19];
    const float* sa_w   = (const float*)d_in[20];
    const float* sa_b   = (const float*)d_in[21];
    const float* fc1_w  = (const float*)d_in[22];
    const float* fc1_b  = (const float*)d_in[23];
    const float* fc2_w  = (const float*)d_in[24];
    const float* fc2_b  = (const float*)d_in[25];
    float* out = (float*)d_out;

    static cudaStream_t s1, s2, s3;
    static cudaEvent_t eFork, eWt, eDw0, eDw1, eO3, eO20, eStR, eFc, eL1, eL2;
    static bool inited = false;
    if (!inited){
        cudaStreamCreateWithFlags(&s1, cudaStreamNonBlocking);
        cudaStreamCreateWithFlags(&s2, cudaStreamNonBlocking);
        cudaStreamCreateWithFlags(&s3, cudaStreamNonBlocking);
        cudaEventCreateWithFlags(&eFork, cudaEventDisableTiming);
        cudaEventCreateWithFlags(&eWt,  cudaEventDisableTiming);
        cudaEventCreateWithFlags(&eDw0, cudaEventDisableTiming);
        cudaEventCreateWithFlags(&eDw1, cudaEventDisableTiming);
        cudaEventCreateWithFlags(&eO3,  cudaEventDisableTiming);
        cudaEventCreateWithFlags(&eO20, cudaEventDisableTiming);
        cudaEventCreateWithFlags(&eStR, cudaEventDisableTiming);
        cudaEventCreateWithFlags(&eFc,  cudaEventDisableTiming);
        cudaEventCreateWithFlags(&eL1,  cudaEventDisableTiming);
        cudaEventCreateWithFlags(&eL2,  cudaEventDisableTiming);
        inited = true;
    }
    cudaStream_t s0 = 0;

    // fork
    cudaEventRecord(eFork, s0);
    cudaStreamWaitEvent(s1, eFork, 0);
    cudaStreamWaitEvent(s2, eFork, 0);
    cudaStreamWaitEvent(s3, eFork, 0);

    // stage 1: per-source chains (dwS(src0) is global launch #3 for ncu)
    k_tr2<<<dim3(200, 8, NB), dim3(32,8), 0, s0>>>(x0, 0, 6400);
    k_tr2<<<dim3(50,  8, NB), dim3(32,8), 0, s1>>>(x1, 1, 1600);
    k_tr2<<<dim3(13,  8, NB), dim3(32,8), 0, s2>>>(x2, 2,  400);
    k_dwS<<<dim3(200, 1, NB), 256, 0, s0>>>(0, dw_w_m, dw_s_m, dw_b_m,
                                               dw_w_h, dw_s_h, dw_b_h,
                                               dw_w_l, dw_s_l, dw_b_l);
    cudaEventRecord(eDw0, s0);
    k_wt2<<<(3*192*112 + 255)/256, 256, 0, s3>>>(off_w);
    cudaEventRecord(eWt, s3);
    k_dwS<<<dim3(50, 1, NB), 256, 0, s1>>>(1, dw_w_m, dw_s_m, dw_b_m,
                                              dw_w_h, dw_s_h, dw_b_h,
                                              dw_w_l, dw_s_l, dw_b_l);
    cudaEventRecord(eDw1, s1);
    k_dwS<<<dim3(13, 1, NB), 256, 0, s2>>>(2, dw_w_m, dw_s_m, dw_b_m,
                                              dw_w_h, dw_s_h, dw_b_h,
                                              dw_w_l, dw_s_l, dw_b_l);

    // stage 2: om per class, each as early as its deps allow
    cudaStreamWaitEvent(s0, eWt, 0);
    cudaStreamWaitEvent(s1, eWt, 0);
    cudaStreamWaitEvent(s2, eWt, 0);
    cudaStreamWaitEvent(s3, eDw0, 0);
    const int SM80 = (64*84 + 192*28)*4;
    const int SM40 = (64*44 + 192*28)*4;
    const int SM40s2 = (64*84 + 192*28)*4;
    const int SM20 = (64*24 + 192*28)*4;
    k_om3<1,80,4,20,160><<<dim3(1*80*NB, 4, 1), 160, SM80, s0>>>(80, 80, 80, 80, off_b, 0, 0);
    k_om3<1,40,4,10,80><<<dim3(1*40*NB, 4, 2), 80, SM40, s1>>>(40, 40, 40, 40, off_b, 1, 2);
    k_om3<2,40,2,20,160><<<dim3(1*40*NB, 4, 1), 160, SM40s2, s3>>>(80, 80, 40, 40, off_b, 3, 3);
    cudaStreamWaitEvent(s3, eDw1, 0);
    k_om3<2,20,2,10,80><<<dim3(1*20*NB, 4, 1), 80, SM40, s3>>>(40, 40, 20, 20, off_b, 6, 6);
    cudaEventRecord(eO3, s3);
    cudaStreamWaitEvent(s2, eDw1, 0);
    k_om3<1,20,4,5,64><<<dim3(1*20*NB, 4, 2), 64, SM20, s2>>>(20, 20, 20, 20, off_b, 4, 5);
    cudaEventRecord(eO20, s2);

    // stage 3a: sampler+stats for b0 on s0 (critical path)
    k_sampB <<<dim3(400, NB),  256, 0, s0>>>(0);
    k_statsB<<<dim3(16, NB),   256, 0, s0>>>(0);

    // stage 3b: sampler+stats for b1..b6 on s1 (375 blocks = 400..774)
    cudaStreamWaitEvent(s1, eO3, 0);
    cudaStreamWaitEvent(s1, eO20, 0);
    k_sampB <<<dim3(375, NB),  256, 0, s1>>>(400);
    k_statsB<<<dim3(6*16, NB), 256, 0, s1>>>(1);
    cudaEventRecord(eStR, s1);

    // stage 3c: attn + fc on s0
    cudaStreamWaitEvent(s0, eStR, 0);
    k_attnB <<<dim3(3, NB), 256, 0, s0>>>(sa_w, sa_b, gn_g_m, gn_b_m, gn_g_h, gn_b_h, gn_g_l, gn_b_l);
    k_fcB   <<<3,           256, 0, s0>>>(fc1_w, fc1_b, fc2_w, fc2_b);
    cudaEventRecord(eFc, s0);
    cudaStreamWaitEvent(s1, eFc, 0);
    cudaStreamWaitEvent(s2, eFc, 0);

    // stage 4: fused outputs concurrent
    k_outL<0><<<dim3(200, NB), dim3(32,8), 0, s0>>>(out,
        gn_g_m, gn_b_m, gn_g_h, gn_b_h, gn_g_l, gn_b_l);
    k_outL<1><<<dim3(50, NB),  dim3(32,8), 0, s1>>>(out + (size_t)NB*CH*6400,
        gn_g_m, gn_b_m, gn_g_h, gn_b_h, gn_g_l, gn_b_l);
    k_outL<2><<<dim3(13, NB),  dim3(32,8), 0, s2>>>(out + (size_t)NB*CH*8000,
        gn_g_m, gn_b_m, gn_g_h, gn_b_h, gn_g_l, gn_b_l);
    cudaEventRecord(eL1, s1);
    cudaEventRecord(eL2, s2);
    cudaStreamWaitEvent(s0, eL1, 0);
    cudaStreamWaitEvent(s0, eL2, 0);
}

// round 14
// speedup vs baseline: 1.2711x; 1.0044x over previous
#include <cuda_runtime.h>
#include <math.h>

#define NB   4
#define CH   256
#define OMC  108

// ---- packed f32x2 ops ----
#define PACKF2(out, lo, hi) \
    asm("mov.b64 %0, {%1, %2};" : "=l"(out) : "f"(lo), "f"(hi))
#define UNPACKF2(lo, hi, in) \
    asm("mov.b64 {%0, %1}, %2;" : "=f"(lo), "=f"(hi) : "l"(in))
#define FMAF2(d, a, b, c) \
    asm("fma.rn.f32x2 %0, %1, %2, %3;" : "=l"(d) : "l"(a), "l"(b), "l"(c))

// ---- branch tables (7 branches) ----
__device__ __constant__ int BR_SRC[7]    = {0,1,1,0,2,2,1};
__device__ __constant__ int BR_HS[7]     = {80,40,40,80,20,20,40};
__device__ __constant__ int BR_STRIDE[7] = {1,1,1,2,1,1,2};
__device__ __constant__ int BR_HO[7]     = {80,40,40,40,20,20,20};
__device__ __constant__ int BR_SOFT[7]   = {0,1,0,1,1,0,1};
__device__ __constant__ int BR_UPH[7]    = {0,80,0,0,40,0,0};
__device__ __constant__ int BR_GNSEL[7]  = {0,1,0,2,1,0,2};
__device__ __constant__ int DWPFX[7]     = {0,6400,8000,9600,16000,16400,16800};
__device__ __constant__ int OMPFX[7]     = {0,6400,8000,9600,11200,11600,12000};
__device__ __constant__ int SAMP_PFX16[7] = {0,400,500,600,700,725,750};

__device__ __constant__ int SRC_NSETS[3]  = {2,3,2};
__device__ __constant__ int SRC_WSEL[3][3]= {{0,2,0},{1,0,2},{1,0,0}};
__device__ __constant__ int SRC_DST[3][3] = {{0,9600,0},{6400,8000,16800},{16000,16400,0}};

// ---------------- scratch ----------------
__device__ float g_x0[NB*80*80*CH];
__device__ float g_x1[NB*40*40*CH];
__device__ float g_x2[NB*20*20*CH];
__device__ float g_dwb[18400*NB*CH];
__device__ float g_om [12400*NB*OMC];
__device__ float g_feat[12400*NB*CH];
__device__ float g_wT2[3*192*112];
__device__ float g_a[7*NB];
__device__ float g_y[3*NB*CH];
__device__ float g_z[3*NB*1024];
__device__ float g_cmean[7*NB*CH];
__device__ float g_gmu[7*NB*16];
__device__ float g_ginv[7*NB*16];

__device__ __forceinline__ const float* pick_x(int s){
    return s==0 ? g_x0 : (s==1 ? g_x1 : g_x2);
}
__device__ __forceinline__ float* pick_xm(int s){
    return s==0 ? g_x0 : (s==1 ? g_x1 : g_x2);
}

// ---------------- NCHW -> NHWC tiled transpose ----------------
__global__ void k_tr2(const float* __restrict__ in, int sel, int HW){
    __shared__ float tile[32][33];
    float* out = pick_xm(sel);
    int n  = blockIdx.z;
    int hw0 = blockIdx.x*32;
    int c0  = blockIdx.y*32;
    int tx = threadIdx.x, ty = threadIdx.y;
    #pragma unroll
    for (int q = 0; q < 4; ++q){
        int c = c0 + ty + q*8;
        int hw = hw0 + tx;
        float v = (hw < HW) ? in[((size_t)n*CH + c)*HW + hw] : 0.f;
        tile[ty + q*8][tx] = v;
    }
    __syncthreads();
    #pragma unroll
    for (int q = 0; q < 4; ++q){
        int hw = hw0 + ty + q*8;
        int c  = c0 + tx;
        if (hw < HW) out[((size_t)n*HW + hw)*CH + c] = tile[tx][ty + q*8];
    }
}

// weight transform: [dy][ic*3+dx][slot(4g x 28)]
__global__ void k_wt2(const float* __restrict__ ow){
    int i = blockIdx.x*blockDim.x + threadIdx.x;
    if (i >= 3*192*112) return;
    int slot = i % 112;
    int r    = (i / 112) % 192;
    int dy   = i / (112*192);
    int ic = r/3, dx = r%3;
    int g = slot/28, jj = slot%28;
    float v = 0.f;
    if (jj < 27) v = ow[(g*27+jj)*576 + ic*9 + dy*3 + dx];
    g_wT2[i] = v;
}

// ---------------- shared-source depthwise conv (single source per launch) ----
__global__ void __launch_bounds__(256, 3)
k_dwS(int src,
      const float* __restrict__ wm, const float* __restrict__ sm_, const float* __restrict__ bm_,
      const float* __restrict__ wh, const float* __restrict__ sh_, const float* __restrict__ bh_,
      const float* __restrict__ wl, const float* __restrict__ sl_, const float* __restrict__ bl_){
    __shared__ unsigned long long wsm[3][64][9][2];
    __shared__ float4 ssm[3][64], bsm[3][64];
    int n = blockIdx.z;
    int H = (src==0) ? 80 : (src==1 ? 40 : 20);
    int W = H, HW = H*W;
    int nsets = SRC_NSETS[src];
    int t = threadIdx.x;

    for (int s = 0; s < nsets; ++s){
        int sel = SRC_WSEL[src][s];
        const float* wgt = sel==0 ? wm : (sel==1 ? wh : wl);
        const float* sc  = sel==0 ? sm_ : (sel==1 ? sh_ : sl_);
        const float* bi  = sel==0 ? bm_ : (sel==1 ? bh_ : bl_);
        for (int i = t; i < 64*9; i += 256){
            int q = i/9, tp = i%9;
            float a0 = wgt[(q*4+0)*9 + tp], a1 = wgt[(q*4+1)*9 + tp];
            float a2 = wgt[(q*4+2)*9 + tp], a3 = wgt[(q*4+3)*9 + tp];
            PACKF2(wsm[s][q][tp][0], a0, a1);
            PACKF2(wsm[s][q][tp][1], a2, a3);
        }
        for (int i = t; i < 64; i += 256){
            ssm[s][i] = *(const float4*)(sc + i*4);
            bsm[s][i] = *(const float4*)(bi + i*4);
        }
    }
    __syncthreads();

    const float* x = pick_x(src);
    int q  = t & 63;
    int c0 = q*4;
    int lane = t >> 6;
    for (int hw = blockIdx.x*4 + lane; hw < HW; hw += gridDim.x*4){
        int w = hw % W, h = hw / W;
        ulonglong2 tap[9];
        #pragma unroll
        for (int dy = 0; dy < 3; ++dy){
            int yy = h + dy - 1;
            #pragma unroll
            for (int dx = 0; dx < 3; ++dx){
                int xx = w + dx - 1;
                int tp = dy*3 + dx;
                if (yy >= 0 && yy < H && xx >= 0 && xx < W)
                    tap[tp] = *(const ulonglong2*)(x + ((size_t)(n*H+yy)*W + xx)*CH + c0);
                else { tap[tp].x = 0ull; tap[tp].y = 0ull; }
            }
        }
        #pragma unroll 3
        for (int s = 0; s < 3; ++s){
            if (s >= nsets) break;
            unsigned long long a01 = 0ull, a23 = 0ull;
            #pragma unroll
            for (int tp = 0; tp < 9; ++tp){
                FMAF2(a01, tap[tp].x, wsm[s][q][tp][0], a01);
                FMAF2(a23, tap[tp].y, wsm[s][q][tp][1], a23);
            }
            float ax, ay, az, aw;
            UNPACKF2(ax, ay, a01);
            UNPACKF2(az, aw, a23);
            float4 s4 = ssm[s][q], b4 = bsm[s][q];
            float4 o;
            float t0 = ax*s4.x + b4.x; o.x = t0/(1.f+expf(-t0));
            float t1 = ay*s4.y + b4.y; o.y = t1/(1.f+expf(-t1));
            float t2 = az*s4.z + b4.z; o.z = t2/(1.f+expf(-t2));
            float t3 = aw*s4.w + b4.w; o.w = t3/(1.f+expf(-t3));
            float* dst = g_dwb + (size_t)SRC_DST[src][s]*NB*CH;
            *(float4*)(dst + ((size_t)n*HW + hw)*CH + c0) = o;
        }
    }
}

// ---------------- grouped conv 256->108, per-group blocks, FFMA2 ----
template<int STRIDE, int PXO, int TPX, int PXQ, int THREADS>
__global__ void __launch_bounds__(THREADS)
k_om3(int H, int W, int Ho, int Wo, const float* __restrict__ ob, int bA, int bB){
    constexpr int PW  = (PXO-1)*STRIDE + 3;
    constexpr int PWP = (PW + 3) & ~3;
    constexpr int WIN = 3 + (TPX-1)*STRIDE;
    static_assert((TPX*STRIDE) % 4 == 0, "window alignment");
    static_assert(WIN <= 8, "window fits two float4");
    extern __shared__ float sh[];
    float* patch = sh;
    float* wsl   = sh + 64*PWP;

    int br   = blockIdx.z == 0 ? bA : bB;
    const float* src = g_dwb + (size_t)DWPFX[br]*NB*CH;
    float* dst       = g_om  + (size_t)OMPFX[br]*NB*OMC;

    int nt   = (Wo + PXO - 1)/PXO;
    int g    = blockIdx.y;
    int b    = blockIdx.x;
    int tile = b % nt;
    int ho   = (b/nt) % Ho;
    int n    = b/(nt*Ho);
    int wo0  = tile*PXO;
    int hsrc = ho*STRIDE;
    int wsrc0= wo0*STRIDE;
    int cb   = g*64;

    int t   = threadIdx.x;
    int pxq = t % PXQ;
    int li  = t / PXQ;
    bool act = li < 7;
    int xb  = pxq*TPX*STRIDE;

    unsigned long long a01[TPX], a23[TPX];
    #pragma unroll
    for (int p = 0; p < TPX; ++p){ a01[p] = 0ull; a23[p] = 0ull; }

    const float* wsrc_base = g_wT2 + g*28;
    for (int dy = 0; dy < 3; ++dy){
        __syncthreads();
        int gy = hsrc + dy - 1;
        for (int i = t; i < PW*64; i += THREADS){
            int c = i & 63, xx = i >> 6;
            int gx = wsrc0 + xx - 1;
            float v = 0.f;
            if (gy >= 0 && gy < H && gx >= 0 && gx < W)
                v = src[((size_t)(n*H+gy)*W + gx)*CH + cb + c];
            patch[c*PWP + xx] = v;
        }
        {
            const float* ws = wsrc_base + dy*192*112;
            for (int i = t; i < 192*7; i += THREADS){
                int row = i/7, col = (i%7)*4;
                *(float4*)(wsl + row*28 + col) = *(const float4*)(ws + row*112 + col);
            }
        }
        __syncthreads();
        if (act){
            #pragma unroll 4
            for (int ic = 0; ic < 64; ++ic){
                const float* pr = patch + ic*PWP + xb;
                float f[8];
                *(float4*)(f)   = *(const float4*)(pr);
                *(float4*)(f+4) = *(const float4*)(pr+4);
                unsigned long long sv[WIN];
                #pragma unroll
                for (int k2 = 0; k2 < WIN; ++k2) PACKF2(sv[k2], f[k2], f[k2]);
                const float* wb = wsl + (ic*3)*28 + li*4;
                #pragma unroll
                for (int dx = 0; dx < 3; ++dx){
                    ulonglong2 wv = *(const ulonglong2*)(wb + dx*28);
                    #pragma unroll
                    for (int p = 0; p < TPX; ++p){
                        FMAF2(a01[p], sv[dx + p*STRIDE], wv.x, a01[p]);
                        FMAF2(a23[p], sv[dx + p*STRIDE], wv.y, a23[p]);
                    }
                }
            }
        }
    }
    if (act){
        float bj[4];
        #pragma unroll
        for (int j = 0; j < 4; ++j){
            int jj = li*4 + j;
            bj[j] = (jj < 27) ? ob[g*27 + jj] : 0.f;
        }
        #pragma unroll
        for (int p = 0; p < TPX; ++p){
            int wo = wo0 + pxq*TPX + p;
            if (wo < Wo){
                size_t base = ((size_t)(n*Ho+ho)*Wo + wo)*OMC + g*27 + li*4;
                float av[4];
                UNPACKF2(av[0], av[1], a01[p]);
                UNPACKF2(av[2], av[3], a23[p]);
                #pragma unroll
                for (int j = 0; j < 4; ++j)
                    if (li*4 + j < 27) dst[base + j] = av[j] + bj[j];
            }
        }
    }
}

// ---------------- batched DCNv3 sampler: 4x4 2D pixel tiles, 4 px/thread ----
__global__ void k_sampB(int bx0){
    __shared__ float som[16][OMC];
    __shared__ float smk[16][36];
    __shared__ float sw[16][4][9][4];
    __shared__ int   soff[16][4][9][4];
    __shared__ int   sp_hw[16];
    int bx = blockIdx.x + bx0;
    int b = 0;
    #pragma unroll
    for (int i = 1; i < 7; ++i) if (bx >= SAMP_PFX16[i]) b = i;
    int n = blockIdx.y;
    int Ho = BR_HO[b], Wo = Ho, HW = Ho*Wo;
    int H  = BR_HS[b], W = H;
    int stride = BR_STRIDE[b];
    int use_softmax = BR_SOFT[b];
    const float* x = pick_x(BR_SRC[b]);
    const float* omp = g_om + ((size_t)OMPFX[b]*NB + (size_t)n*HW)*OMC;
    int t = threadIdx.x;

    // 4x4 tile mapping
    int tile = bx - SAMP_PFX16[b];
    int tw = Wo >> 2;
    int h0 = (tile/tw)*4, w0 = (tile%tw)*4;
    if (t < 16) sp_hw[t] = (h0 + (t>>2))*Wo + (w0 + (t&3));
    __syncthreads();

    for (int i = t; i < 16*OMC; i += 256)
        som[i/OMC][i%OMC] = omp[(size_t)sp_hw[i/OMC]*OMC + i%OMC];
    __syncthreads();

    if (use_softmax){
        if (t < 64){
            int pp = t >> 2, gg = t & 3;
            float mx = -1e30f;
            #pragma unroll
            for (int k = 0; k < 9; ++k) mx = fmaxf(mx, som[pp][72 + gg*9 + k]);
            float e[9], s = 0.f;
            #pragma unroll
            for (int k = 0; k < 9; ++k){ e[k] = expf(som[pp][72 + gg*9 + k] - mx); s += e[k]; }
            float inv = 1.f/s;
            #pragma unroll
            for (int k = 0; k < 9; ++k) smk[pp][gg*9 + k] = e[k]*inv;
        }
    } else {
        for (int i = t; i < 16*36; i += 256)
            smk[i/36][i%36] = 1.f/(1.f + expf(-som[i/36][72 + i%36]));
    }
    __syncthreads();

    for (int i = t; i < 16*36; i += 256){
        int pix = i / 36, r = i % 36, gg = r / 9, k = r % 9;
        int hw = sp_hw[pix];
        int wo = hw % Wo, ho = hw / Wo;
        float py = (float)(ho*stride) + (float)(k/3 - 1) + som[pix][gg*18 + k*2];
        float px = (float)(wo*stride) + (float)(k%3 - 1) + som[pix][gg*18 + k*2 + 1];
        float m  = smk[pix][gg*9 + k];
        float fy = floorf(py), fx = floorf(px);
        float wy = py - fy, wx = px - fx;
        int iy = (int)fy, ix = (int)fx;
        #pragma unroll
        for (int d0 = 0; d0 < 2; ++d0){
            int yy = iy + d0;
            float wgy = d0 ? wy : (1.f - wy);
            #pragma unroll
            for (int d1 = 0; d1 < 2; ++d1){
                int xx = ix + d1;
                bool valid = (yy >= 0) & (yy < H) & (xx >= 0) & (xx < W);
                int yc = min(max(yy, 0), H-1);
                int xc = min(max(xx, 0), W-1);
                sw[pix][gg][k][d0*2+d1]   = valid ? wgy*(d1 ? wx : (1.f - wx))*m : 0.f;
                soff[pix][gg][k][d0*2+d1] = ((n*H + yc)*W + xc)*CH;
            }
        }
    }
    __syncthreads();

    int lane = t >> 6, q = t & 63, c0 = q*4, g = q >> 4;
    const float* xc = x + c0;
    #pragma unroll
    for (int pi = 0; pi < 4; ++pi){
        int pix = lane + pi*4;
        unsigned long long acc01 = 0ull, acc23 = 0ull;
        #pragma unroll
        for (int k = 0; k < 9; ++k){
            float4 wv = *(const float4*)&sw[pix][g][k][0];
            int4  ov = *(const int4*)&soff[pix][g][k][0];
            unsigned long long w0v, w1v, w2v, w3v;
            PACKF2(w0v, wv.x, wv.x); PACKF2(w1v, wv.y, wv.y);
            PACKF2(w2v, wv.z, wv.z); PACKF2(w3v, wv.w, wv.w);
            ulonglong2 v0 = *(const ulonglong2*)(xc + ov.x);
            ulonglong2 v1 = *(const ulonglong2*)(xc + ov.y);
            ulonglong2 v2 = *(const ulonglong2*)(xc + ov.z);
            ulonglong2 v3 = *(const ulonglong2*)(xc + ov.w);
            FMAF2(acc01, v0.x, w0v, acc01); FMAF2(acc23, v0.y, w0v, acc23);
            FMAF2(acc01, v1.x, w1v, acc01); FMAF2(acc23, v1.y, w1v, acc23);
            FMAF2(acc01, v2.x, w2v, acc01); FMAF2(acc23, v2.y, w2v, acc23);
            FMAF2(acc01, v3.x, w3v, acc01); FMAF2(acc23, v3.y, w3v, acc23);
        }
        float4 acc;
        UNPACKF2(acc.x, acc.y, acc01);
        UNPACKF2(acc.z, acc.w, acc23);
        *(float4*)(g_feat + ((size_t)OMPFX[b]*NB + (size_t)n*HW + sp_hw[pix])*CH + c0) = acc;
    }
}

// ---------------- batched stats (branch-offset subset launch) ----------------
__global__ void k_statsB(int boff){
    __shared__ float wy[80], wx[80];
    __shared__ float r1[256], r2[256];
    __shared__ float4 rw[256];
    int b = (blockIdx.x >> 4) + boff, g = blockIdx.x & 15, n = blockIdx.y;
    int Hs = BR_HO[b], Ws = Hs, HW = Hs*Ws;
    int uph = BR_UPH[b];
    float normw = uph ? 1.f/((float)uph*(float)uph) : 1.f/(float)HW;
    int t = threadIdx.x;
    if (t == 0){
        if (uph){
            for (int i = 0; i < Hs; ++i){ wy[i] = 0.f; wx[i] = 0.f; }
            float ry = (float)(Hs-1)/(float)(uph-1);
            for (int j = 0; j < uph; ++j){
                float c = j*ry; int i0 = (int)floorf(c); float f = c - (float)i0;
                wy[i0] += 1.f - f;
                if (i0 + 1 < Hs) wy[i0+1] += f;
            }
            for (int i = 0; i < Hs; ++i) wx[i] = wy[i];
        } else {
            for (int i = 0; i < Hs; ++i){ wy[i] = 1.f; wx[i] = 1.f; }
        }
    }
    __syncthreads();

    const float* fb = g_feat + ((size_t)OMPFX[b]*NB + (size_t)n*HW)*CH;
    int q  = t & 3;
    int c0 = g*16 + q*4;
    float4 s4 = make_float4(0,0,0,0), w4 = make_float4(0,0,0,0);
    float ss = 0.f;
    int hw0 = t >> 2;
    int h = hw0 / Ws, w = hw0 % Ws;
    for (int hw = hw0; hw < HW; hw += 64){
        float4 v = *(const float4*)(fb + (size_t)hw*CH + c0);
        s4.x += v.x; s4.y += v.y; s4.z += v.z; s4.w += v.w;
        ss += v.x*v.x + v.y*v.y + v.z*v.z + v.w*v.w;
        float ww = wy[h]*wx[w];
        w4.x += v.x*ww; w4.y += v.y*ww; w4.z += v.z*ww; w4.w += v.w*ww;
        w += 64; while (w >= Ws){ w -= Ws; ++h; }
    }
    r1[t] = s4.x + s4.y + s4.z + s4.w;
    r2[t] = ss;
    rw[t] = w4;
    __syncthreads();
    for (int o = 128; o >= 4; o >>= 1){
        if (t < o){
            r1[t] += r1[t+o]; r2[t] += r2[t+o];
            rw[t].x += rw[t+o].x; rw[t].y += rw[t+o].y;
            rw[t].z += rw[t+o].z; rw[t].w += rw[t+o].w;
        }
        __syncthreads();
    }
    if (t == 0){
        float s  = r1[0] + r1[1] + r1[2] + r1[3];
        float sq = r2[0] + r2[1] + r2[2] + r2[3];
        float cnt = (float)HW*16.f;
        float mu  = s/cnt;
        float var = sq/cnt - mu*mu;
        g_gmu [(b*NB+n)*16 + g] = mu;
        g_ginv[(b*NB+n)*16 + g] = rsqrtf(var + 1e-5f);
    }
    if (t < 4){
        float4 wv = rw[t];
        int c = (b*NB+n)*CH + g*16 + t*4;
        g_cmean[c]   = wv.x*normw; g_cmean[c+1] = wv.y*normw;
        g_cmean[c+2] = wv.z*normw; g_cmean[c+3] = wv.w*normw;
    }
}

// ---------------- attn scalars + pooled means ----------------
__device__ __constant__ int LVL_NBR[3] = {2,3,2};
__device__ __constant__ int LVL_BRS[3][3] = {{0,1,-1},{2,3,4},{5,6,-1}};

__global__ void k_attnB(const float* __restrict__ saw, const float* __restrict__ sab,
                        const float* __restrict__ gm, const float* __restrict__ bm,
                        const float* __restrict__ gh, const float* __restrict__ bh,
                        const float* __restrict__ gl, const float* __restrict__ bl){
    __shared__ float red[256];
    __shared__ float sa;
    int lvl = blockIdx.x, n = blockIdx.y, t = threadIdx.x;
    int g = t >> 4;
    int nbr = LVL_NBR[lvl];
    float invl = 1.f/(float)nbr;
    float y = 0.f;
    for (int i = 0; i < nbr; ++i){
        int b = LVL_BRS[lvl][i];
        int gs = BR_GNSEL[b];
        const float* gam = gs==0 ? gm : (gs==1 ? gh : gl);
        const float* bet = gs==0 ? bm : (gs==1 ? bh : bl);
        float m = (g_cmean[(b*NB+n)*CH + t] - g_gmu[(b*NB+n)*16 + g])
                  * g_ginv[(b*NB+n)*16 + g] * gam[t] + bet[t];
        red[t] = m*saw[t];
        __syncthreads();
        for (int o = 128; o > 0; o >>= 1){
            if (t < o) red[t] += red[t+o];
            __syncthreads();
        }
        if (t == 0){
            float a = red[0] + sab[0];
            a = fmaxf(a, 0.f);
            a = fminf(fmaxf((a + 3.f)/6.f, 0.f), 1.f);
            sa = a; g_a[b*NB + n] = a;
        }
        __syncthreads();
        y += sa*m*invl;
        __syncthreads();
    }
    g_y[(lvl*NB + n)*CH + t] = y;
}

// ---------------- fc (all levels) ----------------
__global__ void k_fcB(const float* __restrict__ w1, const float* __restrict__ b1,
                      const float* __restrict__ w2, const float* __restrict__ b2){
    __shared__ float h[4][64];
    int lvl = blockIdx.x;
    int t = threadIdx.x;
    int n = t >> 6, j = t & 63;
    float s = b1[j];
    const float* wr = w1 + j*CH;
    const float* yv = g_y + (lvl*NB + n)*CH;
    for (int c = 0; c < CH; ++c) s += yv[c]*wr[c];
    h[n][j] = fmaxf(s, 0.f);
    __syncthreads();
    for (int og = t; og < NB*1024; og += 256){
        int nn = og >> 10, o = og & 1023;
        float s2 = b2[o];
        const float* w2r = w2 + o*64;
        #pragma unroll 16
        for (int j2 = 0; j2 < 64; ++j2) s2 += h[nn][j2]*w2r[j2];
        float z = fminf(fmaxf(s2 + 3.f, 0.f), 6.f)*(1.f/6.f);
        int qd = o >> 8;
        float v;
        if      (qd == 0) v = (z - 0.5f)*2.f + 1.f;
        else if (qd == 2) v = (z - 0.5f)*2.f;
        else              v = z - 0.5f;
        g_z[(lvl*NB + nn)*1024 + o] = v;
    }
}

// ---------------- fused: GN+attn+upsample sum -> dyrelu -> NCHW out ----------
__device__ __forceinline__ void gn_acc(float4& o, float4 raw, int b, int n, int g,
                                       float4 g4, float4 b4){
    float mu = g_gmu[(b*NB+n)*16 + g], inv = g_ginv[(b*NB+n)*16 + g], a = g_a[b*NB + n];
    o.x += a*((raw.x - mu)*inv*g4.x + b4.x);
    o.y += a*((raw.y - mu)*inv*g4.y + b4.y);
    o.z += a*((raw.z - mu)*inv*g4.z + b4.z);
    o.w += a*((raw.w - mu)*inv*g4.w + b4.w);
}
__device__ __forceinline__ float4 feat_rd(int b, int n, int HW, int hw, int c0){
    return *(const float4*)(g_feat + ((size_t)OMPFX[b]*NB + (size_t)n*HW + hw)*CH + c0);
}
__device__ __forceinline__ float4 feat_up(int b, int n, int Hs, int Ho, int h, int w, int c0){
    float r = (float)(Hs-1)/(float)(Ho-1);
    float cy = h*r, cx = w*r;
    int y0 = (int)floorf(cy), x0 = (int)floorf(cx);
    int y1 = min(y0+1, Hs-1), x1 = min(x0+1, Hs-1);
    float wyf = cy - (float)y0, wxf = cx - (float)x0;
    const float* fb = g_feat + ((size_t)OMPFX[b]*NB + (size_t)n*Hs*Hs)*CH + c0;
    float4 v00 = *(const float4*)(fb + (size_t)(y0*Hs + x0)*CH);
    float4 v01 = *(const float4*)(fb + (size_t)(y0*Hs + x1)*CH);
    float4 v10 = *(const float4*)(fb + (size_t)(y1*Hs + x0)*CH);
    float4 v11 = *(const float4*)(fb + (size_t)(y1*Hs + x1)*CH);
    float a0 = (1.f-wyf)*(1.f-wxf), a1 = (1.f-wyf)*wxf, a2 = wyf*(1.f-wxf), a3 = wyf*wxf;
    float4 o;
    o.x = v00.x*a0 + v01.x*a1 + v10.x*a2 + v11.x*a3;
    o.y = v00.y*a0 + v01.y*a1 + v10.y*a2 + v11.y*a3;
    o.z = v00.z*a0 + v01.z*a1 + v10.z*a2 + v11.z*a3;
    o.w = v00.w*a0 + v01.w*a1 + v10.w*a2 + v11.w*a3;
    return o;
}

template<int LVL>
__global__ void k_outL(float* __restrict__ out,
                       const float* __restrict__ gm, const float* __restrict__ bm,
                       const float* __restrict__ gh, const float* __restrict__ bh,
                       const float* __restrict__ gl, const float* __restrict__ bl){
    constexpr int HoL = (LVL==0) ? 80 : (LVL==1 ? 40 : 20);
    constexpr int HWL = HoL*HoL;
    constexpr float INVL = (LVL==1) ? (1.f/3.f) : 0.5f;
    __shared__ float tile[32][257];
    int n   = blockIdx.y;
    int hw0 = blockIdx.x*32;
    int tx = threadIdx.x, ty = threadIdx.y;
    int tid = ty*32 + tx;

    #pragma unroll
    for (int k = 0; k < 8; ++k){
        int e = k*256 + tid;
        int hwl = e >> 6;
        int q   = e & 63;
        int hw  = hw0 + hwl;
        if (hw < HWL){
            int c0 = q*4, g = q >> 2;
            int w = hw % HoL, h = hw / HoL;
            float4 o = make_float4(0,0,0,0);
            float4 g4, b4;
            if (LVL == 0){
                g4 = *(const float4*)(gm + c0); b4 = *(const float4*)(bm + c0);
                gn_acc(o, feat_rd(0, n, 6400, hw, c0), 0, n, g, g4, b4);
                g4 = *(const float4*)(gh + c0); b4 = *(const float4*)(bh + c0);
                gn_acc(o, feat_up(1, n, 40, 80, h, w, c0), 1, n, g, g4, b4);
            } else if (LVL == 1){
                g4 = *(const float4*)(gm + c0); b4 = *(const float4*)(bm + c0);
                gn_acc(o, feat_rd(2, n, 1600, hw, c0), 2, n, g, g4, b4);
                g4 = *(const float4*)(gl + c0); b4 = *(const float4*)(bl + c0);
                gn_acc(o, feat_rd(3, n, 1600, hw, c0), 3, n, g, g4, b4);
                g4 = *(const float4*)(gh + c0); b4 = *(const float4*)(bh + c0);
                gn_acc(o, feat_up(4, n, 20, 40, h, w, c0), 4, n, g, g4, b4);
            } else {
                g4 = *(const float4*)(gm + c0); b4 = *(const float4*)(bm + c0);
                gn_acc(o, feat_rd(5, n, 400, hw, c0), 5, n, g, g4, b4);
                g4 = *(const float4*)(gl + c0); b4 = *(const float4*)(bl + c0);
                gn_acc(o, feat_rd(6, n, 400, hw, c0), 6, n, g, g4, b4);
            }
            tile[hwl][c0]   = o.x;
            tile[hwl][c0+1] = o.y;
            tile[hwl][c0+2] = o.z;
            tile[hwl][c0+3] = o.w;
        }
    }
    __syncthreads();

    int hw = hw0 + tx;
    if (hw < HWL){
        const float* zb = g_z + (LVL*NB + n)*1024;
        #pragma unroll
        for (int k = 0; k < 32; ++k){
            int c = ty + k*8;
            float f = tile[tx][c]*INVL;
            float a1 = zb[c], b1 = zb[256 + c];
            float a2 = zb[512 + c], b2 = zb[768 + c];
            out[((size_t)n*CH + c)*HWL + hw] = fmaxf(f*a1 + b1, f*a2 + b2);
        }
    }
}

// ---------------- host: branch-pipelined fork/join (graph-capturable) ----------
extern "C" void kernel_launch(void* const* d_in, const int* in_sizes, int n_in,
                              void* d_out, int out_size){
    const float* x0     = (const float*)d_in[0];
    const float* x1     = (const float*)d_in[1];
    const float* x2     = (const float*)d_in[2];
    const float* dw_w_h = (const float*)d_in[3];
    const float* dw_s_h = (const float*)d_in[4];
    const float* dw_b_h = (const float*)d_in[5];
    const float* dw_w_m = (const float*)d_in[6];
    const float* dw_s_m = (const float*)d_in[7];
    const float* dw_b_m = (const float*)d_in[8];
    const float* dw_w_l = (const float*)d_in[9];
    const float* dw_s_l = (const float*)d_in[10];
    const float* dw_b_l = (const float*)d_in[11];
    const float* off_w  = (const float*)d_in[12];
    const float* off_b  = (const float*)d_in[13];
    const float* gn_g_h = (const float*)d_in[14];
    const float* gn_b_h = (const float*)d_in[15];
    const float* gn_g_m = (const float*)d_in[16];
    const float* gn_b_m = (const float*)d_in[17];
    const float* gn_g_l = (const float*)d_in[18];
    const float* gn_b_l = (const float*)d_in[19];
    const float* sa_w   = (const float*)d_in[20];
    const float* sa_b   = (const float*)d_in[21];
    const float* fc1_w  = (const float*)d_in[22];
    const float* fc1_b  = (const float*)d_in[23];
    const float* fc2_w  = (const float*)d_in[24];
    const float* fc2_b  = (const float*)d_in[25];
    float* out = (float*)d_out;

    static cudaStream_t s1, s2, s3;
    static cudaEvent_t eFork, eWt, eDw0, eDw1, eO3, eO20, eStR, eFc, eL1, eL2;
    static bool inited = false;
    if (!inited){
        cudaStreamCreateWithFlags(&s1, cudaStreamNonBlocking);
        cudaStreamCreateWithFlags(&s2, cudaStreamNonBlocking);
        cudaStreamCreateWithFlags(&s3, cudaStreamNonBlocking);
        cudaEventCreateWithFlags(&eFork, cudaEventDisableTiming);
        cudaEventCreateWithFlags(&eWt,  cudaEventDisableTiming);
        cudaEventCreateWithFlags(&eDw0, cudaEventDisableTiming);
        cudaEventCreateWithFlags(&eDw1, cudaEventDisableTiming);
        cudaEventCreateWithFlags(&eO3,  cudaEventDisableTiming);
        cudaEventCreateWithFlags(&eO20, cudaEventDisableTiming);
        cudaEventCreateWithFlags(&eStR, cudaEventDisableTiming);
        cudaEventCreateWithFlags(&eFc,  cudaEventDisableTiming);
        cudaEventCreateWithFlags(&eL1,  cudaEventDisableTiming);
        cudaEventCreateWithFlags(&eL2,  cudaEventDisableTiming);
        inited = true;
    }
    cudaStream_t s0 = 0;

    // fork
    cudaEventRecord(eFork, s0);
    cudaStreamWaitEvent(s1, eFork, 0);
    cudaStreamWaitEvent(s2, eFork, 0);
    cudaStreamWaitEvent(s3, eFork, 0);

    // stage 1: per-source chains (dwS(src0) is global launch #3 for ncu)
    k_tr2<<<dim3(200, 8, NB), dim3(32,8), 0, s0>>>(x0, 0, 6400);
    k_tr2<<<dim3(50,  8, NB), dim3(32,8), 0, s1>>>(x1, 1, 1600);
    k_tr2<<<dim3(13,  8, NB), dim3(32,8), 0, s2>>>(x2, 2,  400);
    k_dwS<<<dim3(200, 1, NB), 256, 0, s0>>>(0, dw_w_m, dw_s_m, dw_b_m,
                                               dw_w_h, dw_s_h, dw_b_h,
                                               dw_w_l, dw_s_l, dw_b_l);
    cudaEventRecord(eDw0, s0);
    k_wt2<<<(3*192*112 + 255)/256, 256, 0, s3>>>(off_w);
    cudaEventRecord(eWt, s3);
    k_dwS<<<dim3(50, 1, NB), 256, 0, s1>>>(1, dw_w_m, dw_s_m, dw_b_m,
                                              dw_w_h, dw_s_h, dw_b_h,
                                              dw_w_l, dw_s_l, dw_b_l);
    cudaEventRecord(eDw1, s1);
    k_dwS<<<dim3(13, 1, NB), 256, 0, s2>>>(2, dw_w_m, dw_s_m, dw_b_m,
                                              dw_w_h, dw_s_h, dw_b_h,
                                              dw_w_l, dw_s_l, dw_b_l);

    // stage 2: om per class, each as early as its deps allow
    cudaStreamWaitEvent(s0, eWt, 0);
    cudaStreamWaitEvent(s1, eWt, 0);
    cudaStreamWaitEvent(s2, eWt, 0);
    cudaStreamWaitEvent(s3, eDw0, 0);
    const int SM80 = (64*84 + 192*28)*4;
    const int SM40 = (64*44 + 192*28)*4;
    const int SM40s2 = (64*84 + 192*28)*4;
    const int SM20 = (64*24 + 192*28)*4;
    k_om3<1,80,4,20,160><<<dim3(1*80*NB, 4, 1), 160, SM80, s0>>>(80, 80, 80, 80, off_b, 0, 0);
    k_om3<1,40,4,10,80><<<dim3(1*40*NB, 4, 2), 80, SM40, s1>>>(40, 40, 40, 40, off_b, 1, 2);
    k_om3<2,40,2,20,160><<<dim3(1*40*NB, 4, 1), 160, SM40s2, s3>>>(80, 80, 40, 40, off_b, 3, 3);
    cudaStreamWaitEvent(s3, eDw1, 0);
    k_om3<2,20,2,10,80><<<dim3(1*20*NB, 4, 1), 80, SM40, s3>>>(40, 40, 20, 20, off_b, 6, 6);
    cudaEventRecord(eO3, s3);
    cudaStreamWaitEvent(s2, eDw1, 0);
    k_om3<1,20,4,5,64><<<dim3(1*20*NB, 4, 2), 64, SM20, s2>>>(20, 20, 20, 20, off_b, 4, 5);
    cudaEventRecord(eO20, s2);

    // stage 3a: sampler+stats for b0 on s0 (critical path)
    k_sampB <<<dim3(400, NB),  256, 0, s0>>>(0);
    k_statsB<<<dim3(16, NB),   256, 0, s0>>>(0);

    // stage 3b: sampler+stats for b1..b6 on s1 (375 blocks = 400..774)
    cudaStreamWaitEvent(s1, eO3, 0);
    cudaStreamWaitEvent(s1, eO20, 0);
    k_sampB <<<dim3(375, NB),  256, 0, s1>>>(400);
    k_statsB<<<dim3(6*16, NB), 256, 0, s1>>>(1);
    cudaEventRecord(eStR, s1);

    // stage 3c: attn + fc on s0
    cudaStreamWaitEvent(s0, eStR, 0);
    k_attnB <<<dim3(3, NB), 256, 0, s0>>>(sa_w, sa_b, gn_g_m, gn_b_m, gn_g_h, gn_b_h, gn_g_l, gn_b_l);
    k_fcB   <<<3,           256, 0, s0>>>(fc1_w, fc1_b, fc2_w, fc2_b);
    cudaEventRecord(eFc, s0);
    cudaStreamWaitEvent(s1, eFc, 0);
    cudaStreamWaitEvent(s2, eFc, 0);

    // stage 4: fused outputs concurrent
    k_outL<0><<<dim3(200, NB), dim3(32,8), 0, s0>>>(out,
        gn_g_m, gn_b_m, gn_g_h, gn_b_h, gn_g_l, gn_b_l);
    k_outL<1><<<dim3(50, NB),  dim3(32,8), 0, s1>>>(out + (size_t)NB*CH*6400,
        gn_g_m, gn_b_m, gn_g_h, gn_b_h, gn_g_l, gn_b_l);
    k_outL<2><<<dim3(13, NB),  dim3(32,8), 0, s2>>>(out + (size_t)NB*CH*8000,
        gn_g_m, gn_b_m, gn_g_h, gn_b_h, gn_g_l, gn_b_l);
    cudaEventRecord(eL1, s1);
    cudaEventRecord(eL2, s2);
    cudaStreamWaitEvent(s0, eL1, 0);
    cudaStreamWaitEvent(s0, eL2, 0);
}

// round 16
// speedup vs baseline: 1.2714x; 1.0003x over previous
#include <cuda_runtime.h>
#include <math.h>

#define NB   4
#define CH   256
#define OMC  108

// ---- packed f32x2 ops ----
#define PACKF2(out, lo, hi) \
    asm("mov.b64 %0, {%1, %2};" : "=l"(out) : "f"(lo), "f"(hi))
#define UNPACKF2(lo, hi, in) \
    asm("mov.b64 {%0, %1}, %2;" : "=f"(lo), "=f"(hi) : "l"(in))
#define FMAF2(d, a, b, c) \
    asm("fma.rn.f32x2 %0, %1, %2, %3;" : "=l"(d) : "l"(a), "l"(b), "l"(c))

// ---- branch tables (7 branches) ----
__device__ __constant__ int BR_SRC[7]    = {0,1,1,0,2,2,1};
__device__ __constant__ int BR_HS[7]     = {80,40,40,80,20,20,40};
__device__ __constant__ int BR_STRIDE[7] = {1,1,1,2,1,1,2};
__device__ __constant__ int BR_HO[7]     = {80,40,40,40,20,20,20};
__device__ __constant__ int BR_SOFT[7]   = {0,1,0,1,1,0,1};
__device__ __constant__ int BR_UPH[7]    = {0,80,0,0,40,0,0};
__device__ __constant__ int BR_GNSEL[7]  = {0,1,0,2,1,0,2};
__device__ __constant__ int DWPFX[7]     = {0,6400,8000,9600,16000,16400,16800};
__device__ __constant__ int OMPFX[7]     = {0,6400,8000,9600,11200,11600,12000};
__device__ __constant__ int SAMP_PFX16[7] = {0,400,500,600,700,725,750};

__device__ __constant__ int SRC_NSETS[3]  = {2,3,2};
__device__ __constant__ int SRC_WSEL[3][3]= {{0,2,0},{1,0,2},{1,0,0}};
__device__ __constant__ int SRC_DST[3][3] = {{0,9600,0},{6400,8000,16800},{16000,16400,0}};

// ---------------- scratch ----------------
__device__ float g_x0[NB*80*80*CH];
__device__ float g_x1[NB*40*40*CH];
__device__ float g_x2[NB*20*20*CH];
__device__ float g_dwb[18400*NB*CH];
__device__ float g_om [12400*NB*OMC];
__device__ float g_feat[12400*NB*CH];
__device__ float g_wT2[3*192*112];
__device__ float g_a[7*NB];
__device__ float g_y[3*NB*CH];
__device__ float g_z[3*NB*1024];
__device__ float g_cmean[7*NB*CH];
__device__ float g_gmu[7*NB*16];
__device__ float g_ginv[7*NB*16];

__device__ __forceinline__ const float* pick_x(int s){
    return s==0 ? g_x0 : (s==1 ? g_x1 : g_x2);
}
__device__ __forceinline__ float* pick_xm(int s){
    return s==0 ? g_x0 : (s==1 ? g_x1 : g_x2);
}

// ---------------- NCHW -> NHWC tiled transpose ----------------
__global__ void k_tr2(const float* __restrict__ in, int sel, int HW){
    __shared__ float tile[32][33];
    float* out = pick_xm(sel);
    int n  = blockIdx.z;
    int hw0 = blockIdx.x*32;
    int c0  = blockIdx.y*32;
    int tx = threadIdx.x, ty = threadIdx.y;
    #pragma unroll
    for (int q = 0; q < 4; ++q){
        int c = c0 + ty + q*8;
        int hw = hw0 + tx;
        float v = (hw < HW) ? in[((size_t)n*CH + c)*HW + hw] : 0.f;
        tile[ty + q*8][tx] = v;
    }
    __syncthreads();
    #pragma unroll
    for (int q = 0; q < 4; ++q){
        int hw = hw0 + ty + q*8;
        int c  = c0 + tx;
        if (hw < HW) out[((size_t)n*HW + hw)*CH + c] = tile[tx][ty + q*8];
    }
}

// weight transform: [dy][ic*3+dx][slot(4g x 28)]
__global__ void k_wt2(const float* __restrict__ ow){
    int i = blockIdx.x*blockDim.x + threadIdx.x;
    if (i >= 3*192*112) return;
    int slot = i % 112;
    int r    = (i / 112) % 192;
    int dy   = i / (112*192);
    int ic = r/3, dx = r%3;
    int g = slot/28, jj = slot%28;
    float v = 0.f;
    if (jj < 27) v = ow[(g*27+jj)*576 + ic*9 + dy*3 + dx];
    g_wT2[i] = v;
}

// ---------------- shared-source depthwise conv (single source per launch) ----
__global__ void __launch_bounds__(256, 3)
k_dwS(int src,
      const float* __restrict__ wm, const float* __restrict__ sm_, const float* __restrict__ bm_,
      const float* __restrict__ wh, const float* __restrict__ sh_, const float* __restrict__ bh_,
      const float* __restrict__ wl, const float* __restrict__ sl_, const float* __restrict__ bl_){
    __shared__ unsigned long long wsm[3][64][9][2];
    __shared__ float4 ssm[3][64], bsm[3][64];
    int n = blockIdx.z;
    int H = (src==0) ? 80 : (src==1 ? 40 : 20);
    int W = H, HW = H*W;
    int nsets = SRC_NSETS[src];
    int t = threadIdx.x;

    for (int s = 0; s < nsets; ++s){
        int sel = SRC_WSEL[src][s];
        const float* wgt = sel==0 ? wm : (sel==1 ? wh : wl);
        const float* sc  = sel==0 ? sm_ : (sel==1 ? sh_ : sl_);
        const float* bi  = sel==0 ? bm_ : (sel==1 ? bh_ : bl_);
        for (int i = t; i < 64*9; i += 256){
            int q = i/9, tp = i%9;
            float a0 = wgt[(q*4+0)*9 + tp], a1 = wgt[(q*4+1)*9 + tp];
            float a2 = wgt[(q*4+2)*9 + tp], a3 = wgt[(q*4+3)*9 + tp];
            PACKF2(wsm[s][q][tp][0], a0, a1);
            PACKF2(wsm[s][q][tp][1], a2, a3);
        }
        for (int i = t; i < 64; i += 256){
            ssm[s][i] = *(const float4*)(sc + i*4);
            bsm[s][i] = *(const float4*)(bi + i*4);
        }
    }
    __syncthreads();

    const float* x = pick_x(src);
    int q  = t & 63;
    int c0 = q*4;
    int lane = t >> 6;
    for (int hw = blockIdx.x*4 + lane; hw < HW; hw += gridDim.x*4){
        int w = hw % W, h = hw / W;
        ulonglong2 tap[9];
        #pragma unroll
        for (int dy = 0; dy < 3; ++dy){
            int yy = h + dy - 1;
            #pragma unroll
            for (int dx = 0; dx < 3; ++dx){
                int xx = w + dx - 1;
                int tp = dy*3 + dx;
                if (yy >= 0 && yy < H && xx >= 0 && xx < W)
                    tap[tp] = *(const ulonglong2*)(x + ((size_t)(n*H+yy)*W + xx)*CH + c0);
                else { tap[tp].x = 0ull; tap[tp].y = 0ull; }
            }
        }
        #pragma unroll 3
        for (int s = 0; s < 3; ++s){
            if (s >= nsets) break;
            unsigned long long a01 = 0ull, a23 = 0ull;
            #pragma unroll
            for (int tp = 0; tp < 9; ++tp){
                FMAF2(a01, tap[tp].x, wsm[s][q][tp][0], a01);
                FMAF2(a23, tap[tp].y, wsm[s][q][tp][1], a23);
            }
            float ax, ay, az, aw;
            UNPACKF2(ax, ay, a01);
            UNPACKF2(az, aw, a23);
            float4 s4 = ssm[s][q], b4 = bsm[s][q];
            float4 o;
            float t0 = ax*s4.x + b4.x; o.x = t0/(1.f+expf(-t0));
            float t1 = ay*s4.y + b4.y; o.y = t1/(1.f+expf(-t1));
            float t2 = az*s4.z + b4.z; o.z = t2/(1.f+expf(-t2));
            float t3 = aw*s4.w + b4.w; o.w = t3/(1.f+expf(-t3));
            float* dst = g_dwb + (size_t)SRC_DST[src][s]*NB*CH;
            *(float4*)(dst + ((size_t)n*HW + hw)*CH + c0) = o;
        }
    }
}

// ---------------- grouped conv 256->108, per-group blocks, FFMA2 ----
template<int STRIDE, int PXO, int TPX, int PXQ, int THREADS>
__global__ void __launch_bounds__(THREADS)
k_om3(int H, int W, int Ho, int Wo, const float* __restrict__ ob, int bA, int bB){
    constexpr int PW  = (PXO-1)*STRIDE + 3;
    constexpr int PWP = (PW + 3) & ~3;
    constexpr int WIN = 3 + (TPX-1)*STRIDE;
    static_assert((TPX*STRIDE) % 4 == 0, "window alignment");
    static_assert(WIN <= 8, "window fits two float4");
    extern __shared__ float sh[];
    float* patch = sh;
    float* wsl   = sh + 64*PWP;

    int br   = blockIdx.z == 0 ? bA : bB;
    const float* src = g_dwb + (size_t)DWPFX[br]*NB*CH;
    float* dst       = g_om  + (size_t)OMPFX[br]*NB*OMC;

    int nt   = (Wo + PXO - 1)/PXO;
    int g    = blockIdx.y;
    int b    = blockIdx.x;
    int tile = b % nt;
    int ho   = (b/nt) % Ho;
    int n    = b/(nt*Ho);
    int wo0  = tile*PXO;
    int hsrc = ho*STRIDE;
    int wsrc0= wo0*STRIDE;
    int cb   = g*64;

    int t   = threadIdx.x;
    int pxq = t % PXQ;
    int li  = t / PXQ;
    bool act = li < 7;
    int xb  = pxq*TPX*STRIDE;

    unsigned long long a01[TPX], a23[TPX];
    #pragma unroll
    for (int p = 0; p < TPX; ++p){ a01[p] = 0ull; a23[p] = 0ull; }

    const float* wsrc_base = g_wT2 + g*28;
    for (int dy = 0; dy < 3; ++dy){
        __syncthreads();
        int gy = hsrc + dy - 1;
        for (int i = t; i < PW*64; i += THREADS){
            int c = i & 63, xx = i >> 6;
            int gx = wsrc0 + xx - 1;
            float v = 0.f;
            if (gy >= 0 && gy < H && gx >= 0 && gx < W)
                v = src[((size_t)(n*H+gy)*W + gx)*CH + cb + c];
            patch[c*PWP + xx] = v;
        }
        {
            const float* ws = wsrc_base + dy*192*112;
            for (int i = t; i < 192*7; i += THREADS){
                int row = i/7, col = (i%7)*4;
                *(float4*)(wsl + row*28 + col) = *(const float4*)(ws + row*112 + col);
            }
        }
        __syncthreads();
        if (act){
            #pragma unroll 4
            for (int ic = 0; ic < 64; ++ic){
                const float* pr = patch + ic*PWP + xb;
                float f[8];
                *(float4*)(f)   = *(const float4*)(pr);
                *(float4*)(f+4) = *(const float4*)(pr+4);
                unsigned long long sv[WIN];
                #pragma unroll
                for (int k2 = 0; k2 < WIN; ++k2) PACKF2(sv[k2], f[k2], f[k2]);
                const float* wb = wsl + (ic*3)*28 + li*4;
                #pragma unroll
                for (int dx = 0; dx < 3; ++dx){
                    ulonglong2 wv = *(const ulonglong2*)(wb + dx*28);
                    #pragma unroll
                    for (int p = 0; p < TPX; ++p){
                        FMAF2(a01[p], sv[dx + p*STRIDE], wv.x, a01[p]);
                        FMAF2(a23[p], sv[dx + p*STRIDE], wv.y, a23[p]);
                    }
                }
            }
        }
    }
    if (act){
        float bj[4];
        #pragma unroll
        for (int j = 0; j < 4; ++j){
            int jj = li*4 + j;
            bj[j] = (jj < 27) ? ob[g*27 + jj] : 0.f;
        }
        #pragma unroll
        for (int p = 0; p < TPX; ++p){
            int wo = wo0 + pxq*TPX + p;
            if (wo < Wo){
                size_t base = ((size_t)(n*Ho+ho)*Wo + wo)*OMC + g*27 + li*4;
                float av[4];
                UNPACKF2(av[0], av[1], a01[p]);
                UNPACKF2(av[2], av[3], a23[p]);
                #pragma unroll
                for (int j = 0; j < 4; ++j)
                    if (li*4 + j < 27) dst[base + j] = av[j] + bj[j];
            }
        }
    }
}

// ---------------- batched DCNv3 sampler: 4x4 2D pixel tiles, 4 px/thread ----
__global__ void k_sampB(int bx0){
    __shared__ float som[16][OMC];
    __shared__ float smk[16][36];
    __shared__ float sw[16][4][9][4];
    __shared__ int   soff[16][4][9][4];
    __shared__ int   sp_hw[16];
    int bx = blockIdx.x + bx0;
    int b = 0;
    #pragma unroll
    for (int i = 1; i < 7; ++i) if (bx >= SAMP_PFX16[i]) b = i;
    int n = blockIdx.y;
    int Ho = BR_HO[b], Wo = Ho, HW = Ho*Wo;
    int H  = BR_HS[b], W = H;
    int stride = BR_STRIDE[b];
    int use_softmax = BR_SOFT[b];
    const float* x = pick_x(BR_SRC[b]);
    const float* omp = g_om + ((size_t)OMPFX[b]*NB + (size_t)n*HW)*OMC;
    int t = threadIdx.x;

    int tile = bx - SAMP_PFX16[b];
    int tw = Wo >> 2;
    int h0 = (tile/tw)*4, w0 = (tile%tw)*4;
    if (t < 16) sp_hw[t] = (h0 + (t>>2))*Wo + (w0 + (t&3));
    __syncthreads();

    for (int i = t; i < 16*OMC; i += 256)
        som[i/OMC][i%OMC] = omp[(size_t)sp_hw[i/OMC]*OMC + i%OMC];
    __syncthreads();

    if (use_softmax){
        if (t < 64){
            int pp = t >> 2, gg = t & 3;
            float mx = -1e30f;
            #pragma unroll
            for (int k = 0; k < 9; ++k) mx = fmaxf(mx, som[pp][72 + gg*9 + k]);
            float e[9], s = 0.f;
            #pragma unroll
            for (int k = 0; k < 9; ++k){ e[k] = expf(som[pp][72 + gg*9 + k] - mx); s += e[k]; }
            float inv = 1.f/s;
            #pragma unroll
            for (int k = 0; k < 9; ++k) smk[pp][gg*9 + k] = e[k]*inv;
        }
    } else {
        for (int i = t; i < 16*36; i += 256)
            smk[i/36][i%36] = 1.f/(1.f + expf(-som[i/36][72 + i%36]));
    }
    __syncthreads();

    for (int i = t; i < 16*36; i += 256){
        int pix = i / 36, r = i % 36, gg = r / 9, k = r % 9;
        int hw = sp_hw[pix];
        int wo = hw % Wo, ho = hw / Wo;
        float py = (float)(ho*stride) + (float)(k/3 - 1) + som[pix][gg*18 + k*2];
        float px = (float)(wo*stride) + (float)(k%3 - 1) + som[pix][gg*18 + k*2 + 1];
        float m  = smk[pix][gg*9 + k];
        float fy = floorf(py), fx = floorf(px);
        float wy = py - fy, wx = px - fx;
        int iy = (int)fy, ix = (int)fx;
        #pragma unroll
        for (int d0 = 0; d0 < 2; ++d0){
            int yy = iy + d0;
            float wgy = d0 ? wy : (1.f - wy);
            #pragma unroll
            for (int d1 = 0; d1 < 2; ++d1){
                int xx = ix + d1;
                bool valid = (yy >= 0) & (yy < H) & (xx >= 0) & (xx < W);
                int yc = min(max(yy, 0), H-1);
                int xc = min(max(xx, 0), W-1);
                sw[pix][gg][k][d0*2+d1]   = valid ? wgy*(d1 ? wx : (1.f - wx))*m : 0.f;
                soff[pix][gg][k][d0*2+d1] = ((n*H + yc)*W + xc)*CH;
            }
        }
    }
    __syncthreads();

    int lane = t >> 6, q = t & 63, c0 = q*4, g = q >> 4;
    const float* xc = x + c0;
    #pragma unroll
    for (int pi = 0; pi < 4; ++pi){
        int pix = lane + pi*4;
        unsigned long long acc01 = 0ull, acc23 = 0ull;
        #pragma unroll
        for (int k = 0; k < 9; ++k){
            float4 wv = *(const float4*)&sw[pix][g][k][0];
            int4  ov = *(const int4*)&soff[pix][g][k][0];
            unsigned long long w0v, w1v, w2v, w3v;
            PACKF2(w0v, wv.x, wv.x); PACKF2(w1v, wv.y, wv.y);
            PACKF2(w2v, wv.z, wv.z); PACKF2(w3v, wv.w, wv.w);
            ulonglong2 v0 = *(const ulonglong2*)(xc + ov.x);
            ulonglong2 v1 = *(const ulonglong2*)(xc + ov.y);
            ulonglong2 v2 = *(const ulonglong2*)(xc + ov.z);
            ulonglong2 v3 = *(const ulonglong2*)(xc + ov.w);
            FMAF2(acc01, v0.x, w0v, acc01); FMAF2(acc23, v0.y, w0v, acc23);
            FMAF2(acc01, v1.x, w1v, acc01); FMAF2(acc23, v1.y, w1v, acc23);
            FMAF2(acc01, v2.x, w2v, acc01); FMAF2(acc23, v2.y, w2v, acc23);
            FMAF2(acc01, v3.x, w3v, acc01); FMAF2(acc23, v3.y, w3v, acc23);
        }
        float4 acc;
        UNPACKF2(acc.x, acc.y, acc01);
        UNPACKF2(acc.z, acc.w, acc23);
        *(float4*)(g_feat + ((size_t)OMPFX[b]*NB + (size_t)n*HW + sp_hw[pix])*CH + c0) = acc;
    }
}

// ---------------- batched stats (branch-offset subset launch) ----------------
__global__ void k_statsB(int boff){
    __shared__ float wy[80], wx[80];
    __shared__ float r1[256], r2[256];
    __shared__ float4 rw[256];
    int b = (blockIdx.x >> 4) + boff, g = blockIdx.x & 15, n = blockIdx.y;
    int Hs = BR_HO[b], Ws = Hs, HW = Hs*Ws;
    int uph = BR_UPH[b];
    float normw = uph ? 1.f/((float)uph*(float)uph) : 1.f/(float)HW;
    int t = threadIdx.x;
    if (t == 0){
        if (uph){
            for (int i = 0; i < Hs; ++i){ wy[i] = 0.f; wx[i] = 0.f; }
            float ry = (float)(Hs-1)/(float)(uph-1);
            for (int j = 0; j < uph; ++j){
                float c = j*ry; int i0 = (int)floorf(c); float f = c - (float)i0;
                wy[i0] += 1.f - f;
                if (i0 + 1 < Hs) wy[i0+1] += f;
            }
            for (int i = 0; i < Hs; ++i) wx[i] = wy[i];
        } else {
            for (int i = 0; i < Hs; ++i){ wy[i] = 1.f; wx[i] = 1.f; }
        }
    }
    __syncthreads();

    const float* fb = g_feat + ((size_t)OMPFX[b]*NB + (size_t)n*HW)*CH;
    int q  = t & 3;
    int c0 = g*16 + q*4;
    float4 s4 = make_float4(0,0,0,0), w4 = make_float4(0,0,0,0);
    float ss = 0.f;
    int hw0 = t >> 2;
    int h = hw0 / Ws, w = hw0 % Ws;
    for (int hw = hw0; hw < HW; hw += 64){
        float4 v = *(const float4*)(fb + (size_t)hw*CH + c0);
        s4.x += v.x; s4.y += v.y; s4.z += v.z; s4.w += v.w;
        ss += v.x*v.x + v.y*v.y + v.z*v.z + v.w*v.w;
        float ww = wy[h]*wx[w];
        w4.x += v.x*ww; w4.y += v.y*ww; w4.z += v.z*ww; w4.w += v.w*ww;
        w += 64; while (w >= Ws){ w -= Ws; ++h; }
    }
    r1[t] = s4.x + s4.y + s4.z + s4.w;
    r2[t] = ss;
    rw[t] = w4;
    __syncthreads();
    for (int o = 128; o >= 4; o >>= 1){
        if (t < o){
            r1[t] += r1[t+o]; r2[t] += r2[t+o];
            rw[t].x += rw[t+o].x; rw[t].y += rw[t+o].y;
            rw[t].z += rw[t+o].z; rw[t].w += rw[t+o].w;
        }
        __syncthreads();
    }
    if (t == 0){
        float s  = r1[0] + r1[1] + r1[2] + r1[3];
        float sq = r2[0] + r2[1] + r2[2] + r2[3];
        float cnt = (float)HW*16.f;
        float mu  = s/cnt;
        float var = sq/cnt - mu*mu;
        g_gmu [(b*NB+n)*16 + g] = mu;
        g_ginv[(b*NB+n)*16 + g] = rsqrtf(var + 1e-5f);
    }
    if (t < 4){
        float4 wv = rw[t];
        int c = (b*NB+n)*CH + g*16 + t*4;
        g_cmean[c]   = wv.x*normw; g_cmean[c+1] = wv.y*normw;
        g_cmean[c+2] = wv.z*normw; g_cmean[c+3] = wv.w*normw;
    }
}

// ---------------- attn scalars + pooled means (per-level subset) ----------
__device__ __constant__ int LVL_NBR[3] = {2,3,2};
__device__ __constant__ int LVL_BRS[3][3] = {{0,1,-1},{2,3,4},{5,6,-1}};

__global__ void k_attnB(int lvlofs,
                        const float* __restrict__ saw, const float* __restrict__ sab,
                        const float* __restrict__ gm, const float* __restrict__ bm,
                        const float* __restrict__ gh, const float* __restrict__ bh,
                        const float* __restrict__ gl, const float* __restrict__ bl){
    __shared__ float red[256];
    __shared__ float sa;
    int lvl = blockIdx.x + lvlofs, n = blockIdx.y, t = threadIdx.x;
    int g = t >> 4;
    int nbr = LVL_NBR[lvl];
    float invl = 1.f/(float)nbr;
    float y = 0.f;
    for (int i = 0; i < nbr; ++i){
        int b = LVL_BRS[lvl][i];
        int gs = BR_GNSEL[b];
        const float* gam = gs==0 ? gm : (gs==1 ? gh : gl);
        const float* bet = gs==0 ? bm : (gs==1 ? bh : bl);
        float m = (g_cmean[(b*NB+n)*CH + t] - g_gmu[(b*NB+n)*16 + g])
                  * g_ginv[(b*NB+n)*16 + g] * gam[t] + bet[t];
        red[t] = m*saw[t];
        __syncthreads();
        for (int o = 128; o > 0; o >>= 1){
            if (t < o) red[t] += red[t+o];
            __syncthreads();
        }
        if (t == 0){
            float a = red[0] + sab[0];
            a = fmaxf(a, 0.f);
            a = fminf(fmaxf((a + 3.f)/6.f, 0.f), 1.f);
            sa = a; g_a[b*NB + n] = a;
        }
        __syncthreads();
        y += sa*m*invl;
        __syncthreads();
    }
    g_y[(lvl*NB + n)*CH + t] = y;
}

// ---------------- fc (per-level subset) ----------------
__global__ void k_fcB(int lvlofs,
                      const float* __restrict__ w1, const float* __restrict__ b1,
                      const float* __restrict__ w2, const float* __restrict__ b2){
    __shared__ float h[4][64];
    int lvl = blockIdx.x + lvlofs;
    int t = threadIdx.x;
    int n = t >> 6, j = t & 63;
    float s = b1[j];
    const float* wr = w1 + j*CH;
    const float* yv = g_y + (lvl*NB + n)*CH;
    for (int c = 0; c < CH; ++c) s += yv[c]*wr[c];
    h[n][j] = fmaxf(s, 0.f);
    __syncthreads();
    for (int og = t; og < NB*1024; og += 256){
        int nn = og >> 10, o = og & 1023;
        float s2 = b2[o];
        const float* w2r = w2 + o*64;
        #pragma unroll 16
        for (int j2 = 0; j2 < 64; ++j2) s2 += h[nn][j2]*w2r[j2];
        float z = fminf(fmaxf(s2 + 3.f, 0.f), 6.f)*(1.f/6.f);
        int qd = o >> 8;
        float v;
        if      (qd == 0) v = (z - 0.5f)*2.f + 1.f;
        else if (qd == 2) v = (z - 0.5f)*2.f;
        else              v = z - 0.5f;
        g_z[(lvl*NB + nn)*1024 + o] = v;
    }
}

// ---------------- fused: GN+attn+upsample sum -> dyrelu -> NCHW out ----------
__device__ __forceinline__ void gn_acc(float4& o, float4 raw, int b, int n, int g,
                                       float4 g4, float4 b4){
    float mu = g_gmu[(b*NB+n)*16 + g], inv = g_ginv[(b*NB+n)*16 + g], a = g_a[b*NB + n];
    o.x += a*((raw.x - mu)*inv*g4.x + b4.x);
    o.y += a*((raw.y - mu)*inv*g4.y + b4.y);
    o.z += a*((raw.z - mu)*inv*g4.z + b4.z);
    o.w += a*((raw.w - mu)*inv*g4.w + b4.w);
}
__device__ __forceinline__ float4 feat_rd(int b, int n, int HW, int hw, int c0){
    return *(const float4*)(g_feat + ((size_t)OMPFX[b]*NB + (size_t)n*HW + hw)*CH + c0);
}
__device__ __forceinline__ float4 feat_up(int b, int n, int Hs, int Ho, int h, int w, int c0){
    float r = (float)(Hs-1)/(float)(Ho-1);
    float cy = h*r, cx = w*r;
    int y0 = (int)floorf(cy), x0 = (int)floorf(cx);
    int y1 = min(y0+1, Hs-1), x1 = min(x0+1, Hs-1);
    float wyf = cy - (float)y0, wxf = cx - (float)x0;
    const float* fb = g_feat + ((size_t)OMPFX[b]*NB + (size_t)n*Hs*Hs)*CH + c0;
    float4 v00 = *(const float4*)(fb + (size_t)(y0*Hs + x0)*CH);
    float4 v01 = *(const float4*)(fb + (size_t)(y0*Hs + x1)*CH);
    float4 v10 = *(const float4*)(fb + (size_t)(y1*Hs + x0)*CH);
    float4 v11 = *(const float4*)(fb + (size_t)(y1*Hs + x1)*CH);
    float a0 = (1.f-wyf)*(1.f-wxf), a1 = (1.f-wyf)*wxf, a2 = wyf*(1.f-wxf), a3 = wyf*wxf;
    float4 o;
    o.x = v00.x*a0 + v01.x*a1 + v10.x*a2 + v11.x*a3;
    o.y = v00.y*a0 + v01.y*a1 + v10.y*a2 + v11.y*a3;
    o.z = v00.z*a0 + v01.z*a1 + v10.z*a2 + v11.z*a3;
    o.w = v00.w*a0 + v01.w*a1 + v10.w*a2 + v11.w*a3;
    return o;
}

template<int LVL>
__global__ void k_outL(float* __restrict__ out,
                       const float* __restrict__ gm, const float* __restrict__ bm,
                       const float* __restrict__ gh, const float* __restrict__ bh,
                       const float* __restrict__ gl, const float* __restrict__ bl){
    constexpr int HoL = (LVL==0) ? 80 : (LVL==1 ? 40 : 20);
    constexpr int HWL = HoL*HoL;
    constexpr float INVL = (LVL==1) ? (1.f/3.f) : 0.5f;
    __shared__ float tile[32][257];
    int n   = blockIdx.y;
    int hw0 = blockIdx.x*32;
    int tx = threadIdx.x, ty = threadIdx.y;
    int tid = ty*32 + tx;

    #pragma unroll
    for (int k = 0; k < 8; ++k){
        int e = k*256 + tid;
        int hwl = e >> 6;
        int q   = e & 63;
        int hw  = hw0 + hwl;
        if (hw < HWL){
            int c0 = q*4, g = q >> 2;
            int w = hw % HoL, h = hw / HoL;
            float4 o = make_float4(0,0,0,0);
            float4 g4, b4;
            if (LVL == 0){
                g4 = *(const float4*)(gm + c0); b4 = *(const float4*)(bm + c0);
                gn_acc(o, feat_rd(0, n, 6400, hw, c0), 0, n, g, g4, b4);
                g4 = *(const float4*)(gh + c0); b4 = *(const float4*)(bh + c0);
                gn_acc(o, feat_up(1, n, 40, 80, h, w, c0), 1, n, g, g4, b4);
            } else if (LVL == 1){
                g4 = *(const float4*)(gm + c0); b4 = *(const float4*)(bm + c0);
                gn_acc(o, feat_rd(2, n, 1600, hw, c0), 2, n, g, g4, b4);
                g4 = *(const float4*)(gl + c0); b4 = *(const float4*)(bl + c0);
                gn_acc(o, feat_rd(3, n, 1600, hw, c0), 3, n, g, g4, b4);
                g4 = *(const float4*)(gh + c0); b4 = *(const float4*)(bh + c0);
                gn_acc(o, feat_up(4, n, 20, 40, h, w, c0), 4, n, g, g4, b4);
            } else {
                g4 = *(const float4*)(gm + c0); b4 = *(const float4*)(bm + c0);
                gn_acc(o, feat_rd(5, n, 400, hw, c0), 5, n, g, g4, b4);
                g4 = *(const float4*)(gl + c0); b4 = *(const float4*)(bl + c0);
                gn_acc(o, feat_rd(6, n, 400, hw, c0), 6, n, g, g4, b4);
            }
            tile[hwl][c0]   = o.x;
            tile[hwl][c0+1] = o.y;
            tile[hwl][c0+2] = o.z;
            tile[hwl][c0+3] = o.w;
        }
    }
    __syncthreads();

    int hw = hw0 + tx;
    if (hw < HWL){
        const float* zb = g_z + (LVL*NB + n)*1024;
        #pragma unroll
        for (int k = 0; k < 32; ++k){
            int c = ty + k*8;
            float f = tile[tx][c]*INVL;
            float a1 = zb[c], b1 = zb[256 + c];
            float a2 = zb[512 + c], b2 = zb[768 + c];
            out[((size_t)n*CH + c)*HWL + hw] = fmaxf(f*a1 + b1, f*a2 + b2);
        }
    }
}

// ---------------- host: per-level-pipelined fork/join (graph-capturable) ------
extern "C" void kernel_launch(void* const* d_in, const int* in_sizes, int n_in,
                              void* d_out, int out_size){
    const float* x0     = (const float*)d_in[0];
    const float* x1     = (const float*)d_in[1];
    const float* x2     = (const float*)d_in[2];
    const float* dw_w_h = (const float*)d_in[3];
    const float* dw_s_h = (const float*)d_in[4];
    const float* dw_b_h = (const float*)d_in[5];
    const float* dw_w_m = (const float*)d_in[6];
    const float* dw_s_m = (const float*)d_in[7];
    const float* dw_b_m = (const float*)d_in[8];
    const float* dw_w_l = (const float*)d_in[9];
    const float* dw_s_l = (const float*)d_in[10];
    const float* dw_b_l = (const float*)d_in[11];
    const float* off_w  = (const float*)d_in[12];
    const float* off_b  = (const float*)d_in[13];
    const float* gn_g_h = (const float*)d_in[14];
    const float* gn_b_h = (const float*)d_in[15];
    const float* gn_g_m = (const float*)d_in[16];
    const float* gn_b_m = (const float*)d_in[17];
    const float* gn_g_l = (const float*)d_in[18];
    const float* gn_b_l = (const float*)d_in[19];
    const float* sa_w   = (const float*)d_in[20];
    const float* sa_b   = (const float*)d_in[21];
    const float* fc1_w  = (const float*)d_in[22];
    const float* fc1_b  = (const float*)d_in[23];
    const float* fc2_w  = (const float*)d_in[24];
    const float* fc2_b  = (const float*)d_in[25];
    float* out = (float*)d_out;

    static cudaStream_t s1, s2, s3;
    static cudaEvent_t eFork, eWt, eDw0, eDw1, eO3, eO20, eS1, eL3, eL2v;
    static bool inited = false;
    if (!inited){
        cudaStreamCreateWithFlags(&s1, cudaStreamNonBlocking);
        cudaStreamCreateWithFlags(&s2, cudaStreamNonBlocking);
        cudaStreamCreateWithFlags(&s3, cudaStreamNonBlocking);
        cudaEventCreateWithFlags(&eFork, cudaEventDisableTiming);
        cudaEventCreateWithFlags(&eWt,  cudaEventDisableTiming);
        cudaEventCreateWithFlags(&eDw0, cudaEventDisableTiming);
        cudaEventCreateWithFlags(&eDw1, cudaEventDisableTiming);
        cudaEventCreateWithFlags(&eO3,  cudaEventDisableTiming);
        cudaEventCreateWithFlags(&eO20, cudaEventDisableTiming);
        cudaEventCreateWithFlags(&eS1,  cudaEventDisableTiming);
        cudaEventCreateWithFlags(&eL3,  cudaEventDisableTiming);
        cudaEventCreateWithFlags(&eL2v, cudaEventDisableTiming);
        inited = true;
    }
    cudaStream_t s0 = 0;

    // fork
    cudaEventRecord(eFork, s0);
    cudaStreamWaitEvent(s1, eFork, 0);
    cudaStreamWaitEvent(s2, eFork, 0);
    cudaStreamWaitEvent(s3, eFork, 0);

    // stage 1: identical structure to R14 (dwS(src0) at API launch #3)
    k_tr2<<<dim3(200, 8, NB), dim3(32,8), 0, s0>>>(x0, 0, 6400);
    k_tr2<<<dim3(50,  8, NB), dim3(32,8), 0, s1>>>(x1, 1, 1600);
    k_tr2<<<dim3(13,  8, NB), dim3(32,8), 0, s2>>>(x2, 2,  400);
    k_dwS<<<dim3(200, 1, NB), 256, 0, s0>>>(0, dw_w_m, dw_s_m, dw_b_m,
                                               dw_w_h, dw_s_h, dw_b_h,
                                               dw_w_l, dw_s_l, dw_b_l);
    cudaEventRecord(eDw0, s0);
    k_wt2<<<(3*192*112 + 255)/256, 256, 0, s3>>>(off_w);
    cudaEventRecord(eWt, s3);
    k_dwS<<<dim3(50, 1, NB), 256, 0, s1>>>(1, dw_w_m, dw_s_m, dw_b_m,
                                              dw_w_h, dw_s_h, dw_b_h,
                                              dw_w_l, dw_s_l, dw_b_l);
    cudaEventRecord(eDw1, s1);
    k_dwS<<<dim3(13, 1, NB), 256, 0, s2>>>(2, dw_w_m, dw_s_m, dw_b_m,
                                              dw_w_h, dw_s_h, dw_b_h,
                                              dw_w_l, dw_s_l, dw_b_l);

    // stage 2: om per class (identical to R14)
    cudaStreamWaitEvent(s0, eWt, 0);
    cudaStreamWaitEvent(s1, eWt, 0);
    cudaStreamWaitEvent(s2, eWt, 0);
    cudaStreamWaitEvent(s3, eDw0, 0);
    const int SM80 = (64*84 + 192*28)*4;
    const int SM40 = (64*44 + 192*28)*4;
    const int SM40s2 = (64*84 + 192*28)*4;
    const int SM20 = (64*24 + 192*28)*4;
    k_om3<1,80,4,20,160><<<dim3(1*80*NB, 4, 1), 160, SM80, s0>>>(80, 80, 80, 80, off_b, 0, 0);
    k_om3<1,40,4,10,80><<<dim3(1*40*NB, 4, 2), 80, SM40, s1>>>(40, 40, 40, 40, off_b, 1, 2);
    k_om3<2,40,2,20,160><<<dim3(1*40*NB, 4, 1), 160, SM40s2, s3>>>(80, 80, 40, 40, off_b, 3, 3);
    cudaStreamWaitEvent(s3, eDw1, 0);
    k_om3<2,20,2,10,80><<<dim3(1*20*NB, 4, 1), 80, SM40, s3>>>(40, 40, 20, 20, off_b, 6, 6);
    cudaEventRecord(eO3, s3);
    cudaStreamWaitEvent(s2, eDw1, 0);
    k_om3<1,20,4,5,64><<<dim3(1*20*NB, 4, 2), 64, SM20, s2>>>(20, 20, 20, 20, off_b, 4, 5);
    cudaEventRecord(eO20, s2);

    // stage 3a: b0 chain on s0
    k_sampB <<<dim3(400, NB), 256, 0, s0>>>(0);
    k_statsB<<<dim3(16, NB),  256, 0, s0>>>(0);

    // stage 3b: b1,b2 chain on s1 (enables lvl0 early)
    k_sampB <<<dim3(200, NB), 256, 0, s1>>>(400);
    k_statsB<<<dim3(2*16, NB),256, 0, s1>>>(1);
    cudaEventRecord(eS1, s1);

    // stage 3c: b3..b6 chain on s3
    cudaStreamWaitEvent(s3, eO20, 0);
    k_sampB <<<dim3(175, NB), 256, 0, s3>>>(600);
    k_statsB<<<dim3(4*16, NB),256, 0, s3>>>(3);

    // stage 4a: lvl0 epilogue on s0 (overlaps b3..b6 sampling)
    cudaStreamWaitEvent(s0, eS1, 0);
    k_attnB<<<dim3(1, NB), 256, 0, s0>>>(0, sa_w, sa_b, gn_g_m, gn_b_m, gn_g_h, gn_b_h, gn_g_l, gn_b_l);
    k_fcB  <<<1,           256, 0, s0>>>(0, fc1_w, fc1_b, fc2_w, fc2_b);
    k_outL<0><<<dim3(200, NB), dim3(32,8), 0, s0>>>(out,
        gn_g_m, gn_b_m, gn_g_h, gn_b_h, gn_g_l, gn_b_l);

    // stage 4b: lvl1+lvl2 epilogue on s3 (needs b2 stats from s1)
    cudaStreamWaitEvent(s3, eS1, 0);
    k_attnB<<<dim3(2, NB), 256, 0, s3>>>(1, sa_w, sa_b, gn_g_m, gn_b_m, gn_g_h, gn_b_h, gn_g_l, gn_b_l);
    k_fcB  <<<2,           256, 0, s3>>>(1, fc1_w, fc1_b, fc2_w, fc2_b);
    cudaEventRecord(eL2v, s3);
    k_outL<1><<<dim3(50, NB), dim3(32,8), 0, s3>>>(out + (size_t)NB*CH*6400,
        gn_g_m, gn_b_m, gn_g_h, gn_b_h, gn_g_l, gn_b_l);
    cudaEventRecord(eL3, s3);
    cudaStreamWaitEvent(s2, eL2v, 0);
    k_outL<2><<<dim3(13, NB), dim3(32,8), 0, s2>>>(out + (size_t)NB*CH*8000,
        gn_g_m, gn_b_m, gn_g_h, gn_b_h, gn_g_l, gn_b_l);
    cudaEventRecord(eO20, s2);   // reuse event slot for final join

    // join
    cudaStreamWaitEvent(s0, eL3, 0);
    cudaStreamWaitEvent(s0, eO20, 0);
}

// round 17
// speedup vs baseline: 1.2962x; 1.0195x over previous
#include <cuda_runtime.h>
#include <math.h>

#define NB   4
#define CH   256
#define OMC  108
#define OMS  112   // padded om channel stride

// ---- packed f32x2 ops ----
#define PACKF2(out, lo, hi) \
    asm("mov.b64 %0, {%1, %2};" : "=l"(out) : "f"(lo), "f"(hi))
#define UNPACKF2(lo, hi, in) \
    asm("mov.b64 {%0, %1}, %2;" : "=f"(lo), "=f"(hi) : "l"(in))
#define FMAF2(d, a, b, c) \
    asm("fma.rn.f32x2 %0, %1, %2, %3;" : "=l"(d) : "l"(a), "l"(b), "l"(c))

// ---- branch tables (7 branches) ----
__device__ __constant__ int BR_SRC[7]    = {0,1,1,0,2,2,1};
__device__ __constant__ int BR_HS[7]     = {80,40,40,80,20,20,40};
__device__ __constant__ int BR_STRIDE[7] = {1,1,1,2,1,1,2};
__device__ __constant__ int BR_HO[7]     = {80,40,40,40,20,20,20};
__device__ __constant__ int BR_SOFT[7]   = {0,1,0,1,1,0,1};
__device__ __constant__ int BR_UPH[7]    = {0,80,0,0,40,0,0};
__device__ __constant__ int BR_GNSEL[7]  = {0,1,0,2,1,0,2};
__device__ __constant__ int DWPFX[7]     = {0,6400,8000,9600,16000,16400,16800};
__device__ __constant__ int OMPFX[7]     = {0,6400,8000,9600,11200,11600,12000};
__device__ __constant__ int SAMP_PFX16[7] = {0,400,500,600,700,725,750};

__device__ __constant__ int SRC_NSETS[3]  = {2,3,2};
__device__ __constant__ int SRC_WSEL[3][3]= {{0,2,0},{1,0,2},{1,0,0}};
__device__ __constant__ int SRC_DST[3][3] = {{0,9600,0},{6400,8000,16800},{16000,16400,0}};

// ---------------- scratch ----------------
__device__ float g_x0[NB*80*80*CH];
__device__ float g_x1[NB*40*40*CH];
__device__ float g_x2[NB*20*20*CH];
__device__ float g_dwb[18400*NB*CH];
__device__ float g_om [12400*NB*OMS];
__device__ float g_feat[12400*NB*CH];
__device__ float g_wT2[3*192*112];
__device__ float g_a[7*NB];
__device__ float g_y[3*NB*CH];
__device__ float g_z[3*NB*1024];
__device__ float g_cmean[7*NB*CH];
__device__ float g_gmu[7*NB*16];
__device__ float g_ginv[7*NB*16];

__device__ __forceinline__ const float* pick_x(int s){
    return s==0 ? g_x0 : (s==1 ? g_x1 : g_x2);
}
__device__ __forceinline__ float* pick_xm(int s){
    return s==0 ? g_x0 : (s==1 ? g_x1 : g_x2);
}

// ---------------- NCHW -> NHWC tiled transpose (float4 both sides) ----------
__global__ void k_tr2(const float* __restrict__ in, int sel, int HW){
    __shared__ float tile[32][33];
    float* out = pick_xm(sel);
    int n  = blockIdx.z;
    int hw0 = blockIdx.x*32;
    int c0  = blockIdx.y*32;
    int t = threadIdx.x;           // 256
    int cl  = t >> 3;              // 0..31
    int hw4 = (t & 7)*4;
    int hwi = hw0 + hw4;
    const float* ip = in + ((size_t)n*CH + c0 + cl)*HW;
    if (hwi + 3 < HW){
        float4 v = *(const float4*)(ip + hwi);
        tile[cl][hw4]   = v.x; tile[cl][hw4+1] = v.y;
        tile[cl][hw4+2] = v.z; tile[cl][hw4+3] = v.w;
    } else {
        #pragma unroll
        for (int k = 0; k < 4; ++k)
            tile[cl][hw4+k] = (hwi+k < HW) ? ip[hwi+k] : 0.f;
    }
    __syncthreads();
    int hwl = t >> 3;
    int c4  = (t & 7)*4;
    if (hw0 + hwl < HW){
        float4 o;
        o.x = tile[c4][hwl];   o.y = tile[c4+1][hwl];
        o.z = tile[c4+2][hwl]; o.w = tile[c4+3][hwl];
        *(float4*)(out + ((size_t)n*HW + hw0 + hwl)*CH + c0 + c4) = o;
    }
}

// weight transform: [dy][ic*3+dx][slot(4g x 28)]
__global__ void k_wt2(const float* __restrict__ ow){
    int i = blockIdx.x*blockDim.x + threadIdx.x;
    if (i >= 3*192*112) return;
    int slot = i % 112;
    int r    = (i / 112) % 192;
    int dy   = i / (112*192);
    int ic = r/3, dx = r%3;
    int g = slot/28, jj = slot%28;
    float v = 0.f;
    if (jj < 27) v = ow[(g*27+jj)*576 + ic*9 + dy*3 + dx];
    g_wT2[i] = v;
}

// ---------------- shared-source depthwise conv (single source per launch) ----
__global__ void __launch_bounds__(256, 3)
k_dwS(int src,
      const float* __restrict__ wm, const float* __restrict__ sm_, const float* __restrict__ bm_,
      const float* __restrict__ wh, const float* __restrict__ sh_, const float* __restrict__ bh_,
      const float* __restrict__ wl, const float* __restrict__ sl_, const float* __restrict__ bl_){
    __shared__ unsigned long long wsm[3][64][9][2];
    __shared__ float4 ssm[3][64], bsm[3][64];
    int n = blockIdx.z;
    int H = (src==0) ? 80 : (src==1 ? 40 : 20);
    int W = H, HW = H*W;
    int nsets = SRC_NSETS[src];
    int t = threadIdx.x;

    for (int s = 0; s < nsets; ++s){
        int sel = SRC_WSEL[src][s];
        const float* wgt = sel==0 ? wm : (sel==1 ? wh : wl);
        const float* sc  = sel==0 ? sm_ : (sel==1 ? sh_ : sl_);
        const float* bi  = sel==0 ? bm_ : (sel==1 ? bh_ : bl_);
        for (int i = t; i < 64*9; i += 256){
            int q = i/9, tp = i%9;
            float a0 = wgt[(q*4+0)*9 + tp], a1 = wgt[(q*4+1)*9 + tp];
            float a2 = wgt[(q*4+2)*9 + tp], a3 = wgt[(q*4+3)*9 + tp];
            PACKF2(wsm[s][q][tp][0], a0, a1);
            PACKF2(wsm[s][q][tp][1], a2, a3);
        }
        for (int i = t; i < 64; i += 256){
            ssm[s][i] = *(const float4*)(sc + i*4);
            bsm[s][i] = *(const float4*)(bi + i*4);
        }
    }
    __syncthreads();

    const float* x = pick_x(src);
    int q  = t & 63;
    int c0 = q*4;
    int lane = t >> 6;
    for (int hw = blockIdx.x*4 + lane; hw < HW; hw += gridDim.x*4){
        int w = hw % W, h = hw / W;
        ulonglong2 tap[9];
        #pragma unroll
        for (int dy = 0; dy < 3; ++dy){
            int yy = h + dy - 1;
            #pragma unroll
            for (int dx = 0; dx < 3; ++dx){
                int xx = w + dx - 1;
                int tp = dy*3 + dx;
                if (yy >= 0 && yy < H && xx >= 0 && xx < W)
                    tap[tp] = *(const ulonglong2*)(x + ((size_t)(n*H+yy)*W + xx)*CH + c0);
                else { tap[tp].x = 0ull; tap[tp].y = 0ull; }
            }
        }
        #pragma unroll 3
        for (int s = 0; s < 3; ++s){
            if (s >= nsets) break;
            unsigned long long a01 = 0ull, a23 = 0ull;
            #pragma unroll
            for (int tp = 0; tp < 9; ++tp){
                FMAF2(a01, tap[tp].x, wsm[s][q][tp][0], a01);
                FMAF2(a23, tap[tp].y, wsm[s][q][tp][1], a23);
            }
            float ax, ay, az, aw;
            UNPACKF2(ax, ay, a01);
            UNPACKF2(az, aw, a23);
            float4 s4 = ssm[s][q], b4 = bsm[s][q];
            float4 o;
            float t0 = ax*s4.x + b4.x; o.x = t0/(1.f+expf(-t0));
            float t1 = ay*s4.y + b4.y; o.y = t1/(1.f+expf(-t1));
            float t2 = az*s4.z + b4.z; o.z = t2/(1.f+expf(-t2));
            float t3 = aw*s4.w + b4.w; o.w = t3/(1.f+expf(-t3));
            float* dst = g_dwb + (size_t)SRC_DST[src][s]*NB*CH;
            *(float4*)(dst + ((size_t)n*HW + hw)*CH + c0) = o;
        }
    }
}

// ---------------- grouped conv 256->108(pad112), per-group blocks, FFMA2 ----
template<int STRIDE, int PXO, int TPX, int PXQ, int THREADS>
__global__ void __launch_bounds__(THREADS)
k_om3(int H, int W, int Ho, int Wo, const float* __restrict__ ob, int bA, int bB){
    constexpr int PW  = (PXO-1)*STRIDE + 3;
    constexpr int PWP = (PW + 3) & ~3;
    constexpr int WIN = 3 + (TPX-1)*STRIDE;
    static_assert((TPX*STRIDE) % 4 == 0, "window alignment");
    static_assert(WIN <= 8, "window fits two float4");
    extern __shared__ float sh[];
    float* patch = sh;
    float* wsl   = sh + 64*PWP;

    int br   = blockIdx.z == 0 ? bA : bB;
    const float* src = g_dwb + (size_t)DWPFX[br]*NB*CH;
    float* dst       = g_om  + (size_t)OMPFX[br]*NB*OMS;

    int nt   = (Wo + PXO - 1)/PXO;
    int g    = blockIdx.y;
    int b    = blockIdx.x;
    int tile = b % nt;
    int ho   = (b/nt) % Ho;
    int n    = b/(nt*Ho);
    int wo0  = tile*PXO;
    int hsrc = ho*STRIDE;
    int wsrc0= wo0*STRIDE;
    int cb   = g*64;

    int t   = threadIdx.x;
    int pxq = t % PXQ;
    int li  = t / PXQ;
    bool act = li < 7;
    int xb  = pxq*TPX*STRIDE;

    unsigned long long a01[TPX], a23[TPX];
    #pragma unroll
    for (int p = 0; p < TPX; ++p){ a01[p] = 0ull; a23[p] = 0ull; }

    const float* wsrc_base = g_wT2 + g*28;
    for (int dy = 0; dy < 3; ++dy){
        __syncthreads();
        int gy = hsrc + dy - 1;
        for (int i = t; i < PW*64; i += THREADS){
            int c = i & 63, xx = i >> 6;
            int gx = wsrc0 + xx - 1;
            float v = 0.f;
            if (gy >= 0 && gy < H && gx >= 0 && gx < W)
                v = src[((size_t)(n*H+gy)*W + gx)*CH + cb + c];
            patch[c*PWP + xx] = v;
        }
        {
            const float* ws = wsrc_base + dy*192*112;
            for (int i = t; i < 192*7; i += THREADS){
                int row = i/7, col = (i%7)*4;
                *(float4*)(wsl + row*28 + col) = *(const float4*)(ws + row*112 + col);
            }
        }
        __syncthreads();
        if (act){
            #pragma unroll 4
            for (int ic = 0; ic < 64; ++ic){
                const float* pr = patch + ic*PWP + xb;
                float f[8];
                *(float4*)(f)   = *(const float4*)(pr);
                *(float4*)(f+4) = *(const float4*)(pr+4);
                unsigned long long sv[WIN];
                #pragma unroll
                for (int k2 = 0; k2 < WIN; ++k2) PACKF2(sv[k2], f[k2], f[k2]);
                const float* wb = wsl + (ic*3)*28 + li*4;
                #pragma unroll
                for (int dx = 0; dx < 3; ++dx){
                    ulonglong2 wv = *(const ulonglong2*)(wb + dx*28);
                    #pragma unroll
                    for (int p = 0; p < TPX; ++p){
                        FMAF2(a01[p], sv[dx + p*STRIDE], wv.x, a01[p]);
                        FMAF2(a23[p], sv[dx + p*STRIDE], wv.y, a23[p]);
                    }
                }
            }
        }
    }
    if (act){
        float bj[4];
        #pragma unroll
        for (int j = 0; j < 4; ++j){
            int jj = li*4 + j;
            bj[j] = (jj < 27) ? ob[g*27 + jj] : 0.f;
        }
        #pragma unroll
        for (int p = 0; p < TPX; ++p){
            int wo = wo0 + pxq*TPX + p;
            if (wo < Wo){
                float av[4];
                UNPACKF2(av[0], av[1], a01[p]);
                UNPACKF2(av[2], av[3], a23[p]);
                float4 o;
                o.x = av[0] + bj[0];
                o.y = av[1] + bj[1];
                o.z = av[2] + bj[2];
                o.w = av[3] + bj[3];   // padded lane: weights 0, bias 0 -> 0
                *(float4*)(dst + ((size_t)(n*Ho+ho)*Wo + wo)*OMS + g*28 + li*4) = o;
            }
        }
    }
}

// ---------------- batched DCNv3 sampler: 4x4 2D pixel tiles, 4 px/thread ----
__global__ void k_sampB(int bx0){
    __shared__ float som[16][OMC];
    __shared__ float smk[16][36];
    __shared__ float sw[16][4][9][4];
    __shared__ int   soff[16][4][9][4];
    __shared__ int   sp_hw[16];
    int bx = blockIdx.x + bx0;
    int b = 0;
    #pragma unroll
    for (int i = 1; i < 7; ++i) if (bx >= SAMP_PFX16[i]) b = i;
    int n = blockIdx.y;
    int Ho = BR_HO[b], Wo = Ho, HW = Ho*Wo;
    int H  = BR_HS[b], W = H;
    int stride = BR_STRIDE[b];
    int use_softmax = BR_SOFT[b];
    const float* x = pick_x(BR_SRC[b]);
    const float* omp = g_om + ((size_t)OMPFX[b]*NB + (size_t)n*HW)*OMS;
    int t = threadIdx.x;

    int tile = bx - SAMP_PFX16[b];
    int tw = Wo >> 2;
    int h0 = (tile/tw)*4, w0 = (tile%tw)*4;
    if (t < 16) sp_hw[t] = (h0 + (t>>2))*Wo + (w0 + (t&3));
    __syncthreads();

    for (int i = t; i < 16*OMC; i += 256){
        int pix = i/OMC, c = i%OMC;
        int pc = (c/27)*28 + (c%27);   // un-permute padded conv-group layout
        som[pix][c] = omp[(size_t)sp_hw[pix]*OMS + pc];
    }
    __syncthreads();

    if (use_softmax){
        if (t < 64){
            int pp = t >> 2, gg = t & 3;
            float mx = -1e30f;
            #pragma unroll
            for (int k = 0; k < 9; ++k) mx = fmaxf(mx, som[pp][72 + gg*9 + k]);
            float e[9], s = 0.f;
            #pragma unroll
            for (int k = 0; k < 9; ++k){ e[k] = expf(som[pp][72 + gg*9 + k] - mx); s += e[k]; }
            float inv = 1.f/s;
            #pragma unroll
            for (int k = 0; k < 9; ++k) smk[pp][gg*9 + k] = e[k]*inv;
        }
    } else {
        for (int i = t; i < 16*36; i += 256)
            smk[i/36][i%36] = 1.f/(1.f + expf(-som[i/36][72 + i%36]));
    }
    __syncthreads();

    for (int i = t; i < 16*36; i += 256){
        int pix = i / 36, r = i % 36, gg = r / 9, k = r % 9;
        int hw = sp_hw[pix];
        int wo = hw % Wo, ho = hw / Wo;
        float py = (float)(ho*stride) + (float)(k/3 - 1) + som[pix][gg*18 + k*2];
        float px = (float)(wo*stride) + (float)(k%3 - 1) + som[pix][gg*18 + k*2 + 1];
        float m  = smk[pix][gg*9 + k];
        float fy = floorf(py), fx = floorf(px);
        float wy = py - fy, wx = px - fx;
        int iy = (int)fy, ix = (int)fx;
        #pragma unroll
        for (int d0 = 0; d0 < 2; ++d0){
            int yy = iy + d0;
            float wgy = d0 ? wy : (1.f - wy);
            #pragma unroll
            for (int d1 = 0; d1 < 2; ++d1){
                int xx = ix + d1;
                bool valid = (yy >= 0) & (yy < H) & (xx >= 0) & (xx < W);
                int yc = min(max(yy, 0), H-1);
                int xc = min(max(xx, 0), W-1);
                sw[pix][gg][k][d0*2+d1]   = valid ? wgy*(d1 ? wx : (1.f - wx))*m : 0.f;
                soff[pix][gg][k][d0*2+d1] = ((n*H + yc)*W + xc)*CH;
            }
        }
    }
    __syncthreads();

    int lane = t >> 6, q = t & 63, c0 = q*4, g = q >> 4;
    const float* xc = x + c0;
    #pragma unroll
    for (int pi = 0; pi < 4; ++pi){
        int pix = lane + pi*4;
        unsigned long long acc01 = 0ull, acc23 = 0ull;
        #pragma unroll
        for (int k = 0; k < 9; ++k){
            float4 wv = *(const float4*)&sw[pix][g][k][0];
            int4  ov = *(const int4*)&soff[pix][g][k][0];
            unsigned long long w0v, w1v, w2v, w3v;
            PACKF2(w0v, wv.x, wv.x); PACKF2(w1v, wv.y, wv.y);
            PACKF2(w2v, wv.z, wv.z); PACKF2(w3v, wv.w, wv.w);
            ulonglong2 v0 = *(const ulonglong2*)(xc + ov.x);
            ulonglong2 v1 = *(const ulonglong2*)(xc + ov.y);
            ulonglong2 v2 = *(const ulonglong2*)(xc + ov.z);
            ulonglong2 v3 = *(const ulonglong2*)(xc + ov.w);
            FMAF2(acc01, v0.x, w0v, acc01); FMAF2(acc23, v0.y, w0v, acc23);
            FMAF2(acc01, v1.x, w1v, acc01); FMAF2(acc23, v1.y, w1v, acc23);
            FMAF2(acc01, v2.x, w2v, acc01); FMAF2(acc23, v2.y, w2v, acc23);
            FMAF2(acc01, v3.x, w3v, acc01); FMAF2(acc23, v3.y, w3v, acc23);
        }
        float4 acc;
        UNPACKF2(acc.x, acc.y, acc01);
        UNPACKF2(acc.z, acc.w, acc23);
        *(float4*)(g_feat + ((size_t)OMPFX[b]*NB + (size_t)n*HW + sp_hw[pix])*CH + c0) = acc;
    }
}

// ---------------- batched stats (branch-offset subset launch) ----------------
__global__ void k_statsB(int boff){
    __shared__ float wy[80], wx[80];
    __shared__ float r1[256], r2[256];
    __shared__ float4 rw[256];
    int b = (blockIdx.x >> 4) + boff, g = blockIdx.x & 15, n = blockIdx.y;
    int Hs = BR_HO[b], Ws = Hs, HW = Hs*Ws;
    int uph = BR_UPH[b];
    float normw = uph ? 1.f/((float)uph*(float)uph) : 1.f/(float)HW;
    int t = threadIdx.x;
    if (t == 0){
        if (uph){
            for (int i = 0; i < Hs; ++i){ wy[i] = 0.f; wx[i] = 0.f; }
            float ry = (float)(Hs-1)/(float)(uph-1);
            for (int j = 0; j < uph; ++j){
                float c = j*ry; int i0 = (int)floorf(c); float f = c - (float)i0;
                wy[i0] += 1.f - f;
                if (i0 + 1 < Hs) wy[i0+1] += f;
            }
            for (int i = 0; i < Hs; ++i) wx[i] = wy[i];
        } else {
            for (int i = 0; i < Hs; ++i){ wy[i] = 1.f; wx[i] = 1.f; }
        }
    }
    __syncthreads();

    const float* fb = g_feat + ((size_t)OMPFX[b]*NB + (size_t)n*HW)*CH;
    int q  = t & 3;
    int c0 = g*16 + q*4;
    float4 s4 = make_float4(0,0,0,0), w4 = make_float4(0,0,0,0);
    float ss = 0.f;
    int hw0 = t >> 2;
    int h = hw0 / Ws, w = hw0 % Ws;
    for (int hw = hw0; hw < HW; hw += 64){
        float4 v = *(const float4*)(fb + (size_t)hw*CH + c0);
        s4.x += v.x; s4.y += v.y; s4.z += v.z; s4.w += v.w;
        ss += v.x*v.x + v.y*v.y + v.z*v.z + v.w*v.w;
        float ww = wy[h]*wx[w];
        w4.x += v.x*ww; w4.y += v.y*ww; w4.z += v.z*ww; w4.w += v.w*ww;
        w += 64; while (w >= Ws){ w -= Ws; ++h; }
    }
    r1[t] = s4.x + s4.y + s4.z + s4.w;
    r2[t] = ss;
    rw[t] = w4;
    __syncthreads();
    for (int o = 128; o >= 4; o >>= 1){
        if (t < o){
            r1[t] += r1[t+o]; r2[t] += r2[t+o];
            rw[t].x += rw[t+o].x; rw[t].y += rw[t+o].y;
            rw[t].z += rw[t+o].z; rw[t].w += rw[t+o].w;
        }
        __syncthreads();
    }
    if (t == 0){
        float s  = r1[0] + r1[1] + r1[2] + r1[3];
        float sq = r2[0] + r2[1] + r2[2] + r2[3];
        float cnt = (float)HW*16.f;
        float mu  = s/cnt;
        float var = sq/cnt - mu*mu;
        g_gmu [(b*NB+n)*16 + g] = mu;
        g_ginv[(b*NB+n)*16 + g] = rsqrtf(var + 1e-5f);
    }
    if (t < 4){
        float4 wv = rw[t];
        int c = (b*NB+n)*CH + g*16 + t*4;
        g_cmean[c]   = wv.x*normw; g_cmean[c+1] = wv.y*normw;
        g_cmean[c+2] = wv.z*normw; g_cmean[c+3] = wv.w*normw;
    }
}

// ---------------- attn scalars + pooled means (per-level subset) ----------
__device__ __constant__ int LVL_NBR[3] = {2,3,2};
__device__ __constant__ int LVL_BRS[3][3] = {{0,1,-1},{2,3,4},{5,6,-1}};

__global__ void k_attnB(int lvlofs,
                        const float* __restrict__ saw, const float* __restrict__ sab,
                        const float* __restrict__ gm, const float* __restrict__ bm,
                        const float* __restrict__ gh, const float* __restrict__ bh,
                        const float* __restrict__ gl, const float* __restrict__ bl){
    __shared__ float red[256];
    __shared__ float sa;
    int lvl = blockIdx.x + lvlofs, n = blockIdx.y, t = threadIdx.x;
    int g = t >> 4;
    int nbr = LVL_NBR[lvl];
    float invl = 1.f/(float)nbr;
    float y = 0.f;
    for (int i = 0; i < nbr; ++i){
        int b = LVL_BRS[lvl][i];
        int gs = BR_GNSEL[b];
        const float* gam = gs==0 ? gm : (gs==1 ? gh : gl);
        const float* bet = gs==0 ? bm : (gs==1 ? bh : bl);
        float m = (g_cmean[(b*NB+n)*CH + t] - g_gmu[(b*NB+n)*16 + g])
                  * g_ginv[(b*NB+n)*16 + g] * gam[t] + bet[t];
        red[t] = m*saw[t];
        __syncthreads();
        for (int o = 128; o > 0; o >>= 1){
            if (t < o) red[t] += red[t+o];
            __syncthreads();
        }
        if (t == 0){
            float a = red[0] + sab[0];
            a = fmaxf(a, 0.f);
            a = fminf(fmaxf((a + 3.f)/6.f, 0.f), 1.f);
            sa = a; g_a[b*NB + n] = a;
        }
        __syncthreads();
        y += sa*m*invl;
        __syncthreads();
    }
    g_y[(lvl*NB + n)*CH + t] = y;
}

// ---------------- fc (per-level subset) ----------------
__global__ void k_fcB(int lvlofs,
                      const float* __restrict__ w1, const float* __restrict__ b1,
                      const float* __restrict__ w2, const float* __restrict__ b2){
    __shared__ float h[4][64];
    int lvl = blockIdx.x + lvlofs;
    int t = threadIdx.x;
    int n = t >> 6, j = t & 63;
    float s = b1[j];
    const float* wr = w1 + j*CH;
    const float* yv = g_y + (lvl*NB + n)*CH;
    for (int c = 0; c < CH; ++c) s += yv[c]*wr[c];
    h[n][j] = fmaxf(s, 0.f);
    __syncthreads();
    for (int og = t; og < NB*1024; og += 256){
        int nn = og >> 10, o = og & 1023;
        float s2 = b2[o];
        const float* w2r = w2 + o*64;
        #pragma unroll 16
        for (int j2 = 0; j2 < 64; ++j2) s2 += h[nn][j2]*w2r[j2];
        float z = fminf(fmaxf(s2 + 3.f, 0.f), 6.f)*(1.f/6.f);
        int qd = o >> 8;
        float v;
        if      (qd == 0) v = (z - 0.5f)*2.f + 1.f;
        else if (qd == 2) v = (z - 0.5f)*2.f;
        else              v = z - 0.5f;
        g_z[(lvl*NB + nn)*1024 + o] = v;
    }
}

// ---------------- fused: GN+attn+upsample sum -> dyrelu -> NCHW out ----------
__device__ __forceinline__ void gn_acc(float4& o, float4 raw, int b, int n, int g,
                                       float4 g4, float4 b4){
    float mu = g_gmu[(b*NB+n)*16 + g], inv = g_ginv[(b*NB+n)*16 + g], a = g_a[b*NB + n];
    o.x += a*((raw.x - mu)*inv*g4.x + b4.x);
    o.y += a*((raw.y - mu)*inv*g4.y + b4.y);
    o.z += a*((raw.z - mu)*inv*g4.z + b4.z);
    o.w += a*((raw.w - mu)*inv*g4.w + b4.w);
}
__device__ __forceinline__ float4 feat_rd(int b, int n, int HW, int hw, int c0){
    return *(const float4*)(g_feat + ((size_t)OMPFX[b]*NB + (size_t)n*HW + hw)*CH + c0);
}
__device__ __forceinline__ float4 feat_up(int b, int n, int Hs, int Ho, int h, int w, int c0){
    float r = (float)(Hs-1)/(float)(Ho-1);
    float cy = h*r, cx = w*r;
    int y0 = (int)floorf(cy), x0 = (int)floorf(cx);
    int y1 = min(y0+1, Hs-1), x1 = min(x0+1, Hs-1);
    float wyf = cy - (float)y0, wxf = cx - (float)x0;
    const float* fb = g_feat + ((size_t)OMPFX[b]*NB + (size_t)n*Hs*Hs)*CH + c0;
    float4 v00 = *(const float4*)(fb + (size_t)(y0*Hs + x0)*CH);
    float4 v01 = *(const float4*)(fb + (size_t)(y0*Hs + x1)*CH);
    float4 v10 = *(const float4*)(fb + (size_t)(y1*Hs + x0)*CH);
    float4 v11 = *(const float4*)(fb + (size_t)(y1*Hs + x1)*CH);
    float a0 = (1.f-wyf)*(1.f-wxf), a1 = (1.f-wyf)*wxf, a2 = wyf*(1.f-wxf), a3 = wyf*wxf;
    float4 o;
    o.x = v00.x*a0 + v01.x*a1 + v10.x*a2 + v11.x*a3;
    o.y = v00.y*a0 + v01.y*a1 + v10.y*a2 + v11.y*a3;
    o.z = v00.z*a0 + v01.z*a1 + v10.z*a2 + v11.z*a3;
    o.w = v00.w*a0 + v01.w*a1 + v10.w*a2 + v11.w*a3;
    return o;
}

template<int LVL>
__global__ void k_outL(float* __restrict__ out,
                       const float* __restrict__ gm, const float* __restrict__ bm,
                       const float* __restrict__ gh, const float* __restrict__ bh,
                       const float* __restrict__ gl, const float* __restrict__ bl){
    constexpr int HoL = (LVL==0) ? 80 : (LVL==1 ? 40 : 20);
    constexpr int HWL = HoL*HoL;
    constexpr float INVL = (LVL==1) ? (1.f/3.f) : 0.5f;
    __shared__ float tile[32][257];
    int n   = blockIdx.y;
    int hw0 = blockIdx.x*32;
    int tx = threadIdx.x, ty = threadIdx.y;
    int tid = ty*32 + tx;

    #pragma unroll
    for (int k = 0; k < 8; ++k){
        int e = k*256 + tid;
        int hwl = e >> 6;
        int q   = e & 63;
        int hw  = hw0 + hwl;
        if (hw < HWL){
            int c0 = q*4, g = q >> 2;
            int w = hw % HoL, h = hw / HoL;
            float4 o = make_float4(0,0,0,0);
            float4 g4, b4;
            if (LVL == 0){
                g4 = *(const float4*)(gm + c0); b4 = *(const float4*)(bm + c0);
                gn_acc(o, feat_rd(0, n, 6400, hw, c0), 0, n, g, g4, b4);
                g4 = *(const float4*)(gh + c0); b4 = *(const float4*)(bh + c0);
                gn_acc(o, feat_up(1, n, 40, 80, h, w, c0), 1, n, g, g4, b4);
            } else if (LVL == 1){
                g4 = *(const float4*)(gm + c0); b4 = *(const float4*)(bm + c0);
                gn_acc(o, feat_rd(2, n, 1600, hw, c0), 2, n, g, g4, b4);
                g4 = *(const float4*)(gl + c0); b4 = *(const float4*)(bl + c0);
                gn_acc(o, feat_rd(3, n, 1600, hw, c0), 3, n, g, g4, b4);
                g4 = *(const float4*)(gh + c0); b4 = *(const float4*)(bh + c0);
                gn_acc(o, feat_up(4, n, 20, 40, h, w, c0), 4, n, g, g4, b4);
            } else {
                g4 = *(const float4*)(gm + c0); b4 = *(const float4*)(bm + c0);
                gn_acc(o, feat_rd(5, n, 400, hw, c0), 5, n, g, g4, b4);
                g4 = *(const float4*)(gl + c0); b4 = *(const float4*)(bl + c0);
                gn_acc(o, feat_rd(6, n, 400, hw, c0), 6, n, g, g4, b4);
            }
            tile[hwl][c0]   = o.x;
            tile[hwl][c0+1] = o.y;
            tile[hwl][c0+2] = o.z;
            tile[hwl][c0+3] = o.w;
        }
    }
    __syncthreads();

    int hw = hw0 + tx;
    if (hw < HWL){
        const float* zb = g_z + (LVL*NB + n)*1024;
        #pragma unroll
        for (int k = 0; k < 32; ++k){
            int c = ty + k*8;
            float f = tile[tx][c]*INVL;
            float a1 = zb[c], b1 = zb[256 + c];
            float a2 = zb[512 + c], b2 = zb[768 + c];
            out[((size_t)n*CH + c)*HWL + hw] = fmaxf(f*a1 + b1, f*a2 + b2);
        }
    }
}

// ---------------- host: per-level-pipelined fork/join (graph-capturable) ------
extern "C" void kernel_launch(void* const* d_in, const int* in_sizes, int n_in,
                              void* d_out, int out_size){
    const float* x0     = (const float*)d_in[0];
    const float* x1     = (const float*)d_in[1];
    const float* x2     = (const float*)d_in[2];
    const float* dw_w_h = (const float*)d_in[3];
    const float* dw_s_h = (const float*)d_in[4];
    const float* dw_b_h = (const float*)d_in[5];
    const float* dw_w_m = (const float*)d_in[6];
    const float* dw_s_m = (const float*)d_in[7];
    const float* dw_b_m = (const float*)d_in[8];
    const float* dw_w_l = (const float*)d_in[9];
    const float* dw_s_l = (const float*)d_in[10];
    const float* dw_b_l = (const float*)d_in[11];
    const float* off_w  = (const float*)d_in[12];
    const float* off_b  = (const float*)d_in[13];
    const float* gn_g_h = (const float*)d_in[14];
    const float* gn_b_h = (const float*)d_in[15];
    const float* gn_g_m = (const float*)d_in[16];
    const float* gn_b_m = (const float*)d_in[17];
    const float* gn_g_l = (const float*)d_in[18];
    const float* gn_b_l = (const float*)d_in[19];
    const float* sa_w   = (const float*)d_in[20];
    const float* sa_b   = (const float*)d_in[21];
    const float* fc1_w  = (const float*)d_in[22];
    const float* fc1_b  = (const float*)d_in[23];
    const float* fc2_w  = (const float*)d_in[24];
    const float* fc2_b  = (const float*)d_in[25];
    float* out = (float*)d_out;

    static cudaStream_t s1, s2, s3;
    static cudaEvent_t eFork, eWt, eDw0, eDw1, eO3, eO20, eS1, eL3, eL2v;
    static bool inited = false;
    if (!inited){
        cudaStreamCreateWithFlags(&s1, cudaStreamNonBlocking);
        cudaStreamCreateWithFlags(&s2, cudaStreamNonBlocking);
        cudaStreamCreateWithFlags(&s3, cudaStreamNonBlocking);
        cudaEventCreateWithFlags(&eFork, cudaEventDisableTiming);
        cudaEventCreateWithFlags(&eWt,  cudaEventDisableTiming);
        cudaEventCreateWithFlags(&eDw0, cudaEventDisableTiming);
        cudaEventCreateWithFlags(&eDw1, cudaEventDisableTiming);
        cudaEventCreateWithFlags(&eO3,  cudaEventDisableTiming);
        cudaEventCreateWithFlags(&eO20, cudaEventDisableTiming);
        cudaEventCreateWithFlags(&eS1,  cudaEventDisableTiming);
        cudaEventCreateWithFlags(&eL3,  cudaEventDisableTiming);
        cudaEventCreateWithFlags(&eL2v, cudaEventDisableTiming);
        inited = true;
    }
    cudaStream_t s0 = 0;

    // fork
    cudaEventRecord(eFork, s0);
    cudaStreamWaitEvent(s1, eFork, 0);
    cudaStreamWaitEvent(s2, eFork, 0);
    cudaStreamWaitEvent(s3, eFork, 0);

    // stage 1 (same topology as R16; tr2 now 256-thread flat blocks)
    k_tr2<<<dim3(200, 8, NB), 256, 0, s0>>>(x0, 0, 6400);
    k_tr2<<<dim3(50,  8, NB), 256, 0, s1>>>(x1, 1, 1600);
    k_tr2<<<dim3(13,  8, NB), 256, 0, s2>>>(x2, 2,  400);
    k_dwS<<<dim3(200, 1, NB), 256, 0, s0>>>(0, dw_w_m, dw_s_m, dw_b_m,
                                               dw_w_h, dw_s_h, dw_b_h,
                                               dw_w_l, dw_s_l, dw_b_l);
    cudaEventRecord(eDw0, s0);
    k_wt2<<<(3*192*112 + 255)/256, 256, 0, s3>>>(off_w);
    cudaEventRecord(eWt, s3);
    k_dwS<<<dim3(50, 1, NB), 256, 0, s1>>>(1, dw_w_m, dw_s_m, dw_b_m,
                                              dw_w_h, dw_s_h, dw_b_h,
                                              dw_w_l, dw_s_l, dw_b_l);
    cudaEventRecord(eDw1, s1);
    k_dwS<<<dim3(13, 1, NB), 256, 0, s2>>>(2, dw_w_m, dw_s_m, dw_b_m,
                                              dw_w_h, dw_s_h, dw_b_h,
                                              dw_w_l, dw_s_l, dw_b_l);

    // stage 2: om per class
    cudaStreamWaitEvent(s0, eWt, 0);
    cudaStreamWaitEvent(s1, eWt, 0);
    cudaStreamWaitEvent(s2, eWt, 0);
    cudaStreamWaitEvent(s3, eDw0, 0);
    const int SM80 = (64*84 + 192*28)*4;
    const int SM40 = (64*44 + 192*28)*4;
    const int SM40s2 = (64*84 + 192*28)*4;
    const int SM20 = (64*24 + 192*28)*4;
    k_om3<1,80,4,20,160><<<dim3(1*80*NB, 4, 1), 160, SM80, s0>>>(80, 80, 80, 80, off_b, 0, 0);
    k_om3<1,40,4,10,80><<<dim3(1*40*NB, 4, 2), 80, SM40, s1>>>(40, 40, 40, 40, off_b, 1, 2);
    k_om3<2,40,2,20,160><<<dim3(1*40*NB, 4, 1), 160, SM40s2, s3>>>(80, 80, 40, 40, off_b, 3, 3);
    cudaStreamWaitEvent(s3, eDw1, 0);
    k_om3<2,20,2,10,80><<<dim3(1*20*NB, 4, 1), 80, SM40, s3>>>(40, 40, 20, 20, off_b, 6, 6);
    cudaEventRecord(eO3, s3);
    cudaStreamWaitEvent(s2, eDw1, 0);
    k_om3<1,20,4,5,64><<<dim3(1*20*NB, 4, 2), 64, SM20, s2>>>(20, 20, 20, 20, off_b, 4, 5);
    cudaEventRecord(eO20, s2);

    // stage 3a: b0 chain on s0
    k_sampB <<<dim3(400, NB), 256, 0, s0>>>(0);
    k_statsB<<<dim3(16, NB),  256, 0, s0>>>(0);

    // stage 3b: b1,b2 chain on s1
    k_sampB <<<dim3(200, NB), 256, 0, s1>>>(400);
    k_statsB<<<dim3(2*16, NB),256, 0, s1>>>(1);
    cudaEventRecord(eS1, s1);

    // stage 3c: b3..b6 chain on s3
    cudaStreamWaitEvent(s3, eO20, 0);
    k_sampB <<<dim3(175, NB), 256, 0, s3>>>(600);
    k_statsB<<<dim3(4*16, NB),256, 0, s3>>>(3);

    // stage 4a: lvl0 epilogue on s0
    cudaStreamWaitEvent(s0, eS1, 0);
    k_attnB<<<dim3(1, NB), 256, 0, s0>>>(0, sa_w, sa_b, gn_g_m, gn_b_m, gn_g_h, gn_b_h, gn_g_l, gn_b_l);
    k_fcB  <<<1,           256, 0, s0>>>(0, fc1_w, fc1_b, fc2_w, fc2_b);
    k_outL<0><<<dim3(200, NB), dim3(32,8), 0, s0>>>(out,
        gn_g_m, gn_b_m, gn_g_h, gn_b_h, gn_g_l, gn_b_l);

    // stage 4b: lvl1+lvl2 epilogue on s3
    cudaStreamWaitEvent(s3, eS1, 0);
    k_attnB<<<dim3(2, NB), 256, 0, s3>>>(1, sa_w, sa_b, gn_g_m, gn_b_m, gn_g_h, gn_b_h, gn_g_l, gn_b_l);
    k_fcB  <<<2,           256, 0, s3>>>(1, fc1_w, fc1_b, fc2_w, fc2_b);
    cudaEventRecord(eL2v, s3);
    k_outL<1><<<dim3(50, NB), dim3(32,8), 0, s3>>>(out + (size_t)NB*CH*6400,
        gn_g_m, gn_b_m, gn_g_h, gn_b_h, gn_g_l, gn_b_l);
    cudaEventRecord(eL3, s3);
    cudaStreamWaitEvent(s2, eL2v, 0);
    k_outL<2><<<dim3(13, NB), dim3(32,8), 0, s2>>>(out + (size_t)NB*CH*8000,
        gn_g_m, gn_b_m, gn_g_h, gn_b_h, gn_g_l, gn_b_l);
    cudaEventRecord(eO20, s2);

    // join
    cudaStreamWaitEvent(s0, eL3, 0);
    cudaStreamWaitEvent(s0, eO20, 0);
}